// round 1
// baseline (speedup 1.0000x reference)
#include <cuda_runtime.h>
#include <stdint.h>

// Problem constants (fixed by dataset)
#define S_LEN   4096
#define DMODEL  1024
#define NHEADS  8
#define HDIM    128
#define NHID    2048
#define EPSN    1e-6f

// ---------------------------------------------------------------------------
// Scratch (device globals — no allocations allowed)
// ---------------------------------------------------------------------------
__device__ float g_q[(size_t)S_LEN * DMODEL];                 // 16 MB
__device__ float g_khat[(size_t)NHID * NHEADS * HDIM];        // 8 MB
__device__ float g_attn[(size_t)NHEADS * S_LEN * NHID];       // 256 MB
__device__ float g_y[(size_t)S_LEN * DMODEL];                 // 16 MB

// ---------------------------------------------------------------------------
// Packed fp32x2 helpers (Blackwell FFMA2 path)
// ---------------------------------------------------------------------------
__device__ __forceinline__ unsigned long long pack2(float lo, float hi) {
    unsigned long long r;
    asm("mov.b64 %0, {%1, %2};"
        : "=l"(r) : "r"(__float_as_uint(lo)), "r"(__float_as_uint(hi)));
    return r;
}
__device__ __forceinline__ void unpack2(unsigned long long v, float& lo, float& hi) {
    unsigned a, b;
    asm("mov.b64 {%0, %1}, %2;" : "=r"(a), "=r"(b) : "l"(v));
    lo = __uint_as_float(a);
    hi = __uint_as_float(b);
}
__device__ __forceinline__ unsigned long long fma2(unsigned long long a,
                                                   unsigned long long b,
                                                   unsigned long long c) {
    unsigned long long d;
    asm("fma.rn.f32x2 %0, %1, %2, %3;" : "=l"(d) : "l"(a), "l"(b), "l"(c));
    return d;
}

// ---------------------------------------------------------------------------
// Row normalize: rows of 128 floats, one warp per row.
// useScale: multiply by attn_scale[row % NHEADS] (keys path).
// ---------------------------------------------------------------------------
__global__ void normalize_rows128(const float* __restrict__ src,
                                  float* __restrict__ dst,
                                  const float* __restrict__ attn_scale,
                                  int nrows, int useScale) {
    int row  = blockIdx.x * (blockDim.x >> 5) + (threadIdx.x >> 5);
    int lane = threadIdx.x & 31;
    if (row >= nrows) return;
    float4 v = reinterpret_cast<const float4*>(src + (size_t)row * HDIM)[lane];
    float ss = v.x * v.x + v.y * v.y + v.z * v.z + v.w * v.w;
    #pragma unroll
    for (int o = 16; o; o >>= 1) ss += __shfl_xor_sync(0xFFFFFFFFu, ss, o);
    float sc = rsqrtf(ss + EPSN);
    if (useScale) sc *= attn_scale[row & (NHEADS - 1)];
    v.x *= sc; v.y *= sc; v.z *= sc; v.w *= sc;
    reinterpret_cast<float4*>(dst + (size_t)row * HDIM)[lane] = v;
}

// ---------------------------------------------------------------------------
// Tiled fp32 GEMM: C[M,N] = A[M,K] * B
//   TRANS_B = false: B is [K,N] (ldb = row stride over K)
//   TRANS_B = true : B is [N,K] (ldb = row stride over N), dot over K
// Block tile 64x128, BK=8, 128 threads, 8x8 per thread, FFMA2 inner loop.
// blockIdx.z selects head via element offsets aZ/bZ/cZ.
// All dims assumed exact multiples of tiles (true for this problem).
// ---------------------------------------------------------------------------
#define BKD 8
template <bool TRANS_B>
__global__ __launch_bounds__(128, 2)
void gemm_f32x2(const float* __restrict__ A, const float* __restrict__ B,
                float* __restrict__ C,
                int M, int N, int K,
                int lda, int ldb, int ldc,
                long long aZ, long long bZ, long long cZ) {
    __shared__ float As[BKD][64 + 8];    // 72*4=288B rows, 16B aligned
    __shared__ float Bs[BKD][128 + 8];   // 136*4=544B rows, 16B aligned

    const int tid = threadIdx.x;
    const int m0  = blockIdx.x * 64;
    const int n0  = blockIdx.y * 128;
    const long long z = blockIdx.z;
    A += z * aZ; B += z * bZ; C += z * cZ;

    const int ty = tid >> 4;       // 0..7  -> rows ty*8..+7
    const int tx = tid & 15;       // 0..15 -> cols tx*8..+7

    // A tile load map: one float4 per thread along K
    const int a_m = tid >> 1;          // 0..63
    const int a_k = (tid & 1) * 4;     // 0 or 4

    unsigned long long acc[8][4];
    #pragma unroll
    for (int i = 0; i < 8; i++)
        #pragma unroll
        for (int j = 0; j < 4; j++) acc[i][j] = 0ull;

    for (int k0 = 0; k0 < K; k0 += BKD) {
        // ---- load A tile (store transposed As[k][m]) ----
        {
            float4 av = *reinterpret_cast<const float4*>(
                A + (long long)(m0 + a_m) * lda + k0 + a_k);
            As[a_k + 0][a_m] = av.x;
            As[a_k + 1][a_m] = av.y;
            As[a_k + 2][a_m] = av.z;
            As[a_k + 3][a_m] = av.w;
        }
        // ---- load B tile ----
        if (!TRANS_B) {
            int bk = tid >> 4;            // 0..7
            int bn = (tid & 15) * 8;      // 0..120
            const float* bp = B + (long long)(k0 + bk) * ldb + n0 + bn;
            float4 b0 = *reinterpret_cast<const float4*>(bp);
            float4 b1 = *reinterpret_cast<const float4*>(bp + 4);
            *reinterpret_cast<float4*>(&Bs[bk][bn])     = b0;
            *reinterpret_cast<float4*>(&Bs[bk][bn + 4]) = b1;
        } else {
            int bn = tid;                 // 0..127
            const float* bp = B + (long long)(n0 + bn) * ldb + k0;
            float4 b0 = *reinterpret_cast<const float4*>(bp);
            float4 b1 = *reinterpret_cast<const float4*>(bp + 4);
            Bs[0][bn] = b0.x; Bs[1][bn] = b0.y; Bs[2][bn] = b0.z; Bs[3][bn] = b0.w;
            Bs[4][bn] = b1.x; Bs[5][bn] = b1.y; Bs[6][bn] = b1.z; Bs[7][bn] = b1.w;
        }
        __syncthreads();

        // ---- compute ----
        #pragma unroll
        for (int kk = 0; kk < BKD; kk++) {
            float4 a0 = *reinterpret_cast<const float4*>(&As[kk][ty * 8]);
            float4 a1 = *reinterpret_cast<const float4*>(&As[kk][ty * 8 + 4]);
            float4 b0 = *reinterpret_cast<const float4*>(&Bs[kk][tx * 8]);
            float4 b1 = *reinterpret_cast<const float4*>(&Bs[kk][tx * 8 + 4]);
            unsigned long long bp[4];
            bp[0] = pack2(b0.x, b0.y);
            bp[1] = pack2(b0.z, b0.w);
            bp[2] = pack2(b1.x, b1.y);
            bp[3] = pack2(b1.z, b1.w);
            float af[8] = {a0.x, a0.y, a0.z, a0.w, a1.x, a1.y, a1.z, a1.w};
            #pragma unroll
            for (int i = 0; i < 8; i++) {
                unsigned long long ad = pack2(af[i], af[i]);
                #pragma unroll
                for (int j = 0; j < 4; j++) acc[i][j] = fma2(ad, bp[j], acc[i][j]);
            }
        }
        __syncthreads();
    }

    // ---- epilogue ----
    #pragma unroll
    for (int i = 0; i < 8; i++) {
        long long row = m0 + ty * 8 + i;
        float4 c0, c1;
        unpack2(acc[i][0], c0.x, c0.y);
        unpack2(acc[i][1], c0.z, c0.w);
        unpack2(acc[i][2], c1.x, c1.y);
        unpack2(acc[i][3], c1.z, c1.w);
        float* cp = C + row * ldc + n0 + tx * 8;
        *reinterpret_cast<float4*>(cp)     = c0;
        *reinterpret_cast<float4*>(cp + 4) = c1;
    }
}

// ---------------------------------------------------------------------------
// Softmax over rows of 2048, one block (256 threads) per row, in place.
// ---------------------------------------------------------------------------
__global__ __launch_bounds__(256)
void softmax2048(float* __restrict__ attn) {
    const size_t row = blockIdx.x;
    float* p = attn + row * (size_t)NHID;
    const int tid  = threadIdx.x;
    const int lane = tid & 31;
    const int wid  = tid >> 5;
    __shared__ float red[8];

    float v[8];
    float mx = -1e30f;
    #pragma unroll
    for (int i = 0; i < 8; i++) {
        v[i] = p[tid + i * 256];
        mx = fmaxf(mx, v[i]);
    }
    #pragma unroll
    for (int o = 16; o; o >>= 1) mx = fmaxf(mx, __shfl_xor_sync(0xFFFFFFFFu, mx, o));
    if (lane == 0) red[wid] = mx;
    __syncthreads();
    mx = red[0];
    #pragma unroll
    for (int w = 1; w < 8; w++) mx = fmaxf(mx, red[w]);

    float s = 0.0f;
    #pragma unroll
    for (int i = 0; i < 8; i++) {
        v[i] = __expf(v[i] - mx);
        s += v[i];
    }
    #pragma unroll
    for (int o = 16; o; o >>= 1) s += __shfl_xor_sync(0xFFFFFFFFu, s, o);
    __syncthreads();               // everyone done reading red (max phase)
    if (lane == 0) red[wid] = s;
    __syncthreads();
    float tot = red[0];
    #pragma unroll
    for (int w = 1; w < 8; w++) tot += red[w];
    float inv = 1.0f / tot;
    #pragma unroll
    for (int i = 0; i < 8; i++) p[tid + i * 256] = v[i] * inv;
}

// ---------------------------------------------------------------------------
// Launch: x, Wq, keys, values, attn_scale, Wo  ->  out [4096,1024] fp32
// ---------------------------------------------------------------------------
extern "C" void kernel_launch(void* const* d_in, const int* in_sizes, int n_in,
                              void* d_out, int out_size) {
    const float* x     = (const float*)d_in[0];
    const float* Wq    = (const float*)d_in[1];
    const float* keys  = (const float*)d_in[2];
    const float* vals  = (const float*)d_in[3];
    const float* ascal = (const float*)d_in[4];
    const float* Wo    = (const float*)d_in[5];
    float* out = (float*)d_out;

    float *q, *khat, *attn, *y;
    cudaGetSymbolAddress((void**)&q,    g_q);
    cudaGetSymbolAddress((void**)&khat, g_khat);
    cudaGetSymbolAddress((void**)&attn, g_attn);
    cudaGetSymbolAddress((void**)&y,    g_y);

    // 1) normalize + scale keys: 16384 rows of 128
    normalize_rows128<<<(NHID * NHEADS) / 8, 256>>>(keys, khat, ascal,
                                                    NHID * NHEADS, 1);

    // 2) q = x @ Wq : [4096,1024] = [4096,1024] x [1024,1024]
    gemm_f32x2<false><<<dim3(S_LEN / 64, DMODEL / 128, 1), 128>>>(
        x, Wq, q, S_LEN, DMODEL, DMODEL, DMODEL, DMODEL, DMODEL, 0, 0, 0);

    // 3) normalize q rows (4096*8 rows of 128), in place
    normalize_rows128<<<(S_LEN * NHEADS) / 8, 256>>>(q, q, ascal,
                                                     S_LEN * NHEADS, 0);

    // 4) per-head logits: attn[h][s][j] = sum_d q[s,h*128+d] * khat[j*1024 + h*128 + d]
    gemm_f32x2<true><<<dim3(S_LEN / 64, NHID / 128, NHEADS), 128>>>(
        q, khat, attn,
        S_LEN, NHID, HDIM,
        DMODEL, DMODEL, NHID,
        (long long)HDIM, (long long)HDIM, (long long)S_LEN * NHID);

    // 5) softmax over slots
    softmax2048<<<NHEADS * S_LEN, 256>>>(attn);

    // 6) per-head y[s, h*128+d] = sum_j attn[h][s][j] * values[j*1024 + h*128 + d]
    gemm_f32x2<false><<<dim3(S_LEN / 64, HDIM / 128, NHEADS), 128>>>(
        attn, vals, y,
        S_LEN, HDIM, NHID,
        NHID, DMODEL, DMODEL,
        (long long)S_LEN * NHID, (long long)HDIM, (long long)HDIM);

    // 7) out = y @ Wo
    gemm_f32x2<false><<<dim3(S_LEN / 64, DMODEL / 128, 1), 128>>>(
        y, Wo, out, S_LEN, DMODEL, DMODEL, DMODEL, DMODEL, DMODEL, 0, 0, 0);
}

// round 3
// speedup vs baseline: 2.2703x; 2.2703x over previous
#include <cuda_runtime.h>
#include <cuda_bf16.h>
#include <stdint.h>

#define S_LEN   4096
#define DMODEL  1024
#define NHEADS  8
#define HDIM    128
#define NHID    2048
#define EPSN    1e-6f

// ---------------------------------------------------------------------------
// Scratch (device globals — no allocations allowed)
// ---------------------------------------------------------------------------
__device__ __align__(16) __nv_bfloat16 g_xh[(size_t)S_LEN * DMODEL];
__device__ __align__(16) __nv_bfloat16 g_xl[(size_t)S_LEN * DMODEL];
__device__ __align__(16) __nv_bfloat16 g_wqt_h[(size_t)DMODEL * DMODEL];
__device__ __align__(16) __nv_bfloat16 g_wqt_l[(size_t)DMODEL * DMODEL];
__device__ __align__(16) __nv_bfloat16 g_wot_h[(size_t)DMODEL * DMODEL];
__device__ __align__(16) __nv_bfloat16 g_wot_l[(size_t)DMODEL * DMODEL];
__device__ __align__(16) float         g_qf[(size_t)S_LEN * DMODEL];
__device__ __align__(16) __nv_bfloat16 g_qh[(size_t)S_LEN * DMODEL];
__device__ __align__(16) __nv_bfloat16 g_ql[(size_t)S_LEN * DMODEL];
__device__ __align__(16) __nv_bfloat16 g_kh[(size_t)NHID * NHEADS * HDIM];
__device__ __align__(16) __nv_bfloat16 g_kl[(size_t)NHID * NHEADS * HDIM];
__device__ __align__(16) __nv_bfloat16 g_vth[(size_t)NHEADS * HDIM * NHID];
__device__ __align__(16) __nv_bfloat16 g_vtl[(size_t)NHEADS * HDIM * NHID];
__device__ __align__(16) float         g_attn[(size_t)NHEADS * S_LEN * NHID];
__device__ __align__(16) __nv_bfloat16 g_ph[(size_t)NHEADS * S_LEN * NHID];
__device__ __align__(16) __nv_bfloat16 g_pl[(size_t)NHEADS * S_LEN * NHID];
__device__ __align__(16) float         g_yf[(size_t)S_LEN * DMODEL];
__device__ __align__(16) __nv_bfloat16 g_yh[(size_t)S_LEN * DMODEL];
__device__ __align__(16) __nv_bfloat16 g_yl[(size_t)S_LEN * DMODEL];

// ---------------------------------------------------------------------------
// PTX helpers (baseline sm_80+ instructions only — no 'a'-suffix features)
// ---------------------------------------------------------------------------
__device__ __forceinline__ uint32_t smem_u32(const void* p) {
    uint32_t a;
    asm("{ .reg .u64 t; cvta.to.shared.u64 t, %1; cvt.u32.u64 %0, t; }"
        : "=r"(a) : "l"(p));
    return a;
}
__device__ __forceinline__ void cp16(uint32_t s, const void* g) {
    asm volatile("cp.async.cg.shared.global [%0], [%1], 16;" :: "r"(s), "l"(g));
}
#define CP_COMMIT() asm volatile("cp.async.commit_group;" ::: "memory")
#define CP_WAIT1()  asm volatile("cp.async.wait_group 1;" ::: "memory")

__device__ __forceinline__ void ldsm4(uint32_t& r0, uint32_t& r1,
                                      uint32_t& r2, uint32_t& r3, uint32_t a) {
    asm volatile("ldmatrix.sync.aligned.m8n8.x4.shared.b16 {%0,%1,%2,%3}, [%4];"
                 : "=r"(r0), "=r"(r1), "=r"(r2), "=r"(r3) : "r"(a));
}
__device__ __forceinline__ void mma_bf16(float* d, const uint32_t* a, const uint32_t* b) {
    asm volatile(
        "mma.sync.aligned.m16n8k16.row.col.f32.bf16.bf16.f32 "
        "{%0,%1,%2,%3}, {%4,%5,%6,%7}, {%8,%9}, {%0,%1,%2,%3};"
        : "+f"(d[0]), "+f"(d[1]), "+f"(d[2]), "+f"(d[3])
        : "r"(a[0]), "r"(a[1]), "r"(a[2]), "r"(a[3]), "r"(b[0]), "r"(b[1]));
}

// ---------------------------------------------------------------------------
// Split-bf16 HMMA GEMM: C[128,128] fp32 tile = sum_k (Ah+Al)[m,k]*(Bh+Bl)[n,k]
// A: [M,K] K-major, B: [N,K] K-major. K multiple of 32.
// 256 threads, 8 warps (4 M x 2 N), warp tile 32x64, 3-stage cp.async.
// smem per stage: 4 tiles of 128 rows x 80B (32 bf16 data + 16B pad) = 40960B.
// ---------------------------------------------------------------------------
#define STAGE_B 40960
#define TILE_B  10240

__global__ __launch_bounds__(256, 1)
void gemm_mma(const __nv_bfloat16* __restrict__ Ah, const __nv_bfloat16* __restrict__ Al,
              const __nv_bfloat16* __restrict__ Bh, const __nv_bfloat16* __restrict__ Bl,
              float* __restrict__ C, int K,
              int lda, int ldb, int ldc,
              long long aZ, long long bZ, long long cZ)
{
    extern __shared__ char smem[];
    const uint32_t sbase = smem_u32(smem);
    const int tid = threadIdx.x;
    const int wid = tid >> 5, lane = tid & 31;
    const int wm = wid & 3, wn = wid >> 2;
    const int m0 = blockIdx.x * 128, n0 = blockIdx.y * 128;
    const long long z = blockIdx.z;
    Ah += z * aZ; Al += z * aZ; Bh += z * bZ; Bl += z * bZ; C += z * cZ;

    const int nc = K / 32;

    // per-thread load map: 512 16B-transfers per tile, 2 iterations
    const int lr0 = tid >> 2, lc0 = tid & 3;       // row, chunk for iter 0
    const int lr1 = lr0 + 64;                      // iter 1 (+256 threads)

    auto load_stage = [&](int c) {
        const int k0 = c * 32;
        const uint32_t sb = sbase + (uint32_t)(c % 3) * STAGE_B;
        // iter 0
        {
            uint32_t sa = sb + (uint32_t)(lr0 * 80 + lc0 * 16);
            long long ga = (long long)(m0 + lr0) * lda + k0 + lc0 * 8;
            cp16(sa, Ah + ga);
            cp16(sa + TILE_B, Al + ga);
            long long gb = (long long)(n0 + lr0) * ldb + k0 + lc0 * 8;
            cp16(sa + 2 * TILE_B, Bh + gb);
            cp16(sa + 3 * TILE_B, Bl + gb);
        }
        // iter 1
        {
            uint32_t sa = sb + (uint32_t)(lr1 * 80 + lc0 * 16);
            long long ga = (long long)(m0 + lr1) * lda + k0 + lc0 * 8;
            cp16(sa, Ah + ga);
            cp16(sa + TILE_B, Al + ga);
            long long gb = (long long)(n0 + lr1) * ldb + k0 + lc0 * 8;
            cp16(sa + 2 * TILE_B, Bh + gb);
            cp16(sa + 3 * TILE_B, Bl + gb);
        }
    };

    // ldmatrix lane address components (byte offsets within a tile region)
    //   A m-tile mt, k-step kk: row = wm*32 + mt*16 + (lane&15); chunk = kk/8 + (lane>=16)
    const uint32_t arow = (uint32_t)((wm * 32 + (lane & 15)) * 80 + (lane >> 4) * 16);
    //   B pair p (16 n-rows): row = wn*64 + p*16 + ((lane>>4)<<3) + (lane&7); chunk = kk/8 + ((lane>>3)&1)
    const uint32_t brow = (uint32_t)((wn * 64 + ((lane >> 4) << 3) + (lane & 7)) * 80
                                     + ((lane >> 3) & 1) * 16);

    float acc[2][8][4];
    #pragma unroll
    for (int i = 0; i < 2; i++)
        #pragma unroll
        for (int j = 0; j < 8; j++)
            #pragma unroll
            for (int q = 0; q < 4; q++) acc[i][j][q] = 0.0f;

    load_stage(0); CP_COMMIT();
    if (nc > 1) load_stage(1);
    CP_COMMIT();

    for (int c = 0; c < nc; c++) {
        CP_WAIT1();
        __syncthreads();
        if (c + 2 < nc) load_stage(c + 2);
        CP_COMMIT();

        const uint32_t sb = sbase + (uint32_t)(c % 3) * STAGE_B;
        #pragma unroll
        for (int kk = 0; kk < 2; kk++) {           // two k16 steps
            const uint32_t kbyte = (uint32_t)(kk * 32);
            uint32_t ah[2][4], al[2][4];
            #pragma unroll
            for (int mt = 0; mt < 2; mt++) {
                uint32_t ad = sb + arow + (uint32_t)(mt * 16 * 80) + kbyte;
                ldsm4(ah[mt][0], ah[mt][1], ah[mt][2], ah[mt][3], ad);
                ldsm4(al[mt][0], al[mt][1], al[mt][2], al[mt][3], ad + TILE_B);
            }
            uint32_t bh[8][2], bl[8][2];
            #pragma unroll
            for (int p = 0; p < 4; p++) {
                uint32_t bd = sb + 2 * TILE_B + brow + (uint32_t)(p * 16 * 80) + kbyte;
                ldsm4(bh[2*p][0], bh[2*p][1], bh[2*p+1][0], bh[2*p+1][1], bd);
                ldsm4(bl[2*p][0], bl[2*p][1], bl[2*p+1][0], bl[2*p+1][1], bd + TILE_B);
            }
            #pragma unroll
            for (int mt = 0; mt < 2; mt++)
                #pragma unroll
                for (int nt = 0; nt < 8; nt++) {
                    mma_bf16(acc[mt][nt], ah[mt], bh[nt]);
                    mma_bf16(acc[mt][nt], ah[mt], bl[nt]);
                    mma_bf16(acc[mt][nt], al[mt], bh[nt]);
                }
        }
        __syncthreads();
    }

    // Epilogue: direct fp32 stores
    const int mb = m0 + wm * 32 + (lane >> 2);
    const int nb = n0 + wn * 64 + (lane & 3) * 2;
    #pragma unroll
    for (int mt = 0; mt < 2; mt++)
        #pragma unroll
        for (int nt = 0; nt < 8; nt++) {
            int m = mb + mt * 16;
            int n = nb + nt * 8;
            float2 v0 = {acc[mt][nt][0], acc[mt][nt][1]};
            float2 v1 = {acc[mt][nt][2], acc[mt][nt][3]};
            *reinterpret_cast<float2*>(C + (long long)m * ldc + n) = v0;
            *reinterpret_cast<float2*>(C + (long long)(m + 8) * ldc + n) = v1;
        }
}

// ---------------------------------------------------------------------------
// Elementwise fp32 -> (hi, lo) bf16 split
// ---------------------------------------------------------------------------
__global__ void split_kernel(const float* __restrict__ in,
                             __nv_bfloat16* __restrict__ hi,
                             __nv_bfloat16* __restrict__ lo, size_t n4) {
    size_t i = (size_t)blockIdx.x * blockDim.x + threadIdx.x;
    if (i >= n4) return;
    float4 v = reinterpret_cast<const float4*>(in)[i];
    __nv_bfloat16 h0 = __float2bfloat16_rn(v.x), h1 = __float2bfloat16_rn(v.y);
    __nv_bfloat16 h2 = __float2bfloat16_rn(v.z), h3 = __float2bfloat16_rn(v.w);
    __nv_bfloat162 H0 = {h0, h1}, H1 = {h2, h3};
    __nv_bfloat162 L0 = {__float2bfloat16_rn(v.x - __bfloat162float(h0)),
                         __float2bfloat16_rn(v.y - __bfloat162float(h1))};
    __nv_bfloat162 L1 = {__float2bfloat16_rn(v.z - __bfloat162float(h2)),
                         __float2bfloat16_rn(v.w - __bfloat162float(h3))};
    reinterpret_cast<__nv_bfloat162*>(hi)[i * 2]     = H0;
    reinterpret_cast<__nv_bfloat162*>(hi)[i * 2 + 1] = H1;
    reinterpret_cast<__nv_bfloat162*>(lo)[i * 2]     = L0;
    reinterpret_cast<__nv_bfloat162*>(lo)[i * 2 + 1] = L1;
}

// ---------------------------------------------------------------------------
// Transpose + split: out[c][r] = in[r][c], fp32 -> hi/lo bf16
// ---------------------------------------------------------------------------
__global__ void transpose_split(const float* __restrict__ in, int ldi, long long inZ,
                                __nv_bfloat16* __restrict__ oh,
                                __nv_bfloat16* __restrict__ ol, int ldo, long long outZ) {
    __shared__ float t[32][33];
    in += blockIdx.z * inZ;
    const long long ob = blockIdx.z * outZ;
    const int r0 = blockIdx.y * 32, c0 = blockIdx.x * 32;
    #pragma unroll
    for (int i = threadIdx.y; i < 32; i += 8)
        t[i][threadIdx.x] = in[(long long)(r0 + i) * ldi + c0 + threadIdx.x];
    __syncthreads();
    #pragma unroll
    for (int i = threadIdx.y; i < 32; i += 8) {
        float v = t[threadIdx.x][i];
        __nv_bfloat16 h = __float2bfloat16_rn(v);
        long long o = ob + (long long)(c0 + i) * ldo + r0 + threadIdx.x;
        oh[o] = h;
        ol[o] = __float2bfloat16_rn(v - __bfloat162float(h));
    }
}

// ---------------------------------------------------------------------------
// Row (128) L2-normalize, optional per-head scale, emit hi/lo bf16
// ---------------------------------------------------------------------------
__global__ void normalize_split(const float* __restrict__ src,
                                __nv_bfloat16* __restrict__ hi,
                                __nv_bfloat16* __restrict__ lo,
                                const float* __restrict__ attn_scale,
                                int nrows, int useScale) {
    int row  = blockIdx.x * (blockDim.x >> 5) + (threadIdx.x >> 5);
    int lane = threadIdx.x & 31;
    if (row >= nrows) return;
    float4 v = reinterpret_cast<const float4*>(src + (size_t)row * HDIM)[lane];
    float ss = v.x * v.x + v.y * v.y + v.z * v.z + v.w * v.w;
    #pragma unroll
    for (int o = 16; o; o >>= 1) ss += __shfl_xor_sync(0xFFFFFFFFu, ss, o);
    float sc = rsqrtf(ss + EPSN);
    if (useScale) sc *= attn_scale[row & (NHEADS - 1)];
    float f[4] = {v.x * sc, v.y * sc, v.z * sc, v.w * sc};
    size_t off = (size_t)row * HDIM + lane * 4;
    __nv_bfloat16 h[4];
    #pragma unroll
    for (int i = 0; i < 4; i++) h[i] = __float2bfloat16_rn(f[i]);
    __nv_bfloat162 H0 = {h[0], h[1]}, H1 = {h[2], h[3]};
    __nv_bfloat162 L0 = {__float2bfloat16_rn(f[0] - __bfloat162float(h[0])),
                         __float2bfloat16_rn(f[1] - __bfloat162float(h[1]))};
    __nv_bfloat162 L1 = {__float2bfloat16_rn(f[2] - __bfloat162float(h[2])),
                         __float2bfloat16_rn(f[3] - __bfloat162float(h[3]))};
    *reinterpret_cast<__nv_bfloat162*>(hi + off)     = H0;
    *reinterpret_cast<__nv_bfloat162*>(hi + off + 2) = H1;
    *reinterpret_cast<__nv_bfloat162*>(lo + off)     = L0;
    *reinterpret_cast<__nv_bfloat162*>(lo + off + 2) = L1;
}

// ---------------------------------------------------------------------------
// Softmax over rows of 2048 + split to hi/lo bf16
// ---------------------------------------------------------------------------
__global__ __launch_bounds__(256)
void softmax_split(const float* __restrict__ attn,
                   __nv_bfloat16* __restrict__ ph, __nv_bfloat16* __restrict__ pl) {
    const size_t row = blockIdx.x;
    const float* p = attn + row * (size_t)NHID;
    const int tid = threadIdx.x, lane = tid & 31, wid = tid >> 5;
    __shared__ float red[8];
    float v[8];
    float mx = -1e30f;
    #pragma unroll
    for (int i = 0; i < 8; i++) { v[i] = p[tid + i * 256]; mx = fmaxf(mx, v[i]); }
    #pragma unroll
    for (int o = 16; o; o >>= 1) mx = fmaxf(mx, __shfl_xor_sync(0xFFFFFFFFu, mx, o));
    if (lane == 0) red[wid] = mx;
    __syncthreads();
    mx = red[0];
    #pragma unroll
    for (int w = 1; w < 8; w++) mx = fmaxf(mx, red[w]);
    float s = 0.0f;
    #pragma unroll
    for (int i = 0; i < 8; i++) { v[i] = __expf(v[i] - mx); s += v[i]; }
    #pragma unroll
    for (int o = 16; o; o >>= 1) s += __shfl_xor_sync(0xFFFFFFFFu, s, o);
    __syncthreads();
    if (lane == 0) red[wid] = s;
    __syncthreads();
    float tot = red[0];
    #pragma unroll
    for (int w = 1; w < 8; w++) tot += red[w];
    float inv = 1.0f / tot;
    #pragma unroll
    for (int i = 0; i < 8; i++) {
        float pv = v[i] * inv;
        __nv_bfloat16 h = __float2bfloat16_rn(pv);
        ph[row * (size_t)NHID + tid + i * 256] = h;
        pl[row * (size_t)NHID + tid + i * 256] =
            __float2bfloat16_rn(pv - __bfloat162float(h));
    }
}

// ---------------------------------------------------------------------------
// Launch
// ---------------------------------------------------------------------------
extern "C" void kernel_launch(void* const* d_in, const int* in_sizes, int n_in,
                              void* d_out, int out_size) {
    const float* x     = (const float*)d_in[0];
    const float* Wq    = (const float*)d_in[1];
    const float* keys  = (const float*)d_in[2];
    const float* vals  = (const float*)d_in[3];
    const float* ascal = (const float*)d_in[4];
    const float* Wo    = (const float*)d_in[5];
    float* out = (float*)d_out;

    __nv_bfloat16 *xh, *xl, *wqh, *wql, *woh, *wol, *qh, *ql, *kh, *kl;
    __nv_bfloat16 *vth, *vtl, *ph, *pl, *yh, *yl;
    float *qf, *attn, *yf;
    cudaGetSymbolAddress((void**)&xh, g_xh);   cudaGetSymbolAddress((void**)&xl, g_xl);
    cudaGetSymbolAddress((void**)&wqh, g_wqt_h); cudaGetSymbolAddress((void**)&wql, g_wqt_l);
    cudaGetSymbolAddress((void**)&woh, g_wot_h); cudaGetSymbolAddress((void**)&wol, g_wot_l);
    cudaGetSymbolAddress((void**)&qf, g_qf);
    cudaGetSymbolAddress((void**)&qh, g_qh);   cudaGetSymbolAddress((void**)&ql, g_ql);
    cudaGetSymbolAddress((void**)&kh, g_kh);   cudaGetSymbolAddress((void**)&kl, g_kl);
    cudaGetSymbolAddress((void**)&vth, g_vth); cudaGetSymbolAddress((void**)&vtl, g_vtl);
    cudaGetSymbolAddress((void**)&attn, g_attn);
    cudaGetSymbolAddress((void**)&ph, g_ph);   cudaGetSymbolAddress((void**)&pl, g_pl);
    cudaGetSymbolAddress((void**)&yf, g_yf);
    cudaGetSymbolAddress((void**)&yh, g_yh);   cudaGetSymbolAddress((void**)&yl, g_yl);

    const int SMEM = 3 * STAGE_B;   // 122880 B
    cudaFuncSetAttribute(gemm_mma, cudaFuncAttributeMaxDynamicSharedMemorySize, SMEM);

    // ---- prep ----
    split_kernel<<<(S_LEN * DMODEL / 4 + 255) / 256, 256>>>(x, xh, xl,
                                                            (size_t)S_LEN * DMODEL / 4);
    transpose_split<<<dim3(32, 32, 1), dim3(32, 8)>>>(Wq, DMODEL, 0, wqh, wql, DMODEL, 0);
    transpose_split<<<dim3(32, 32, 1), dim3(32, 8)>>>(Wo, DMODEL, 0, woh, wol, DMODEL, 0);
    // vT[h][d][j] = values[j][h*128+d]
    transpose_split<<<dim3(HDIM / 32, NHID / 32, NHEADS), dim3(32, 8)>>>(
        vals, DMODEL, (long long)HDIM, vth, vtl, NHID, (long long)HDIM * NHID);
    // khat: normalize+scale key rows -> hi/lo
    normalize_split<<<(NHID * NHEADS) / 8, 256>>>(keys, kh, kl, ascal,
                                                  NHID * NHEADS, 1);

    // ---- Q-proj: qf[4096,1024] = x @ Wq  (B = WqT, K-major) ----
    gemm_mma<<<dim3(S_LEN / 128, DMODEL / 128, 1), 256, SMEM>>>(
        xh, xl, wqh, wql, qf, DMODEL, DMODEL, DMODEL, DMODEL, 0, 0, 0);

    // ---- normalize q -> hi/lo ----
    normalize_split<<<(S_LEN * NHEADS) / 8, 256>>>(qf, qh, ql, ascal,
                                                   S_LEN * NHEADS, 0);

    // ---- QK: attn[h][s][j], K=128 per head ----
    gemm_mma<<<dim3(S_LEN / 128, NHID / 128, NHEADS), 256, SMEM>>>(
        qh, ql, kh, kl, attn, HDIM,
        DMODEL, DMODEL, NHID,
        (long long)HDIM, (long long)HDIM, (long long)S_LEN * NHID);

    // ---- softmax + split ----
    softmax_split<<<NHEADS * S_LEN, 256>>>(attn, ph, pl);

    // ---- AV: yf[s][h*128+d] = P[h] @ vT[h], K=2048 ----
    gemm_mma<<<dim3(S_LEN / 128, 1, NHEADS), 256, SMEM>>>(
        ph, pl, vth, vtl, yf, NHID,
        NHID, NHID, DMODEL,
        (long long)S_LEN * NHID, (long long)HDIM * NHID, (long long)HDIM);

    // ---- split y ----
    split_kernel<<<(S_LEN * DMODEL / 4 + 255) / 256, 256>>>(yf, yh, yl,
                                                            (size_t)S_LEN * DMODEL / 4);

    // ---- O-proj: out = y @ Wo ----
    gemm_mma<<<dim3(S_LEN / 128, DMODEL / 128, 1), 256, SMEM>>>(
        yh, yl, woh, wol, out, DMODEL, DMODEL, DMODEL, DMODEL, 0, 0, 0);
}

// round 4
// speedup vs baseline: 2.8866x; 1.2715x over previous
#include <cuda_runtime.h>
#include <cuda_bf16.h>
#include <stdint.h>

#define S_LEN   4096
#define DMODEL  1024
#define NHEADS  8
#define HDIM    128
#define NHID    2048
#define EPSN    1e-6f
#define CHUNK   64
#define NCHUNK  (NHID / CHUNK)

// ---------------------------------------------------------------------------
// Scratch (device globals — no allocations allowed)
// ---------------------------------------------------------------------------
__device__ __align__(16) __nv_bfloat16 g_xh[(size_t)S_LEN * DMODEL];
__device__ __align__(16) __nv_bfloat16 g_xl[(size_t)S_LEN * DMODEL];
__device__ __align__(16) __nv_bfloat16 g_wqt_h[(size_t)DMODEL * DMODEL];
__device__ __align__(16) __nv_bfloat16 g_wqt_l[(size_t)DMODEL * DMODEL];
__device__ __align__(16) __nv_bfloat16 g_wot_h[(size_t)DMODEL * DMODEL];
__device__ __align__(16) __nv_bfloat16 g_wot_l[(size_t)DMODEL * DMODEL];
__device__ __align__(16) float         g_qf[(size_t)S_LEN * DMODEL];
__device__ __align__(16) __nv_bfloat16 g_qh[(size_t)S_LEN * DMODEL];
__device__ __align__(16) __nv_bfloat16 g_ql[(size_t)S_LEN * DMODEL];
__device__ __align__(16) __nv_bfloat16 g_kh[(size_t)NHID * NHEADS * HDIM];
__device__ __align__(16) __nv_bfloat16 g_kl[(size_t)NHID * NHEADS * HDIM];
__device__ __align__(16) __nv_bfloat16 g_vth[(size_t)NHEADS * HDIM * NHID];
__device__ __align__(16) __nv_bfloat16 g_vtl[(size_t)NHEADS * HDIM * NHID];
__device__ __align__(16) __nv_bfloat16 g_yh[(size_t)S_LEN * DMODEL];
__device__ __align__(16) __nv_bfloat16 g_yl[(size_t)S_LEN * DMODEL];

// ---------------------------------------------------------------------------
// PTX helpers (baseline sm_80+ only)
// ---------------------------------------------------------------------------
__device__ __forceinline__ uint32_t smem_u32(const void* p) {
    uint32_t a;
    asm("{ .reg .u64 t; cvta.to.shared.u64 t, %1; cvt.u32.u64 %0, t; }"
        : "=r"(a) : "l"(p));
    return a;
}
__device__ __forceinline__ void cp16(uint32_t s, const void* g) {
    asm volatile("cp.async.cg.shared.global [%0], [%1], 16;" :: "r"(s), "l"(g));
}
#define CP_COMMIT() asm volatile("cp.async.commit_group;" ::: "memory")
#define CP_WAIT(n)  asm volatile("cp.async.wait_group %0;" :: "n"(n) : "memory")

__device__ __forceinline__ void ldsm4(uint32_t& r0, uint32_t& r1,
                                      uint32_t& r2, uint32_t& r3, uint32_t a) {
    asm volatile("ldmatrix.sync.aligned.m8n8.x4.shared.b16 {%0,%1,%2,%3}, [%4];"
                 : "=r"(r0), "=r"(r1), "=r"(r2), "=r"(r3) : "r"(a));
}
__device__ __forceinline__ void mma_bf16(float* d, const uint32_t* a, const uint32_t* b) {
    asm volatile(
        "mma.sync.aligned.m16n8k16.row.col.f32.bf16.bf16.f32 "
        "{%0,%1,%2,%3}, {%4,%5,%6,%7}, {%8,%9}, {%0,%1,%2,%3};"
        : "+f"(d[0]), "+f"(d[1]), "+f"(d[2]), "+f"(d[3])
        : "r"(a[0]), "r"(a[1]), "r"(a[2]), "r"(a[3]), "r"(b[0]), "r"(b[1]));
}
// pack two fp32 -> bf16x2 register, low = x, high = y
__device__ __forceinline__ uint32_t pkbf(float x, float y) {
    uint32_t r;
    asm("cvt.rn.bf16x2.f32 %0, %1, %2;" : "=r"(r) : "f"(y), "f"(x));
    return r;
}

// ---------------------------------------------------------------------------
// Fused attention: per (128 q-rows, head): Y = softmax(Q·K^T) V, hi/lo bf16 out
// smem layout (bytes):
//   Q:   0      .. 81920   : 4 slabs hi (s*10240) + 4 slabs lo (+40960)
//                            slab = 128 rows x 80B (64B data = 32 bf16 dims)
//   K0:  81920, K1: 122880 : each 40960 = 4 slabs hi (s*5120, 64 rows x 80B)
//                            + lo (+20480)
//   V:   163840 .. 204800  : 2 slabs hi (s*10240, 128 rows x 80B) + lo (+20480)
// ---------------------------------------------------------------------------
#define SQ   0u
#define SK0  81920u
#define SK1  122880u
#define SV   163840u
#define SMEM_ATTN 204800

__global__ __launch_bounds__(256, 1)
void attn_fused(const __nv_bfloat16* __restrict__ qh, const __nv_bfloat16* __restrict__ ql,
                const __nv_bfloat16* __restrict__ kh, const __nv_bfloat16* __restrict__ kl,
                const __nv_bfloat16* __restrict__ vth, const __nv_bfloat16* __restrict__ vtl,
                __nv_bfloat16* __restrict__ yh, __nv_bfloat16* __restrict__ yl)
{
    extern __shared__ char smem[];
    const uint32_t sb = smem_u32(smem);
    const int tid = threadIdx.x;
    const int w = tid >> 5, lane = tid & 31;
    const int h = blockIdx.y;
    const int qrow0 = blockIdx.x * 128;

    const __nv_bfloat16* qhp = qh + (size_t)qrow0 * DMODEL + h * HDIM;
    const __nv_bfloat16* qlp = ql + (size_t)qrow0 * DMODEL + h * HDIM;
    const __nv_bfloat16* khp = kh + h * HDIM;
    const __nv_bfloat16* klp = kl + h * HDIM;
    const __nv_bfloat16* vhp = vth + (size_t)h * HDIM * NHID;
    const __nv_bfloat16* vlp = vtl + (size_t)h * HDIM * NHID;

    // ---- stage Q (group 0) ----
    #pragma unroll
    for (int it = 0; it < 8; it++) {
        int i = tid + it * 256;               // 0..2047
        int r = i >> 4, c = i & 15, s = c >> 2, c16 = c & 3;
        uint32_t sa = sb + SQ + (uint32_t)(s * 10240 + r * 80 + c16 * 16);
        size_t go = (size_t)r * DMODEL + s * 32 + c16 * 8;
        cp16(sa, qhp + go);
        cp16(sa + 40960, qlp + go);
    }
    CP_COMMIT();

    // ---- K chunk loader ----
    auto loadK = [&](int c) {
        const uint32_t kb = sb + ((c & 1) ? SK1 : SK0);
        const int j0 = c * CHUNK;
        const int r = tid >> 2, c16 = tid & 3;
        #pragma unroll
        for (int s = 0; s < 4; s++) {
            uint32_t sa = kb + (uint32_t)(s * 5120 + r * 80 + c16 * 16);
            size_t go = (size_t)(j0 + r) * DMODEL + s * 32 + c16 * 8;
            cp16(sa, khp + go);
            cp16(sa + 20480, klp + go);
        }
    };
    // ---- V chunk loader ----
    auto loadV = [&](int c) {
        const int j0 = c * CHUNK;
        #pragma unroll
        for (int it = 0; it < 4; it++) {
            int i = tid + it * 256;           // 0..1023
            int s = i >> 9, r = (i >> 2) & 127, c16 = i & 3;
            uint32_t sa = sb + SV + (uint32_t)(s * 10240 + r * 80 + c16 * 16);
            size_t go = (size_t)r * NHID + j0 + s * 32 + c16 * 8;
            cp16(sa, vhp + go);
            cp16(sa + 20480, vlp + go);
        }
    };

    loadK(0);
    CP_COMMIT();

    // ldmatrix address bases
    const uint32_t qa = (uint32_t)((w * 16 + (lane & 15)) * 80 + (lane >> 4) * 16);
    const uint32_t ba = (uint32_t)(((((lane >> 4) << 3) + (lane & 7)) * 80)
                                   + ((lane >> 3) & 1) * 16);

    float Y[16][4];
    #pragma unroll
    for (int i = 0; i < 16; i++)
        #pragma unroll
        for (int j = 0; j < 4; j++) Y[i][j] = 0.0f;
    float rm0 = -1e30f, rm1 = -1e30f, l0 = 0.0f, l1 = 0.0f;

    for (int c = 0; c < NCHUNK; c++) {
        loadV(c);
        CP_COMMIT();
        if (c + 1 < NCHUNK) { loadK(c + 1); CP_COMMIT(); CP_WAIT(2); }
        else                { CP_WAIT(1); }
        __syncthreads();

        // ---- QK: S[128 x 64] ----
        const uint32_t kb = sb + ((c & 1) ? SK1 : SK0);
        float S[8][4];
        #pragma unroll
        for (int i = 0; i < 8; i++)
            #pragma unroll
            for (int j = 0; j < 4; j++) S[i][j] = 0.0f;

        #pragma unroll
        for (int kk = 0; kk < 8; kk++) {
            uint32_t qaddr = sb + SQ + (uint32_t)((kk >> 1) * 10240 + (kk & 1) * 32) + qa;
            uint32_t ah[4], al[4];
            ldsm4(ah[0], ah[1], ah[2], ah[3], qaddr);
            ldsm4(al[0], al[1], al[2], al[3], qaddr + 40960);
            uint32_t bh[8][2], bl[8][2];
            #pragma unroll
            for (int p = 0; p < 4; p++) {
                uint32_t ka = kb + (uint32_t)((kk >> 1) * 5120 + p * 16 * 80 + (kk & 1) * 32) + ba;
                ldsm4(bh[2*p][0], bh[2*p][1], bh[2*p+1][0], bh[2*p+1][1], ka);
                ldsm4(bl[2*p][0], bl[2*p][1], bl[2*p+1][0], bl[2*p+1][1], ka + 20480);
            }
            #pragma unroll
            for (int nt = 0; nt < 8; nt++) {
                mma_bf16(S[nt], ah, bh[nt]);
                mma_bf16(S[nt], al, bh[nt]);
                mma_bf16(S[nt], ah, bl[nt]);
            }
        }

        // ---- online softmax ----
        float mx0 = -1e30f, mx1 = -1e30f;
        #pragma unroll
        for (int nt = 0; nt < 8; nt++) {
            mx0 = fmaxf(mx0, fmaxf(S[nt][0], S[nt][1]));
            mx1 = fmaxf(mx1, fmaxf(S[nt][2], S[nt][3]));
        }
        #pragma unroll
        for (int o = 1; o <= 2; o <<= 1) {
            mx0 = fmaxf(mx0, __shfl_xor_sync(0xFFFFFFFFu, mx0, o));
            mx1 = fmaxf(mx1, __shfl_xor_sync(0xFFFFFFFFu, mx1, o));
        }
        float nm0 = fmaxf(rm0, mx0), nm1 = fmaxf(rm1, mx1);
        float a0 = __expf(rm0 - nm0), a1 = __expf(rm1 - nm1);
        rm0 = nm0; rm1 = nm1;
        float s0 = 0.0f, s1 = 0.0f;
        #pragma unroll
        for (int nt = 0; nt < 8; nt++) {
            S[nt][0] = __expf(S[nt][0] - nm0);
            S[nt][1] = __expf(S[nt][1] - nm0);
            S[nt][2] = __expf(S[nt][2] - nm1);
            S[nt][3] = __expf(S[nt][3] - nm1);
            s0 += S[nt][0] + S[nt][1];
            s1 += S[nt][2] + S[nt][3];
        }
        #pragma unroll
        for (int o = 1; o <= 2; o <<= 1) {
            s0 += __shfl_xor_sync(0xFFFFFFFFu, s0, o);
            s1 += __shfl_xor_sync(0xFFFFFFFFu, s1, o);
        }
        l0 = l0 * a0 + s0;
        l1 = l1 * a1 + s1;
        #pragma unroll
        for (int nt = 0; nt < 16; nt++) {
            Y[nt][0] *= a0; Y[nt][1] *= a0; Y[nt][2] *= a1; Y[nt][3] *= a1;
        }

        // ---- pack P -> hi/lo bf16 A-fragments ----
        uint32_t pa[4][4], pl4[4][4];
        #pragma unroll
        for (int kk2 = 0; kk2 < 4; kk2++) {
            #pragma unroll
            for (int half = 0; half < 2; half++) {
                int nt = 2 * kk2 + half;
                uint32_t u01 = pkbf(S[nt][0], S[nt][1]);
                uint32_t u23 = pkbf(S[nt][2], S[nt][3]);
                float r0h = __uint_as_float(u01 << 16);
                float r1h = __uint_as_float(u01 & 0xFFFF0000u);
                float r2h = __uint_as_float(u23 << 16);
                float r3h = __uint_as_float(u23 & 0xFFFF0000u);
                pa[kk2][2*half]     = u01;
                pa[kk2][2*half + 1] = u23;
                pl4[kk2][2*half]     = pkbf(S[nt][0] - r0h, S[nt][1] - r1h);
                pl4[kk2][2*half + 1] = pkbf(S[nt][2] - r2h, S[nt][3] - r3h);
            }
        }

        // ---- wait V, then AV ----
        if (c + 1 < NCHUNK) CP_WAIT(1); else CP_WAIT(0);
        __syncthreads();

        #pragma unroll
        for (int kk2 = 0; kk2 < 4; kk2++) {
            #pragma unroll
            for (int p = 0; p < 8; p++) {
                uint32_t va = sb + SV + (uint32_t)((kk2 >> 1) * 10240 + p * 16 * 80
                                                   + (kk2 & 1) * 32) + ba;
                uint32_t vh[4], vl[4];
                ldsm4(vh[0], vh[1], vh[2], vh[3], va);
                ldsm4(vl[0], vl[1], vl[2], vl[3], va + 20480);
                uint32_t b0h[2] = {vh[0], vh[1]}, b1h[2] = {vh[2], vh[3]};
                uint32_t b0l[2] = {vl[0], vl[1]}, b1l[2] = {vl[2], vl[3]};
                mma_bf16(Y[2*p],     pa[kk2],  b0h);
                mma_bf16(Y[2*p],     pl4[kk2], b0h);
                mma_bf16(Y[2*p],     pa[kk2],  b0l);
                mma_bf16(Y[2*p + 1], pa[kk2],  b1h);
                mma_bf16(Y[2*p + 1], pl4[kk2], b1h);
                mma_bf16(Y[2*p + 1], pa[kk2],  b1l);
            }
        }
        __syncthreads();
    }

    // ---- epilogue: y = Y / l, split hi/lo bf16 ----
    const float r0 = 1.0f / l0, r1 = 1.0f / l1;
    const int g = lane >> 2, colb = (lane & 3) * 2;
    #pragma unroll
    for (int nt = 0; nt < 16; nt++) {
        float v0 = Y[nt][0] * r0, v1 = Y[nt][1] * r0;
        float v2 = Y[nt][2] * r1, v3 = Y[nt][3] * r1;
        uint32_t h01 = pkbf(v0, v1), h23 = pkbf(v2, v3);
        uint32_t lo01 = pkbf(v0 - __uint_as_float(h01 << 16),
                             v1 - __uint_as_float(h01 & 0xFFFF0000u));
        uint32_t lo23 = pkbf(v2 - __uint_as_float(h23 << 16),
                             v3 - __uint_as_float(h23 & 0xFFFF0000u));
        size_t o0 = (size_t)(qrow0 + w * 16 + g) * DMODEL + h * HDIM + nt * 8 + colb;
        size_t o1 = o0 + (size_t)8 * DMODEL;
        *reinterpret_cast<uint32_t*>(yh + o0) = h01;
        *reinterpret_cast<uint32_t*>(yl + o0) = lo01;
        *reinterpret_cast<uint32_t*>(yh + o1) = h23;
        *reinterpret_cast<uint32_t*>(yl + o1) = lo23;
    }
}

// ---------------------------------------------------------------------------
// Split-bf16 HMMA GEMM (unchanged from round 3) for the two projections
// ---------------------------------------------------------------------------
#define STAGE_B 40960
#define TILE_B  10240

__global__ __launch_bounds__(256, 1)
void gemm_mma(const __nv_bfloat16* __restrict__ Ah, const __nv_bfloat16* __restrict__ Al,
              const __nv_bfloat16* __restrict__ Bh, const __nv_bfloat16* __restrict__ Bl,
              float* __restrict__ C, int K,
              int lda, int ldb, int ldc,
              long long aZ, long long bZ, long long cZ)
{
    extern __shared__ char smem[];
    const uint32_t sbase = smem_u32(smem);
    const int tid = threadIdx.x;
    const int wid = tid >> 5, lane = tid & 31;
    const int wm = wid & 3, wn = wid >> 2;
    const int m0 = blockIdx.x * 128, n0 = blockIdx.y * 128;
    const long long z = blockIdx.z;
    Ah += z * aZ; Al += z * aZ; Bh += z * bZ; Bl += z * bZ; C += z * cZ;

    const int nc = K / 32;
    const int lr0 = tid >> 2, lc0 = tid & 3;
    const int lr1 = lr0 + 64;

    auto load_stage = [&](int c) {
        const int k0 = c * 32;
        const uint32_t sb = sbase + (uint32_t)(c % 3) * STAGE_B;
        {
            uint32_t sa = sb + (uint32_t)(lr0 * 80 + lc0 * 16);
            long long ga = (long long)(m0 + lr0) * lda + k0 + lc0 * 8;
            cp16(sa, Ah + ga);
            cp16(sa + TILE_B, Al + ga);
            long long gb = (long long)(n0 + lr0) * ldb + k0 + lc0 * 8;
            cp16(sa + 2 * TILE_B, Bh + gb);
            cp16(sa + 3 * TILE_B, Bl + gb);
        }
        {
            uint32_t sa = sb + (uint32_t)(lr1 * 80 + lc0 * 16);
            long long ga = (long long)(m0 + lr1) * lda + k0 + lc0 * 8;
            cp16(sa, Ah + ga);
            cp16(sa + TILE_B, Al + ga);
            long long gb = (long long)(n0 + lr1) * ldb + k0 + lc0 * 8;
            cp16(sa + 2 * TILE_B, Bh + gb);
            cp16(sa + 3 * TILE_B, Bl + gb);
        }
    };

    const uint32_t arow = (uint32_t)((wm * 32 + (lane & 15)) * 80 + (lane >> 4) * 16);
    const uint32_t brow = (uint32_t)((wn * 64 + ((lane >> 4) << 3) + (lane & 7)) * 80
                                     + ((lane >> 3) & 1) * 16);

    float acc[2][8][4];
    #pragma unroll
    for (int i = 0; i < 2; i++)
        #pragma unroll
        for (int j = 0; j < 8; j++)
            #pragma unroll
            for (int q = 0; q < 4; q++) acc[i][j][q] = 0.0f;

    load_stage(0); CP_COMMIT();
    if (nc > 1) load_stage(1);
    CP_COMMIT();

    for (int c = 0; c < nc; c++) {
        CP_WAIT(1);
        __syncthreads();
        if (c + 2 < nc) load_stage(c + 2);
        CP_COMMIT();

        const uint32_t sb = sbase + (uint32_t)(c % 3) * STAGE_B;
        #pragma unroll
        for (int kk = 0; kk < 2; kk++) {
            const uint32_t kbyte = (uint32_t)(kk * 32);
            uint32_t ah[2][4], al[2][4];
            #pragma unroll
            for (int mt = 0; mt < 2; mt++) {
                uint32_t ad = sb + arow + (uint32_t)(mt * 16 * 80) + kbyte;
                ldsm4(ah[mt][0], ah[mt][1], ah[mt][2], ah[mt][3], ad);
                ldsm4(al[mt][0], al[mt][1], al[mt][2], al[mt][3], ad + TILE_B);
            }
            uint32_t bh[8][2], bl[8][2];
            #pragma unroll
            for (int p = 0; p < 4; p++) {
                uint32_t bd = sb + 2 * TILE_B + brow + (uint32_t)(p * 16 * 80) + kbyte;
                ldsm4(bh[2*p][0], bh[2*p][1], bh[2*p+1][0], bh[2*p+1][1], bd);
                ldsm4(bl[2*p][0], bl[2*p][1], bl[2*p+1][0], bl[2*p+1][1], bd + TILE_B);
            }
            #pragma unroll
            for (int mt = 0; mt < 2; mt++)
                #pragma unroll
                for (int nt = 0; nt < 8; nt++) {
                    mma_bf16(acc[mt][nt], ah[mt], bh[nt]);
                    mma_bf16(acc[mt][nt], ah[mt], bl[nt]);
                    mma_bf16(acc[mt][nt], al[mt], bh[nt]);
                }
        }
        __syncthreads();
    }

    const int mb = m0 + wm * 32 + (lane >> 2);
    const int nb = n0 + wn * 64 + (lane & 3) * 2;
    #pragma unroll
    for (int mt = 0; mt < 2; mt++)
        #pragma unroll
        for (int nt = 0; nt < 8; nt++) {
            int m = mb + mt * 16;
            int n = nb + nt * 8;
            float2 v0 = {acc[mt][nt][0], acc[mt][nt][1]};
            float2 v1 = {acc[mt][nt][2], acc[mt][nt][3]};
            *reinterpret_cast<float2*>(C + (long long)m * ldc + n) = v0;
            *reinterpret_cast<float2*>(C + (long long)(m + 8) * ldc + n) = v1;
        }
}

// ---------------------------------------------------------------------------
// Elementwise fp32 -> (hi, lo) bf16 split
// ---------------------------------------------------------------------------
__global__ void split_kernel(const float* __restrict__ in,
                             __nv_bfloat16* __restrict__ hi,
                             __nv_bfloat16* __restrict__ lo, size_t n4) {
    size_t i = (size_t)blockIdx.x * blockDim.x + threadIdx.x;
    if (i >= n4) return;
    float4 v = reinterpret_cast<const float4*>(in)[i];
    __nv_bfloat16 h0 = __float2bfloat16_rn(v.x), h1 = __float2bfloat16_rn(v.y);
    __nv_bfloat16 h2 = __float2bfloat16_rn(v.z), h3 = __float2bfloat16_rn(v.w);
    __nv_bfloat162 H0 = {h0, h1}, H1 = {h2, h3};
    __nv_bfloat162 L0 = {__float2bfloat16_rn(v.x - __bfloat162float(h0)),
                         __float2bfloat16_rn(v.y - __bfloat162float(h1))};
    __nv_bfloat162 L1 = {__float2bfloat16_rn(v.z - __bfloat162float(h2)),
                         __float2bfloat16_rn(v.w - __bfloat162float(h3))};
    reinterpret_cast<__nv_bfloat162*>(hi)[i * 2]     = H0;
    reinterpret_cast<__nv_bfloat162*>(hi)[i * 2 + 1] = H1;
    reinterpret_cast<__nv_bfloat162*>(lo)[i * 2]     = L0;
    reinterpret_cast<__nv_bfloat162*>(lo)[i * 2 + 1] = L1;
}

// ---------------------------------------------------------------------------
// Transpose + split: out[c][r] = in[r][c], fp32 -> hi/lo bf16
// ---------------------------------------------------------------------------
__global__ void transpose_split(const float* __restrict__ in, int ldi, long long inZ,
                                __nv_bfloat16* __restrict__ oh,
                                __nv_bfloat16* __restrict__ ol, int ldo, long long outZ) {
    __shared__ float t[32][33];
    in += blockIdx.z * inZ;
    const long long ob = blockIdx.z * outZ;
    const int r0 = blockIdx.y * 32, c0 = blockIdx.x * 32;
    #pragma unroll
    for (int i = threadIdx.y; i < 32; i += 8)
        t[i][threadIdx.x] = in[(long long)(r0 + i) * ldi + c0 + threadIdx.x];
    __syncthreads();
    #pragma unroll
    for (int i = threadIdx.y; i < 32; i += 8) {
        float v = t[threadIdx.x][i];
        __nv_bfloat16 h = __float2bfloat16_rn(v);
        long long o = ob + (long long)(c0 + i) * ldo + r0 + threadIdx.x;
        oh[o] = h;
        ol[o] = __float2bfloat16_rn(v - __bfloat162float(h));
    }
}

// ---------------------------------------------------------------------------
// Row (128) L2-normalize, optional per-head scale, emit hi/lo bf16
// ---------------------------------------------------------------------------
__global__ void normalize_split(const float* __restrict__ src,
                                __nv_bfloat16* __restrict__ hi,
                                __nv_bfloat16* __restrict__ lo,
                                const float* __restrict__ attn_scale,
                                int nrows, int useScale) {
    int row  = blockIdx.x * (blockDim.x >> 5) + (threadIdx.x >> 5);
    int lane = threadIdx.x & 31;
    if (row >= nrows) return;
    float4 v = reinterpret_cast<const float4*>(src + (size_t)row * HDIM)[lane];
    float ss = v.x * v.x + v.y * v.y + v.z * v.z + v.w * v.w;
    #pragma unroll
    for (int o = 16; o; o >>= 1) ss += __shfl_xor_sync(0xFFFFFFFFu, ss, o);
    float sc = rsqrtf(ss + EPSN);
    if (useScale) sc *= attn_scale[row & (NHEADS - 1)];
    float f[4] = {v.x * sc, v.y * sc, v.z * sc, v.w * sc};
    size_t off = (size_t)row * HDIM + lane * 4;
    __nv_bfloat16 h[4];
    #pragma unroll
    for (int i = 0; i < 4; i++) h[i] = __float2bfloat16_rn(f[i]);
    __nv_bfloat162 H0 = {h[0], h[1]}, H1 = {h[2], h[3]};
    __nv_bfloat162 L0 = {__float2bfloat16_rn(f[0] - __bfloat162float(h[0])),
                         __float2bfloat16_rn(f[1] - __bfloat162float(h[1]))};
    __nv_bfloat162 L1 = {__float2bfloat16_rn(f[2] - __bfloat162float(h[2])),
                         __float2bfloat16_rn(f[3] - __bfloat162float(h[3]))};
    *reinterpret_cast<__nv_bfloat162*>(hi + off)     = H0;
    *reinterpret_cast<__nv_bfloat162*>(hi + off + 2) = H1;
    *reinterpret_cast<__nv_bfloat162*>(lo + off)     = L0;
    *reinterpret_cast<__nv_bfloat162*>(lo + off + 2) = L1;
}

// ---------------------------------------------------------------------------
// Launch
// ---------------------------------------------------------------------------
extern "C" void kernel_launch(void* const* d_in, const int* in_sizes, int n_in,
                              void* d_out, int out_size) {
    const float* x     = (const float*)d_in[0];
    const float* Wq    = (const float*)d_in[1];
    const float* keys  = (const float*)d_in[2];
    const float* vals  = (const float*)d_in[3];
    const float* ascal = (const float*)d_in[4];
    const float* Wo    = (const float*)d_in[5];
    float* out = (float*)d_out;

    __nv_bfloat16 *xh, *xl, *wqh, *wql, *woh, *wol, *qh, *ql, *kh, *kl;
    __nv_bfloat16 *vth, *vtl, *yh, *yl;
    float *qf;
    cudaGetSymbolAddress((void**)&xh, g_xh);   cudaGetSymbolAddress((void**)&xl, g_xl);
    cudaGetSymbolAddress((void**)&wqh, g_wqt_h); cudaGetSymbolAddress((void**)&wql, g_wqt_l);
    cudaGetSymbolAddress((void**)&woh, g_wot_h); cudaGetSymbolAddress((void**)&wol, g_wot_l);
    cudaGetSymbolAddress((void**)&qf, g_qf);
    cudaGetSymbolAddress((void**)&qh, g_qh);   cudaGetSymbolAddress((void**)&ql, g_ql);
    cudaGetSymbolAddress((void**)&kh, g_kh);   cudaGetSymbolAddress((void**)&kl, g_kl);
    cudaGetSymbolAddress((void**)&vth, g_vth); cudaGetSymbolAddress((void**)&vtl, g_vtl);
    cudaGetSymbolAddress((void**)&yh, g_yh);   cudaGetSymbolAddress((void**)&yl, g_yl);

    const int SMEM = 3 * STAGE_B;   // 122880 B
    cudaFuncSetAttribute(gemm_mma, cudaFuncAttributeMaxDynamicSharedMemorySize, SMEM);
    cudaFuncSetAttribute(attn_fused, cudaFuncAttributeMaxDynamicSharedMemorySize, SMEM_ATTN);

    // ---- prep ----
    split_kernel<<<(S_LEN * DMODEL / 4 + 255) / 256, 256>>>(x, xh, xl,
                                                            (size_t)S_LEN * DMODEL / 4);
    transpose_split<<<dim3(32, 32, 1), dim3(32, 8)>>>(Wq, DMODEL, 0, wqh, wql, DMODEL, 0);
    transpose_split<<<dim3(32, 32, 1), dim3(32, 8)>>>(Wo, DMODEL, 0, woh, wol, DMODEL, 0);
    transpose_split<<<dim3(HDIM / 32, NHID / 32, NHEADS), dim3(32, 8)>>>(
        vals, DMODEL, (long long)HDIM, vth, vtl, NHID, (long long)HDIM * NHID);
    normalize_split<<<(NHID * NHEADS) / 8, 256>>>(keys, kh, kl, ascal,
                                                  NHID * NHEADS, 1);

    // ---- Q-proj ----
    gemm_mma<<<dim3(S_LEN / 128, DMODEL / 128, 1), 256, SMEM>>>(
        xh, xl, wqh, wql, qf, DMODEL, DMODEL, DMODEL, DMODEL, 0, 0, 0);

    // ---- normalize q -> hi/lo ----
    normalize_split<<<(S_LEN * NHEADS) / 8, 256>>>(qf, qh, ql, ascal,
                                                   S_LEN * NHEADS, 0);

    // ---- fused attention: QK + softmax + AV ----
    attn_fused<<<dim3(S_LEN / 128, NHEADS), 256, SMEM_ATTN>>>(
        qh, ql, kh, kl, vth, vtl, yh, yl);

    // ---- O-proj: out = y @ Wo ----
    gemm_mma<<<dim3(S_LEN / 128, DMODEL / 128, 1), 256, SMEM>>>(
        yh, yl, woh, wol, out, DMODEL, DMODEL, DMODEL, DMODEL, 0, 0, 0);
}

// round 5
// speedup vs baseline: 3.4056x; 1.1798x over previous
#include <cuda_runtime.h>
#include <cuda_bf16.h>
#include <stdint.h>

#define S_LEN   4096
#define DMODEL  1024
#define NHEADS  8
#define HDIM    128
#define NHID    2048
#define EPSN    1e-6f
#define CHUNK   64
#define NCHUNK  (NHID / CHUNK)

// ---------------------------------------------------------------------------
// Scratch (device globals — no allocations allowed)
// ---------------------------------------------------------------------------
__device__ __align__(16) __nv_bfloat16 g_xh[(size_t)S_LEN * DMODEL];
__device__ __align__(16) __nv_bfloat16 g_xl[(size_t)S_LEN * DMODEL];   // unused (2-term Qproj)
__device__ __align__(16) __nv_bfloat16 g_wqt_h[(size_t)DMODEL * DMODEL];
__device__ __align__(16) __nv_bfloat16 g_wqt_l[(size_t)DMODEL * DMODEL];
__device__ __align__(16) __nv_bfloat16 g_wot_h[(size_t)DMODEL * DMODEL];
__device__ __align__(16) __nv_bfloat16 g_wot_l[(size_t)DMODEL * DMODEL];
__device__ __align__(16) float         g_qf[(size_t)S_LEN * DMODEL];
__device__ __align__(16) __nv_bfloat16 g_qh[(size_t)S_LEN * DMODEL];
__device__ __align__(16) __nv_bfloat16 g_ql[(size_t)S_LEN * DMODEL];   // unused (2-term QK)
__device__ __align__(16) __nv_bfloat16 g_kh[(size_t)NHID * NHEADS * HDIM];
__device__ __align__(16) __nv_bfloat16 g_kl[(size_t)NHID * NHEADS * HDIM];
__device__ __align__(16) __nv_bfloat16 g_vth[(size_t)NHEADS * HDIM * NHID];
__device__ __align__(16) __nv_bfloat16 g_vtl[(size_t)NHEADS * HDIM * NHID];
__device__ __align__(16) __nv_bfloat16 g_yh[(size_t)S_LEN * DMODEL];
__device__ __align__(16) __nv_bfloat16 g_yl[(size_t)S_LEN * DMODEL];

// ---------------------------------------------------------------------------
// PTX helpers (baseline sm_80+ only)
// ---------------------------------------------------------------------------
__device__ __forceinline__ uint32_t smem_u32(const void* p) {
    uint32_t a;
    asm("{ .reg .u64 t; cvta.to.shared.u64 t, %1; cvt.u32.u64 %0, t; }"
        : "=r"(a) : "l"(p));
    return a;
}
__device__ __forceinline__ void cp16(uint32_t s, const void* g) {
    asm volatile("cp.async.cg.shared.global [%0], [%1], 16;" :: "r"(s), "l"(g));
}
#define CP_COMMIT() asm volatile("cp.async.commit_group;" ::: "memory")
#define CP_WAIT(n)  asm volatile("cp.async.wait_group %0;" :: "n"(n) : "memory")

__device__ __forceinline__ void ldsm4(uint32_t& r0, uint32_t& r1,
                                      uint32_t& r2, uint32_t& r3, uint32_t a) {
    asm volatile("ldmatrix.sync.aligned.m8n8.x4.shared.b16 {%0,%1,%2,%3}, [%4];"
                 : "=r"(r0), "=r"(r1), "=r"(r2), "=r"(r3) : "r"(a));
}
__device__ __forceinline__ void mma_bf16(float* d, const uint32_t* a, const uint32_t* b) {
    asm volatile(
        "mma.sync.aligned.m16n8k16.row.col.f32.bf16.bf16.f32 "
        "{%0,%1,%2,%3}, {%4,%5,%6,%7}, {%8,%9}, {%0,%1,%2,%3};"
        : "+f"(d[0]), "+f"(d[1]), "+f"(d[2]), "+f"(d[3])
        : "r"(a[0]), "r"(a[1]), "r"(a[2]), "r"(a[3]), "r"(b[0]), "r"(b[1]));
}
// pack two fp32 -> bf16x2 register, low = x, high = y
__device__ __forceinline__ uint32_t pkbf(float x, float y) {
    uint32_t r;
    asm("cvt.rn.bf16x2.f32 %0, %1, %2;" : "=r"(r) : "f"(y), "f"(x));
    return r;
}

// ---------------------------------------------------------------------------
// Fused attention: per (128 q-rows, head): Y = softmax(Q·K^T) V, hi/lo bf16 out
// QK uses 2-term split (qh·kh + qh·kl); AV uses 3-term. No running max:
// |logits| <= attn_scale, so unnormalized exp is fp32-safe; divide by l at end.
// smem (bytes):
//   Q:  0      .. 40960  : 4 slabs hi (s*10240), slab = 128 rows x 80B
//   K0: 40960, K1: 81920 : 4 slabs hi (s*5120, 64 rows x 80B) + lo (+20480)
//   V0: 122880, V1: 163840 : 2 slabs hi (s*10240, 128 rows x 80B) + lo (+20480)
// ---------------------------------------------------------------------------
#define SQ   0u
#define SK0  40960u
#define SK1  81920u
#define SV0  122880u
#define SV1  163840u
#define SMEM_ATTN 204800

__global__ __launch_bounds__(256, 1)
void attn_fused(const __nv_bfloat16* __restrict__ qh,
                const __nv_bfloat16* __restrict__ kh, const __nv_bfloat16* __restrict__ kl,
                const __nv_bfloat16* __restrict__ vth, const __nv_bfloat16* __restrict__ vtl,
                __nv_bfloat16* __restrict__ yh, __nv_bfloat16* __restrict__ yl)
{
    extern __shared__ char smem[];
    const uint32_t sb = smem_u32(smem);
    const int tid = threadIdx.x;
    const int w = tid >> 5, lane = tid & 31;
    const int h = blockIdx.y;
    const int qrow0 = blockIdx.x * 128;

    const __nv_bfloat16* qhp = qh + (size_t)qrow0 * DMODEL + h * HDIM;
    const __nv_bfloat16* khp = kh + h * HDIM;
    const __nv_bfloat16* klp = kl + h * HDIM;
    const __nv_bfloat16* vhp = vth + (size_t)h * HDIM * NHID;
    const __nv_bfloat16* vlp = vtl + (size_t)h * HDIM * NHID;

    // ---- stage Q hi (group 0) ----
    #pragma unroll
    for (int it = 0; it < 8; it++) {
        int i = tid + it * 256;               // 0..2047
        int r = i >> 4, c = i & 15, s = c >> 2, c16 = c & 3;
        uint32_t sa = sb + SQ + (uint32_t)(s * 10240 + r * 80 + c16 * 16);
        cp16(sa, qhp + (size_t)r * DMODEL + s * 32 + c16 * 8);
    }
    CP_COMMIT();

    auto loadK = [&](int c) {
        const uint32_t kb = sb + ((c & 1) ? SK1 : SK0);
        const int j0 = c * CHUNK;
        const int r = tid >> 2, c16 = tid & 3;
        #pragma unroll
        for (int s = 0; s < 4; s++) {
            uint32_t sa = kb + (uint32_t)(s * 5120 + r * 80 + c16 * 16);
            size_t go = (size_t)(j0 + r) * DMODEL + s * 32 + c16 * 8;
            cp16(sa, khp + go);
            cp16(sa + 20480, klp + go);
        }
    };
    auto loadV = [&](int c) {
        const uint32_t vb = sb + ((c & 1) ? SV1 : SV0);
        const int j0 = c * CHUNK;
        #pragma unroll
        for (int it = 0; it < 4; it++) {
            int i = tid + it * 256;           // 0..1023
            int s = i >> 9, r = (i >> 2) & 127, c16 = i & 3;
            uint32_t sa = vb + (uint32_t)(s * 10240 + r * 80 + c16 * 16);
            size_t go = (size_t)r * NHID + j0 + s * 32 + c16 * 8;
            cp16(sa, vhp + go);
            cp16(sa + 20480, vlp + go);
        }
    };

    loadK(0); loadV(0); CP_COMMIT();
    loadK(1); loadV(1); CP_COMMIT();

    const uint32_t qa = (uint32_t)((w * 16 + (lane & 15)) * 80 + (lane >> 4) * 16);
    const uint32_t ba = (uint32_t)(((((lane >> 4) << 3) + (lane & 7)) * 80)
                                   + ((lane >> 3) & 1) * 16);

    float Y[16][4];
    #pragma unroll
    for (int i = 0; i < 16; i++)
        #pragma unroll
        for (int j = 0; j < 4; j++) Y[i][j] = 0.0f;
    float l0 = 0.0f, l1 = 0.0f;

    for (int c = 0; c < NCHUNK; c++) {
        CP_WAIT(1);
        __syncthreads();

        // ---- QK: S[128 x 64], 2-term split ----
        const uint32_t kb = sb + ((c & 1) ? SK1 : SK0);
        float S[8][4];
        #pragma unroll
        for (int i = 0; i < 8; i++)
            #pragma unroll
            for (int j = 0; j < 4; j++) S[i][j] = 0.0f;

        #pragma unroll
        for (int kk = 0; kk < 8; kk++) {
            uint32_t qaddr = sb + SQ + (uint32_t)((kk >> 1) * 10240 + (kk & 1) * 32) + qa;
            uint32_t ah[4];
            ldsm4(ah[0], ah[1], ah[2], ah[3], qaddr);
            uint32_t bh[8][2], bl[8][2];
            #pragma unroll
            for (int p = 0; p < 4; p++) {
                uint32_t ka = kb + (uint32_t)((kk >> 1) * 5120 + p * 1280 + (kk & 1) * 32) + ba;
                ldsm4(bh[2*p][0], bh[2*p][1], bh[2*p+1][0], bh[2*p+1][1], ka);
                ldsm4(bl[2*p][0], bl[2*p][1], bl[2*p+1][0], bl[2*p+1][1], ka + 20480);
            }
            #pragma unroll
            for (int nt = 0; nt < 8; nt++) {
                mma_bf16(S[nt], ah, bh[nt]);
                mma_bf16(S[nt], ah, bl[nt]);
            }
        }

        // ---- exp (no max subtraction; logits bounded by attn_scale) ----
        #pragma unroll
        for (int nt = 0; nt < 8; nt++) {
            S[nt][0] = __expf(S[nt][0]);
            S[nt][1] = __expf(S[nt][1]);
            S[nt][2] = __expf(S[nt][2]);
            S[nt][3] = __expf(S[nt][3]);
            l0 += S[nt][0] + S[nt][1];
            l1 += S[nt][2] + S[nt][3];
        }

        // ---- pack P -> hi/lo bf16 A-fragments ----
        uint32_t pa[4][4], pl4[4][4];
        #pragma unroll
        for (int kk2 = 0; kk2 < 4; kk2++) {
            #pragma unroll
            for (int half = 0; half < 2; half++) {
                int nt = 2 * kk2 + half;
                uint32_t u01 = pkbf(S[nt][0], S[nt][1]);
                uint32_t u23 = pkbf(S[nt][2], S[nt][3]);
                float r0h = __uint_as_float(u01 << 16);
                float r1h = __uint_as_float(u01 & 0xFFFF0000u);
                float r2h = __uint_as_float(u23 << 16);
                float r3h = __uint_as_float(u23 & 0xFFFF0000u);
                pa[kk2][2*half]      = u01;
                pa[kk2][2*half + 1]  = u23;
                pl4[kk2][2*half]     = pkbf(S[nt][0] - r0h, S[nt][1] - r1h);
                pl4[kk2][2*half + 1] = pkbf(S[nt][2] - r2h, S[nt][3] - r3h);
            }
        }

        // ---- AV (3-term) ----
        const uint32_t vb = sb + ((c & 1) ? SV1 : SV0);
        #pragma unroll
        for (int kk2 = 0; kk2 < 4; kk2++) {
            #pragma unroll
            for (int p = 0; p < 8; p++) {
                uint32_t va = vb + (uint32_t)((kk2 >> 1) * 10240 + p * 1280
                                              + (kk2 & 1) * 32) + ba;
                uint32_t vh[4], vl[4];
                ldsm4(vh[0], vh[1], vh[2], vh[3], va);
                ldsm4(vl[0], vl[1], vl[2], vl[3], va + 20480);
                uint32_t b0h[2] = {vh[0], vh[1]}, b1h[2] = {vh[2], vh[3]};
                uint32_t b0l[2] = {vl[0], vl[1]}, b1l[2] = {vl[2], vl[3]};
                mma_bf16(Y[2*p],     pa[kk2],  b0h);
                mma_bf16(Y[2*p],     pl4[kk2], b0h);
                mma_bf16(Y[2*p],     pa[kk2],  b0l);
                mma_bf16(Y[2*p + 1], pa[kk2],  b1h);
                mma_bf16(Y[2*p + 1], pl4[kk2], b1h);
                mma_bf16(Y[2*p + 1], pa[kk2],  b1l);
            }
        }
        __syncthreads();

        if (c + 2 < NCHUNK) { loadK(c + 2); loadV(c + 2); }
        CP_COMMIT();
    }

    // ---- epilogue: reduce l across quad, y = Y / l, split hi/lo bf16 ----
    #pragma unroll
    for (int o = 1; o <= 2; o <<= 1) {
        l0 += __shfl_xor_sync(0xFFFFFFFFu, l0, o);
        l1 += __shfl_xor_sync(0xFFFFFFFFu, l1, o);
    }
    const float r0 = 1.0f / l0, r1 = 1.0f / l1;
    const int g = lane >> 2, colb = (lane & 3) * 2;
    #pragma unroll
    for (int nt = 0; nt < 16; nt++) {
        float v0 = Y[nt][0] * r0, v1 = Y[nt][1] * r0;
        float v2 = Y[nt][2] * r1, v3 = Y[nt][3] * r1;
        uint32_t h01 = pkbf(v0, v1), h23 = pkbf(v2, v3);
        uint32_t lo01 = pkbf(v0 - __uint_as_float(h01 << 16),
                             v1 - __uint_as_float(h01 & 0xFFFF0000u));
        uint32_t lo23 = pkbf(v2 - __uint_as_float(h23 << 16),
                             v3 - __uint_as_float(h23 & 0xFFFF0000u));
        size_t o0 = (size_t)(qrow0 + w * 16 + g) * DMODEL + h * HDIM + nt * 8 + colb;
        size_t o1 = o0 + (size_t)8 * DMODEL;
        *reinterpret_cast<uint32_t*>(yh + o0) = h01;
        *reinterpret_cast<uint32_t*>(yl + o0) = lo01;
        *reinterpret_cast<uint32_t*>(yh + o1) = h23;
        *reinterpret_cast<uint32_t*>(yl + o1) = lo23;
    }
}

// ---------------------------------------------------------------------------
// Split-bf16 HMMA GEMM; THREE=true: hh+hl+lh, THREE=false: hh+hl (A-lo unused)
// ---------------------------------------------------------------------------
#define STAGE_B 40960
#define TILE_B  10240

template <bool THREE>
__global__ __launch_bounds__(256, 1)
void gemm_mma(const __nv_bfloat16* __restrict__ Ah, const __nv_bfloat16* __restrict__ Al,
              const __nv_bfloat16* __restrict__ Bh, const __nv_bfloat16* __restrict__ Bl,
              float* __restrict__ C, int K,
              int lda, int ldb, int ldc,
              long long aZ, long long bZ, long long cZ)
{
    extern __shared__ char smem[];
    const uint32_t sbase = smem_u32(smem);
    const int tid = threadIdx.x;
    const int wid = tid >> 5, lane = tid & 31;
    const int wm = wid & 3, wn = wid >> 2;
    const int m0 = blockIdx.x * 128, n0 = blockIdx.y * 128;
    const long long z = blockIdx.z;
    Ah += z * aZ; Al += z * aZ; Bh += z * bZ; Bl += z * bZ; C += z * cZ;

    const int nc = K / 32;
    const int lr0 = tid >> 2, lc0 = tid & 3;
    const int lr1 = lr0 + 64;

    auto load_stage = [&](int c) {
        const int k0 = c * 32;
        const uint32_t sb = sbase + (uint32_t)(c % 3) * STAGE_B;
        {
            uint32_t sa = sb + (uint32_t)(lr0 * 80 + lc0 * 16);
            long long ga = (long long)(m0 + lr0) * lda + k0 + lc0 * 8;
            cp16(sa, Ah + ga);
            if (THREE) cp16(sa + TILE_B, Al + ga);
            long long gb = (long long)(n0 + lr0) * ldb + k0 + lc0 * 8;
            cp16(sa + 2 * TILE_B, Bh + gb);
            cp16(sa + 3 * TILE_B, Bl + gb);
        }
        {
            uint32_t sa = sb + (uint32_t)(lr1 * 80 + lc0 * 16);
            long long ga = (long long)(m0 + lr1) * lda + k0 + lc0 * 8;
            cp16(sa, Ah + ga);
            if (THREE) cp16(sa + TILE_B, Al + ga);
            long long gb = (long long)(n0 + lr1) * ldb + k0 + lc0 * 8;
            cp16(sa + 2 * TILE_B, Bh + gb);
            cp16(sa + 3 * TILE_B, Bl + gb);
        }
    };

    const uint32_t arow = (uint32_t)((wm * 32 + (lane & 15)) * 80 + (lane >> 4) * 16);
    const uint32_t brow = (uint32_t)((wn * 64 + ((lane >> 4) << 3) + (lane & 7)) * 80
                                     + ((lane >> 3) & 1) * 16);

    float acc[2][8][4];
    #pragma unroll
    for (int i = 0; i < 2; i++)
        #pragma unroll
        for (int j = 0; j < 8; j++)
            #pragma unroll
            for (int q = 0; q < 4; q++) acc[i][j][q] = 0.0f;

    load_stage(0); CP_COMMIT();
    if (nc > 1) load_stage(1);
    CP_COMMIT();

    for (int c = 0; c < nc; c++) {
        CP_WAIT(1);
        __syncthreads();
        if (c + 2 < nc) load_stage(c + 2);
        CP_COMMIT();

        const uint32_t sb = sbase + (uint32_t)(c % 3) * STAGE_B;
        #pragma unroll
        for (int kk = 0; kk < 2; kk++) {
            const uint32_t kbyte = (uint32_t)(kk * 32);
            uint32_t ah[2][4], al[2][4];
            #pragma unroll
            for (int mt = 0; mt < 2; mt++) {
                uint32_t ad = sb + arow + (uint32_t)(mt * 16 * 80) + kbyte;
                ldsm4(ah[mt][0], ah[mt][1], ah[mt][2], ah[mt][3], ad);
                if (THREE) ldsm4(al[mt][0], al[mt][1], al[mt][2], al[mt][3], ad + TILE_B);
            }
            uint32_t bh[8][2], bl[8][2];
            #pragma unroll
            for (int p = 0; p < 4; p++) {
                uint32_t bd = sb + 2 * TILE_B + brow + (uint32_t)(p * 16 * 80) + kbyte;
                ldsm4(bh[2*p][0], bh[2*p][1], bh[2*p+1][0], bh[2*p+1][1], bd);
                ldsm4(bl[2*p][0], bl[2*p][1], bl[2*p+1][0], bl[2*p+1][1], bd + TILE_B);
            }
            #pragma unroll
            for (int mt = 0; mt < 2; mt++)
                #pragma unroll
                for (int nt = 0; nt < 8; nt++) {
                    mma_bf16(acc[mt][nt], ah[mt], bh[nt]);
                    mma_bf16(acc[mt][nt], ah[mt], bl[nt]);
                    if (THREE) mma_bf16(acc[mt][nt], al[mt], bh[nt]);
                }
        }
        __syncthreads();
    }

    const int mb = m0 + wm * 32 + (lane >> 2);
    const int nb = n0 + wn * 64 + (lane & 3) * 2;
    #pragma unroll
    for (int mt = 0; mt < 2; mt++)
        #pragma unroll
        for (int nt = 0; nt < 8; nt++) {
            int m = mb + mt * 16;
            int n = nb + nt * 8;
            float2 v0 = {acc[mt][nt][0], acc[mt][nt][1]};
            float2 v1 = {acc[mt][nt][2], acc[mt][nt][3]};
            *reinterpret_cast<float2*>(C + (long long)m * ldc + n) = v0;
            *reinterpret_cast<float2*>(C + (long long)(m + 8) * ldc + n) = v1;
        }
}

// ---------------------------------------------------------------------------
// Elementwise fp32 -> (hi, lo) bf16 split (lo optional)
// ---------------------------------------------------------------------------
__global__ void split_kernel(const float* __restrict__ in,
                             __nv_bfloat16* __restrict__ hi,
                             __nv_bfloat16* __restrict__ lo, size_t n4, int writeLo) {
    size_t i = (size_t)blockIdx.x * blockDim.x + threadIdx.x;
    if (i >= n4) return;
    float4 v = reinterpret_cast<const float4*>(in)[i];
    __nv_bfloat16 h0 = __float2bfloat16_rn(v.x), h1 = __float2bfloat16_rn(v.y);
    __nv_bfloat16 h2 = __float2bfloat16_rn(v.z), h3 = __float2bfloat16_rn(v.w);
    __nv_bfloat162 H0 = {h0, h1}, H1 = {h2, h3};
    reinterpret_cast<__nv_bfloat162*>(hi)[i * 2]     = H0;
    reinterpret_cast<__nv_bfloat162*>(hi)[i * 2 + 1] = H1;
    if (writeLo) {
        __nv_bfloat162 L0 = {__float2bfloat16_rn(v.x - __bfloat162float(h0)),
                             __float2bfloat16_rn(v.y - __bfloat162float(h1))};
        __nv_bfloat162 L1 = {__float2bfloat16_rn(v.z - __bfloat162float(h2)),
                             __float2bfloat16_rn(v.w - __bfloat162float(h3))};
        reinterpret_cast<__nv_bfloat162*>(lo)[i * 2]     = L0;
        reinterpret_cast<__nv_bfloat162*>(lo)[i * 2 + 1] = L1;
    }
}

// ---------------------------------------------------------------------------
// Transpose + split: out[c][r] = in[r][c], fp32 -> hi/lo bf16
// ---------------------------------------------------------------------------
__global__ void transpose_split(const float* __restrict__ in, int ldi, long long inZ,
                                __nv_bfloat16* __restrict__ oh,
                                __nv_bfloat16* __restrict__ ol, int ldo, long long outZ) {
    __shared__ float t[32][33];
    in += blockIdx.z * inZ;
    const long long ob = blockIdx.z * outZ;
    const int r0 = blockIdx.y * 32, c0 = blockIdx.x * 32;
    #pragma unroll
    for (int i = threadIdx.y; i < 32; i += 8)
        t[i][threadIdx.x] = in[(long long)(r0 + i) * ldi + c0 + threadIdx.x];
    __syncthreads();
    #pragma unroll
    for (int i = threadIdx.y; i < 32; i += 8) {
        float v = t[threadIdx.x][i];
        __nv_bfloat16 h = __float2bfloat16_rn(v);
        long long o = ob + (long long)(c0 + i) * ldo + r0 + threadIdx.x;
        oh[o] = h;
        ol[o] = __float2bfloat16_rn(v - __bfloat162float(h));
    }
}

// ---------------------------------------------------------------------------
// Row (128) L2-normalize, optional per-head scale, emit hi (+ optional lo) bf16
// ---------------------------------------------------------------------------
__global__ void normalize_split(const float* __restrict__ src,
                                __nv_bfloat16* __restrict__ hi,
                                __nv_bfloat16* __restrict__ lo,
                                const float* __restrict__ attn_scale,
                                int nrows, int useScale, int writeLo) {
    int row  = blockIdx.x * (blockDim.x >> 5) + (threadIdx.x >> 5);
    int lane = threadIdx.x & 31;
    if (row >= nrows) return;
    float4 v = reinterpret_cast<const float4*>(src + (size_t)row * HDIM)[lane];
    float ss = v.x * v.x + v.y * v.y + v.z * v.z + v.w * v.w;
    #pragma unroll
    for (int o = 16; o; o >>= 1) ss += __shfl_xor_sync(0xFFFFFFFFu, ss, o);
    float sc = rsqrtf(ss + EPSN);
    if (useScale) sc *= attn_scale[row & (NHEADS - 1)];
    float f[4] = {v.x * sc, v.y * sc, v.z * sc, v.w * sc};
    size_t off = (size_t)row * HDIM + lane * 4;
    __nv_bfloat16 h[4];
    #pragma unroll
    for (int i = 0; i < 4; i++) h[i] = __float2bfloat16_rn(f[i]);
    __nv_bfloat162 H0 = {h[0], h[1]}, H1 = {h[2], h[3]};
    *reinterpret_cast<__nv_bfloat162*>(hi + off)     = H0;
    *reinterpret_cast<__nv_bfloat162*>(hi + off + 2) = H1;
    if (writeLo) {
        __nv_bfloat162 L0 = {__float2bfloat16_rn(f[0] - __bfloat162float(h[0])),
                             __float2bfloat16_rn(f[1] - __bfloat162float(h[1]))};
        __nv_bfloat162 L1 = {__float2bfloat16_rn(f[2] - __bfloat162float(h[2])),
                             __float2bfloat16_rn(f[3] - __bfloat162float(h[3]))};
        *reinterpret_cast<__nv_bfloat162*>(lo + off)     = L0;
        *reinterpret_cast<__nv_bfloat162*>(lo + off + 2) = L1;
    }
}

// ---------------------------------------------------------------------------
// Launch
// ---------------------------------------------------------------------------
extern "C" void kernel_launch(void* const* d_in, const int* in_sizes, int n_in,
                              void* d_out, int out_size) {
    const float* x     = (const float*)d_in[0];
    const float* Wq    = (const float*)d_in[1];
    const float* keys  = (const float*)d_in[2];
    const float* vals  = (const float*)d_in[3];
    const float* ascal = (const float*)d_in[4];
    const float* Wo    = (const float*)d_in[5];
    float* out = (float*)d_out;

    __nv_bfloat16 *xh, *xl, *wqh, *wql, *woh, *wol, *qh, *ql, *kh, *kl;
    __nv_bfloat16 *vth, *vtl, *yh, *yl;
    float *qf;
    cudaGetSymbolAddress((void**)&xh, g_xh);   cudaGetSymbolAddress((void**)&xl, g_xl);
    cudaGetSymbolAddress((void**)&wqh, g_wqt_h); cudaGetSymbolAddress((void**)&wql, g_wqt_l);
    cudaGetSymbolAddress((void**)&woh, g_wot_h); cudaGetSymbolAddress((void**)&wol, g_wot_l);
    cudaGetSymbolAddress((void**)&qf, g_qf);
    cudaGetSymbolAddress((void**)&qh, g_qh);   cudaGetSymbolAddress((void**)&ql, g_ql);
    cudaGetSymbolAddress((void**)&kh, g_kh);   cudaGetSymbolAddress((void**)&kl, g_kl);
    cudaGetSymbolAddress((void**)&vth, g_vth); cudaGetSymbolAddress((void**)&vtl, g_vtl);
    cudaGetSymbolAddress((void**)&yh, g_yh);   cudaGetSymbolAddress((void**)&yl, g_yl);

    const int SMEM = 3 * STAGE_B;   // 122880 B
    cudaFuncSetAttribute(gemm_mma<true>,  cudaFuncAttributeMaxDynamicSharedMemorySize, SMEM);
    cudaFuncSetAttribute(gemm_mma<false>, cudaFuncAttributeMaxDynamicSharedMemorySize, SMEM);
    cudaFuncSetAttribute(attn_fused, cudaFuncAttributeMaxDynamicSharedMemorySize, SMEM_ATTN);

    // ---- prep ----
    split_kernel<<<(S_LEN * DMODEL / 4 + 255) / 256, 256>>>(x, xh, xl,
                                                            (size_t)S_LEN * DMODEL / 4, 0);
    transpose_split<<<dim3(32, 32, 1), dim3(32, 8)>>>(Wq, DMODEL, 0, wqh, wql, DMODEL, 0);
    transpose_split<<<dim3(32, 32, 1), dim3(32, 8)>>>(Wo, DMODEL, 0, woh, wol, DMODEL, 0);
    transpose_split<<<dim3(HDIM / 32, NHID / 32, NHEADS), dim3(32, 8)>>>(
        vals, DMODEL, (long long)HDIM, vth, vtl, NHID, (long long)HDIM * NHID);
    normalize_split<<<(NHID * NHEADS) / 8, 256>>>(keys, kh, kl, ascal,
                                                  NHID * NHEADS, 1, 1);

    // ---- Q-proj (2-term: A-lo dropped) ----
    gemm_mma<false><<<dim3(S_LEN / 128, DMODEL / 128, 1), 256, SMEM>>>(
        xh, xl, wqh, wql, qf, DMODEL, DMODEL, DMODEL, DMODEL, 0, 0, 0);

    // ---- normalize q -> hi only ----
    normalize_split<<<(S_LEN * NHEADS) / 8, 256>>>(qf, qh, ql, ascal,
                                                   S_LEN * NHEADS, 0, 0);

    // ---- fused attention ----
    attn_fused<<<dim3(S_LEN / 128, NHEADS), 256, SMEM_ATTN>>>(
        qh, kh, kl, vth, vtl, yh, yl);

    // ---- O-proj (3-term) ----
    gemm_mma<true><<<dim3(S_LEN / 128, DMODEL / 128, 1), 256, SMEM>>>(
        yh, yl, woh, wol, out, DMODEL, DMODEL, DMODEL, DMODEL, 0, 0, 0);
}

// round 6
// speedup vs baseline: 4.6642x; 1.3696x over previous
#include <cuda_runtime.h>
#include <cuda_fp16.h>
#include <stdint.h>

#define S_LEN   4096
#define DMODEL  1024
#define NHEADS  8
#define HDIM    128
#define NHID    2048
#define EPSN    1e-6f
#define CHUNK   64
#define NCHUNK  (NHID / CHUNK)

// ---------------------------------------------------------------------------
// Scratch (device globals — no allocations allowed)
// ---------------------------------------------------------------------------
__device__ __align__(16) __half g_xh[(size_t)S_LEN * DMODEL];
__device__ __align__(16) __half g_wqt_h[(size_t)DMODEL * DMODEL];
__device__ __align__(16) __half g_wot_h[(size_t)DMODEL * DMODEL];
__device__ __align__(16) __half g_wot_l[(size_t)DMODEL * DMODEL];
__device__ __align__(16) float  g_qf[(size_t)S_LEN * DMODEL];
__device__ __align__(16) __half g_qh[(size_t)S_LEN * DMODEL];
__device__ __align__(16) __half g_kh[(size_t)NHID * NHEADS * HDIM];
__device__ __align__(16) __half g_vth[(size_t)NHEADS * HDIM * NHID];
__device__ __align__(16) __half g_yh[(size_t)S_LEN * DMODEL];
__device__ __align__(16) __half g_yl[(size_t)S_LEN * DMODEL];

// ---------------------------------------------------------------------------
// PTX helpers (baseline sm_80+ only)
// ---------------------------------------------------------------------------
__device__ __forceinline__ uint32_t smem_u32(const void* p) {
    uint32_t a;
    asm("{ .reg .u64 t; cvta.to.shared.u64 t, %1; cvt.u32.u64 %0, t; }"
        : "=r"(a) : "l"(p));
    return a;
}
__device__ __forceinline__ void cp16(uint32_t s, const void* g) {
    asm volatile("cp.async.cg.shared.global [%0], [%1], 16;" :: "r"(s), "l"(g));
}
#define CP_COMMIT() asm volatile("cp.async.commit_group;" ::: "memory")
#define CP_WAIT(n)  asm volatile("cp.async.wait_group %0;" :: "n"(n) : "memory")

__device__ __forceinline__ void ldsm4(uint32_t& r0, uint32_t& r1,
                                      uint32_t& r2, uint32_t& r3, uint32_t a) {
    asm volatile("ldmatrix.sync.aligned.m8n8.x4.shared.b16 {%0,%1,%2,%3}, [%4];"
                 : "=r"(r0), "=r"(r1), "=r"(r2), "=r"(r3) : "r"(a));
}
__device__ __forceinline__ void mma_f16(float* d, const uint32_t* a, const uint32_t* b) {
    asm volatile(
        "mma.sync.aligned.m16n8k16.row.col.f32.f16.f16.f32 "
        "{%0,%1,%2,%3}, {%4,%5,%6,%7}, {%8,%9}, {%0,%1,%2,%3};"
        : "+f"(d[0]), "+f"(d[1]), "+f"(d[2]), "+f"(d[3])
        : "r"(a[0]), "r"(a[1]), "r"(a[2]), "r"(a[3]), "r"(b[0]), "r"(b[1]));
}
// pack two fp32 -> f16x2 register (lo = x, hi = y)
__device__ __forceinline__ uint32_t pkh(float x, float y) {
    __half2 h = __floats2half2_rn(x, y);
    return *reinterpret_cast<uint32_t*>(&h);
}
__device__ __forceinline__ float lo_f(uint32_t u) {
    __half2 h = *reinterpret_cast<__half2*>(&u);
    return __low2float(h);
}
__device__ __forceinline__ float hi_f(uint32_t u) {
    __half2 h = *reinterpret_cast<__half2*>(&u);
    return __high2float(h);
}

// ---------------------------------------------------------------------------
// Fused attention (fp16): Y = softmax(Q·K^T) V per (128 q-rows, head).
// QK: 1-term fp16 (qh·kh). AV: 2-term (ph·vh + pl·vh). Unnormalized exp
// (|logits| <= attn_scale), divide by l at epilogue.
// smem (half, rows padded to 80B per 32 elems):
//   Q:  0..40960      : 4 slabs (s*10240), slab = 128 rows x 80B
//   K0: 40960, K1: 61440 : 4 slabs (s*5120, 64 rows x 80B)
//   V0: 81920, V1: 102400: 2 slabs (s*10240, 128 rows x 80B)
// ---------------------------------------------------------------------------
#define SQ   0u
#define SK0  40960u
#define SK1  61440u
#define SV0  81920u
#define SV1  102400u
#define SMEM_ATTN 122880

__global__ __launch_bounds__(256, 1)
void attn_fused(const __half* __restrict__ qh,
                const __half* __restrict__ kh,
                const __half* __restrict__ vth,
                __half* __restrict__ yh, __half* __restrict__ yl)
{
    extern __shared__ char smem[];
    const uint32_t sb = smem_u32(smem);
    const int tid = threadIdx.x;
    const int w = tid >> 5, lane = tid & 31;
    const int h = blockIdx.y;
    const int qrow0 = blockIdx.x * 128;

    const __half* qhp = qh + (size_t)qrow0 * DMODEL + h * HDIM;
    const __half* khp = kh + h * HDIM;
    const __half* vhp = vth + (size_t)h * HDIM * NHID;

    // ---- stage Q ----
    #pragma unroll
    for (int it = 0; it < 8; it++) {
        int i = tid + it * 256;               // 0..2047
        int r = i >> 4, c = i & 15, s = c >> 2, c16 = c & 3;
        uint32_t sa = sb + SQ + (uint32_t)(s * 10240 + r * 80 + c16 * 16);
        cp16(sa, qhp + (size_t)r * DMODEL + s * 32 + c16 * 8);
    }
    CP_COMMIT();

    auto loadK = [&](int c) {
        const uint32_t kb = sb + ((c & 1) ? SK1 : SK0);
        const int j0 = c * CHUNK;
        const int r = tid >> 2, c16 = tid & 3;
        #pragma unroll
        for (int s = 0; s < 4; s++) {
            uint32_t sa = kb + (uint32_t)(s * 5120 + r * 80 + c16 * 16);
            cp16(sa, khp + (size_t)(j0 + r) * DMODEL + s * 32 + c16 * 8);
        }
    };
    auto loadV = [&](int c) {
        const uint32_t vb = sb + ((c & 1) ? SV1 : SV0);
        const int j0 = c * CHUNK;
        #pragma unroll
        for (int it = 0; it < 4; it++) {
            int i = tid + it * 256;           // 0..1023
            int s = i >> 9, r = (i >> 2) & 127, c16 = i & 3;
            uint32_t sa = vb + (uint32_t)(s * 10240 + r * 80 + c16 * 16);
            cp16(sa, vhp + (size_t)r * NHID + j0 + s * 32 + c16 * 8);
        }
    };

    loadK(0); loadV(0); CP_COMMIT();
    loadK(1); loadV(1); CP_COMMIT();

    const uint32_t qa = (uint32_t)((w * 16 + (lane & 15)) * 80 + (lane >> 4) * 16);
    const uint32_t ba = (uint32_t)(((((lane >> 4) << 3) + (lane & 7)) * 80)
                                   + ((lane >> 3) & 1) * 16);

    float Y[16][4];
    #pragma unroll
    for (int i = 0; i < 16; i++)
        #pragma unroll
        for (int j = 0; j < 4; j++) Y[i][j] = 0.0f;
    float l0 = 0.0f, l1 = 0.0f;

    for (int c = 0; c < NCHUNK; c++) {
        CP_WAIT(1);
        __syncthreads();

        // ---- QK: S[128 x 64], 1-term fp16 ----
        const uint32_t kb = sb + ((c & 1) ? SK1 : SK0);
        float S[8][4];
        #pragma unroll
        for (int i = 0; i < 8; i++)
            #pragma unroll
            for (int j = 0; j < 4; j++) S[i][j] = 0.0f;

        #pragma unroll
        for (int kk = 0; kk < 8; kk++) {
            uint32_t qaddr = sb + SQ + (uint32_t)((kk >> 1) * 10240 + (kk & 1) * 32) + qa;
            uint32_t ah[4];
            ldsm4(ah[0], ah[1], ah[2], ah[3], qaddr);
            uint32_t bh[8][2];
            #pragma unroll
            for (int p = 0; p < 4; p++) {
                uint32_t ka = kb + (uint32_t)((kk >> 1) * 5120 + p * 1280 + (kk & 1) * 32) + ba;
                ldsm4(bh[2*p][0], bh[2*p][1], bh[2*p+1][0], bh[2*p+1][1], ka);
            }
            #pragma unroll
            for (int nt = 0; nt < 8; nt++)
                mma_f16(S[nt], ah, bh[nt]);
        }

        // ---- exp (no max subtraction; logits bounded) ----
        #pragma unroll
        for (int nt = 0; nt < 8; nt++) {
            S[nt][0] = __expf(S[nt][0]);
            S[nt][1] = __expf(S[nt][1]);
            S[nt][2] = __expf(S[nt][2]);
            S[nt][3] = __expf(S[nt][3]);
            l0 += S[nt][0] + S[nt][1];
            l1 += S[nt][2] + S[nt][3];
        }

        // ---- pack P -> hi/lo fp16 A-fragments ----
        uint32_t pa[4][4], pl4[4][4];
        #pragma unroll
        for (int kk2 = 0; kk2 < 4; kk2++) {
            #pragma unroll
            for (int half = 0; half < 2; half++) {
                int nt = 2 * kk2 + half;
                uint32_t u01 = pkh(S[nt][0], S[nt][1]);
                uint32_t u23 = pkh(S[nt][2], S[nt][3]);
                pa[kk2][2*half]      = u01;
                pa[kk2][2*half + 1]  = u23;
                pl4[kk2][2*half]     = pkh(S[nt][0] - lo_f(u01), S[nt][1] - hi_f(u01));
                pl4[kk2][2*half + 1] = pkh(S[nt][2] - lo_f(u23), S[nt][3] - hi_f(u23));
            }
        }

        // ---- AV: 2-term (p-hi + p-lo, V hi only) ----
        const uint32_t vb = sb + ((c & 1) ? SV1 : SV0);
        #pragma unroll
        for (int kk2 = 0; kk2 < 4; kk2++) {
            #pragma unroll
            for (int p = 0; p < 8; p++) {
                uint32_t va = vb + (uint32_t)((kk2 >> 1) * 10240 + p * 1280
                                              + (kk2 & 1) * 32) + ba;
                uint32_t vh[4];
                ldsm4(vh[0], vh[1], vh[2], vh[3], va);
                uint32_t b0[2] = {vh[0], vh[1]}, b1[2] = {vh[2], vh[3]};
                mma_f16(Y[2*p],     pa[kk2],  b0);
                mma_f16(Y[2*p],     pl4[kk2], b0);
                mma_f16(Y[2*p + 1], pa[kk2],  b1);
                mma_f16(Y[2*p + 1], pl4[kk2], b1);
            }
        }
        __syncthreads();

        if (c + 2 < NCHUNK) { loadK(c + 2); loadV(c + 2); }
        CP_COMMIT();
    }

    // ---- epilogue: reduce l across quad, y = Y / l, split hi/lo fp16 ----
    #pragma unroll
    for (int o = 1; o <= 2; o <<= 1) {
        l0 += __shfl_xor_sync(0xFFFFFFFFu, l0, o);
        l1 += __shfl_xor_sync(0xFFFFFFFFu, l1, o);
    }
    const float r0 = 1.0f / l0, r1 = 1.0f / l1;
    const int g = lane >> 2, colb = (lane & 3) * 2;
    #pragma unroll
    for (int nt = 0; nt < 16; nt++) {
        float v0 = Y[nt][0] * r0, v1 = Y[nt][1] * r0;
        float v2 = Y[nt][2] * r1, v3 = Y[nt][3] * r1;
        uint32_t h01 = pkh(v0, v1), h23 = pkh(v2, v3);
        uint32_t lo01 = pkh(v0 - lo_f(h01), v1 - hi_f(h01));
        uint32_t lo23 = pkh(v2 - lo_f(h23), v3 - hi_f(h23));
        size_t o0 = (size_t)(qrow0 + w * 16 + g) * DMODEL + h * HDIM + nt * 8 + colb;
        size_t o1 = o0 + (size_t)8 * DMODEL;
        *reinterpret_cast<uint32_t*>(yh + o0) = h01;
        *reinterpret_cast<uint32_t*>(yl + o0) = lo01;
        *reinterpret_cast<uint32_t*>(yh + o1) = h23;
        *reinterpret_cast<uint32_t*>(yl + o1) = lo23;
    }
}

// ---------------------------------------------------------------------------
// Split-fp16 HMMA GEMM. TERMS=1: ah·bh. TERMS=3: ah·bh + ah·bl + al·bh.
// ---------------------------------------------------------------------------
#define STAGE_B 40960
#define TILE_B  10240

template <int TERMS>
__global__ __launch_bounds__(256, 1)
void gemm_mma(const __half* __restrict__ Ah, const __half* __restrict__ Al,
              const __half* __restrict__ Bh, const __half* __restrict__ Bl,
              float* __restrict__ C, int K,
              int lda, int ldb, int ldc)
{
    extern __shared__ char smem[];
    const uint32_t sbase = smem_u32(smem);
    const int tid = threadIdx.x;
    const int wid = tid >> 5, lane = tid & 31;
    const int wm = wid & 3, wn = wid >> 2;
    const int m0 = blockIdx.x * 128, n0 = blockIdx.y * 128;

    const int nc = K / 32;
    const int lr0 = tid >> 2, lc0 = tid & 3;
    const int lr1 = lr0 + 64;

    auto load_stage = [&](int c) {
        const int k0 = c * 32;
        const uint32_t sb = sbase + (uint32_t)(c % 3) * STAGE_B;
        {
            uint32_t sa = sb + (uint32_t)(lr0 * 80 + lc0 * 16);
            long long ga = (long long)(m0 + lr0) * lda + k0 + lc0 * 8;
            cp16(sa, Ah + ga);
            if (TERMS == 3) cp16(sa + TILE_B, Al + ga);
            long long gb = (long long)(n0 + lr0) * ldb + k0 + lc0 * 8;
            cp16(sa + 2 * TILE_B, Bh + gb);
            if (TERMS == 3) cp16(sa + 3 * TILE_B, Bl + gb);
        }
        {
            uint32_t sa = sb + (uint32_t)(lr1 * 80 + lc0 * 16);
            long long ga = (long long)(m0 + lr1) * lda + k0 + lc0 * 8;
            cp16(sa, Ah + ga);
            if (TERMS == 3) cp16(sa + TILE_B, Al + ga);
            long long gb = (long long)(n0 + lr1) * ldb + k0 + lc0 * 8;
            cp16(sa + 2 * TILE_B, Bh + gb);
            if (TERMS == 3) cp16(sa + 3 * TILE_B, Bl + gb);
        }
    };

    const uint32_t arow = (uint32_t)((wm * 32 + (lane & 15)) * 80 + (lane >> 4) * 16);
    const uint32_t brow = (uint32_t)((wn * 64 + ((lane >> 4) << 3) + (lane & 7)) * 80
                                     + ((lane >> 3) & 1) * 16);

    float acc[2][8][4];
    #pragma unroll
    for (int i = 0; i < 2; i++)
        #pragma unroll
        for (int j = 0; j < 8; j++)
            #pragma unroll
            for (int q = 0; q < 4; q++) acc[i][j][q] = 0.0f;

    load_stage(0); CP_COMMIT();
    if (nc > 1) load_stage(1);
    CP_COMMIT();

    for (int c = 0; c < nc; c++) {
        CP_WAIT(1);
        __syncthreads();
        if (c + 2 < nc) load_stage(c + 2);
        CP_COMMIT();

        const uint32_t sb = sbase + (uint32_t)(c % 3) * STAGE_B;
        #pragma unroll
        for (int kk = 0; kk < 2; kk++) {
            const uint32_t kbyte = (uint32_t)(kk * 32);
            uint32_t ah[2][4], al[2][4];
            #pragma unroll
            for (int mt = 0; mt < 2; mt++) {
                uint32_t ad = sb + arow + (uint32_t)(mt * 16 * 80) + kbyte;
                ldsm4(ah[mt][0], ah[mt][1], ah[mt][2], ah[mt][3], ad);
                if (TERMS == 3) ldsm4(al[mt][0], al[mt][1], al[mt][2], al[mt][3], ad + TILE_B);
            }
            uint32_t bh[8][2], bl[8][2];
            #pragma unroll
            for (int p = 0; p < 4; p++) {
                uint32_t bd = sb + 2 * TILE_B + brow + (uint32_t)(p * 16 * 80) + kbyte;
                ldsm4(bh[2*p][0], bh[2*p][1], bh[2*p+1][0], bh[2*p+1][1], bd);
                if (TERMS == 3)
                    ldsm4(bl[2*p][0], bl[2*p][1], bl[2*p+1][0], bl[2*p+1][1], bd + TILE_B);
            }
            #pragma unroll
            for (int mt = 0; mt < 2; mt++)
                #pragma unroll
                for (int nt = 0; nt < 8; nt++) {
                    mma_f16(acc[mt][nt], ah[mt], bh[nt]);
                    if (TERMS == 3) {
                        mma_f16(acc[mt][nt], ah[mt], bl[nt]);
                        mma_f16(acc[mt][nt], al[mt], bh[nt]);
                    }
                }
        }
        __syncthreads();
    }

    const int mb = m0 + wm * 32 + (lane >> 2);
    const int nb = n0 + wn * 64 + (lane & 3) * 2;
    #pragma unroll
    for (int mt = 0; mt < 2; mt++)
        #pragma unroll
        for (int nt = 0; nt < 8; nt++) {
            int m = mb + mt * 16;
            int n = nb + nt * 8;
            float2 v0 = {acc[mt][nt][0], acc[mt][nt][1]};
            float2 v1 = {acc[mt][nt][2], acc[mt][nt][3]};
            *reinterpret_cast<float2*>(C + (long long)m * ldc + n) = v0;
            *reinterpret_cast<float2*>(C + (long long)(m + 8) * ldc + n) = v1;
        }
}

// ---------------------------------------------------------------------------
// Elementwise fp32 -> fp16 (hi only)
// ---------------------------------------------------------------------------
__global__ void split_kernel(const float* __restrict__ in,
                             __half* __restrict__ hi, size_t n4) {
    size_t i = (size_t)blockIdx.x * blockDim.x + threadIdx.x;
    if (i >= n4) return;
    float4 v = reinterpret_cast<const float4*>(in)[i];
    reinterpret_cast<uint32_t*>(hi)[i * 2]     = pkh(v.x, v.y);
    reinterpret_cast<uint32_t*>(hi)[i * 2 + 1] = pkh(v.z, v.w);
}

// ---------------------------------------------------------------------------
// Transpose + split: out[c][r] = in[r][c], fp32 -> fp16 hi (+ optional lo)
// ---------------------------------------------------------------------------
__global__ void transpose_split(const float* __restrict__ in, int ldi, long long inZ,
                                __half* __restrict__ oh,
                                __half* __restrict__ ol, int ldo, long long outZ,
                                int writeLo) {
    __shared__ float t[32][33];
    in += blockIdx.z * inZ;
    const long long ob = blockIdx.z * outZ;
    const int r0 = blockIdx.y * 32, c0 = blockIdx.x * 32;
    #pragma unroll
    for (int i = threadIdx.y; i < 32; i += 8)
        t[i][threadIdx.x] = in[(long long)(r0 + i) * ldi + c0 + threadIdx.x];
    __syncthreads();
    #pragma unroll
    for (int i = threadIdx.y; i < 32; i += 8) {
        float v = t[threadIdx.x][i];
        __half h = __float2half_rn(v);
        long long o = ob + (long long)(c0 + i) * ldo + r0 + threadIdx.x;
        oh[o] = h;
        if (writeLo) ol[o] = __float2half_rn(v - __half2float(h));
    }
}

// ---------------------------------------------------------------------------
// Row (128) L2-normalize, optional per-head scale, emit fp16 hi
// ---------------------------------------------------------------------------
__global__ void normalize_split(const float* __restrict__ src,
                                __half* __restrict__ hi,
                                const float* __restrict__ attn_scale,
                                int nrows, int useScale) {
    int row  = blockIdx.x * (blockDim.x >> 5) + (threadIdx.x >> 5);
    int lane = threadIdx.x & 31;
    if (row >= nrows) return;
    float4 v = reinterpret_cast<const float4*>(src + (size_t)row * HDIM)[lane];
    float ss = v.x * v.x + v.y * v.y + v.z * v.z + v.w * v.w;
    #pragma unroll
    for (int o = 16; o; o >>= 1) ss += __shfl_xor_sync(0xFFFFFFFFu, ss, o);
    float sc = rsqrtf(ss + EPSN);
    if (useScale) sc *= attn_scale[row & (NHEADS - 1)];
    size_t off = (size_t)row * HDIM + lane * 4;
    *reinterpret_cast<uint32_t*>(hi + off)     = pkh(v.x * sc, v.y * sc);
    *reinterpret_cast<uint32_t*>(hi + off + 2) = pkh(v.z * sc, v.w * sc);
}

// ---------------------------------------------------------------------------
// Launch
// ---------------------------------------------------------------------------
extern "C" void kernel_launch(void* const* d_in, const int* in_sizes, int n_in,
                              void* d_out, int out_size) {
    const float* x     = (const float*)d_in[0];
    const float* Wq    = (const float*)d_in[1];
    const float* keys  = (const float*)d_in[2];
    const float* vals  = (const float*)d_in[3];
    const float* ascal = (const float*)d_in[4];
    const float* Wo    = (const float*)d_in[5];
    float* out = (float*)d_out;

    __half *xh, *wqh, *woh, *wol, *qh, *kh, *vth, *yh, *yl;
    float *qf;
    cudaGetSymbolAddress((void**)&xh, g_xh);
    cudaGetSymbolAddress((void**)&wqh, g_wqt_h);
    cudaGetSymbolAddress((void**)&woh, g_wot_h); cudaGetSymbolAddress((void**)&wol, g_wot_l);
    cudaGetSymbolAddress((void**)&qf, g_qf);
    cudaGetSymbolAddress((void**)&qh, g_qh);
    cudaGetSymbolAddress((void**)&kh, g_kh);
    cudaGetSymbolAddress((void**)&vth, g_vth);
    cudaGetSymbolAddress((void**)&yh, g_yh);   cudaGetSymbolAddress((void**)&yl, g_yl);

    const int SMEM = 3 * STAGE_B;   // 122880 B
    cudaFuncSetAttribute(gemm_mma<1>, cudaFuncAttributeMaxDynamicSharedMemorySize, SMEM);
    cudaFuncSetAttribute(gemm_mma<3>, cudaFuncAttributeMaxDynamicSharedMemorySize, SMEM);
    cudaFuncSetAttribute(attn_fused, cudaFuncAttributeMaxDynamicSharedMemorySize, SMEM_ATTN);

    // ---- prep ----
    split_kernel<<<(S_LEN * DMODEL / 4 + 255) / 256, 256>>>(x, xh,
                                                            (size_t)S_LEN * DMODEL / 4);
    transpose_split<<<dim3(32, 32, 1), dim3(32, 8)>>>(Wq, DMODEL, 0, wqh, wqh, DMODEL, 0, 0);
    transpose_split<<<dim3(32, 32, 1), dim3(32, 8)>>>(Wo, DMODEL, 0, woh, wol, DMODEL, 0, 1);
    transpose_split<<<dim3(HDIM / 32, NHID / 32, NHEADS), dim3(32, 8)>>>(
        vals, DMODEL, (long long)HDIM, vth, vth, NHID, (long long)HDIM * NHID, 0);
    normalize_split<<<(NHID * NHEADS) / 8, 256>>>(keys, kh, ascal, NHID * NHEADS, 1);

    // ---- Q-proj (1-term fp16) ----
    gemm_mma<1><<<dim3(S_LEN / 128, DMODEL / 128, 1), 256, SMEM>>>(
        xh, xh, wqh, wqh, qf, DMODEL, DMODEL, DMODEL, DMODEL);

    // ---- normalize q -> fp16 ----
    normalize_split<<<(S_LEN * NHEADS) / 8, 256>>>(qf, qh, ascal, S_LEN * NHEADS, 0);

    // ---- fused attention ----
    attn_fused<<<dim3(S_LEN / 128, NHEADS), 256, SMEM_ATTN>>>(qh, kh, vth, yh, yl);

    // ---- O-proj (3-term fp16) ----
    gemm_mma<3><<<dim3(S_LEN / 128, DMODEL / 128, 1), 256, SMEM>>>(
        yh, yl, woh, wol, out, DMODEL, DMODEL, DMODEL, DMODEL);
}

// round 7
// speedup vs baseline: 5.9379x; 1.2731x over previous
#include <cuda_runtime.h>
#include <cuda_fp16.h>
#include <stdint.h>

#define S_LEN   4096
#define DMODEL  1024
#define NHEADS  8
#define HDIM    128
#define NHID    2048
#define EPSN    1e-6f
#define CHUNK   128
#define NCHUNK  (NHID / CHUNK)

// ---------------------------------------------------------------------------
// Scratch (device globals — no allocations allowed)
// ---------------------------------------------------------------------------
__device__ __align__(16) __half g_xh[(size_t)S_LEN * DMODEL];
__device__ __align__(16) __half g_wqt_h[(size_t)DMODEL * DMODEL];
__device__ __align__(16) __half g_wot_h[(size_t)DMODEL * DMODEL];
__device__ __align__(16) float  g_qf[(size_t)S_LEN * DMODEL];
__device__ __align__(16) __half g_qh[(size_t)S_LEN * DMODEL];
__device__ __align__(16) __half g_kh[(size_t)NHID * NHEADS * HDIM];
__device__ __align__(16) __half g_vth[(size_t)NHEADS * HDIM * NHID];
__device__ __align__(16) __half g_yh[(size_t)S_LEN * DMODEL];
__device__ __align__(16) __half g_yl[(size_t)S_LEN * DMODEL];

// ---------------------------------------------------------------------------
// PTX helpers (baseline sm_80+ only)
// ---------------------------------------------------------------------------
__device__ __forceinline__ uint32_t smem_u32(const void* p) {
    uint32_t a;
    asm("{ .reg .u64 t; cvta.to.shared.u64 t, %1; cvt.u32.u64 %0, t; }"
        : "=r"(a) : "l"(p));
    return a;
}
__device__ __forceinline__ void cp16(uint32_t s, const void* g) {
    asm volatile("cp.async.cg.shared.global [%0], [%1], 16;" :: "r"(s), "l"(g));
}
#define CP_COMMIT() asm volatile("cp.async.commit_group;" ::: "memory")
#define CP_WAIT(n)  asm volatile("cp.async.wait_group %0;" :: "n"(n) : "memory")

__device__ __forceinline__ void ldsm4(uint32_t& r0, uint32_t& r1,
                                      uint32_t& r2, uint32_t& r3, uint32_t a) {
    asm volatile("ldmatrix.sync.aligned.m8n8.x4.shared.b16 {%0,%1,%2,%3}, [%4];"
                 : "=r"(r0), "=r"(r1), "=r"(r2), "=r"(r3) : "r"(a));
}
__device__ __forceinline__ void mma_f16(float* d, const uint32_t* a, const uint32_t* b) {
    asm volatile(
        "mma.sync.aligned.m16n8k16.row.col.f32.f16.f16.f32 "
        "{%0,%1,%2,%3}, {%4,%5,%6,%7}, {%8,%9}, {%0,%1,%2,%3};"
        : "+f"(d[0]), "+f"(d[1]), "+f"(d[2]), "+f"(d[3])
        : "r"(a[0]), "r"(a[1]), "r"(a[2]), "r"(a[3]), "r"(b[0]), "r"(b[1]));
}
__device__ __forceinline__ uint32_t pkh(float x, float y) {
    __half2 h = __floats2half2_rn(x, y);
    return *reinterpret_cast<uint32_t*>(&h);
}
__device__ __forceinline__ float lo_f(uint32_t u) {
    __half2 h = *reinterpret_cast<__half2*>(&u);
    return __low2float(h);
}
__device__ __forceinline__ float hi_f(uint32_t u) {
    __half2 h = *reinterpret_cast<__half2*>(&u);
    return __high2float(h);
}

// ---------------------------------------------------------------------------
// Fused attention (fp16): Y = softmax(Q·K^T) V per (128 q-rows, head).
// QK: 1-term. AV: 1-term (p rounded to fp16). Unnormalized exp (|logits| <=
// attn_scale), divide by l at epilogue. CHUNK=128 slots, K/V double-buffered.
// smem (half, rows padded to 80B per 32 elems):
//   Q:  0..40960          : 4 slabs (s*10240), slab = 128 rows x 80B
//   K0: 40960,  K1: 81920 : 4 slabs (s*10240, 128 rows x 80B) [rows = slots]
//   V0: 122880, V1: 163840: 4 slabs (s*10240, 128 rows x 80B) [rows = dims]
// ---------------------------------------------------------------------------
#define SQ   0u
#define SK0  40960u
#define SK1  81920u
#define SV0  122880u
#define SV1  163840u
#define SMEM_ATTN 204800

__global__ __launch_bounds__(256, 1)
void attn_fused(const __half* __restrict__ qh,
                const __half* __restrict__ kh,
                const __half* __restrict__ vth,
                __half* __restrict__ yh, __half* __restrict__ yl)
{
    extern __shared__ char smem[];
    const uint32_t sb = smem_u32(smem);
    const int tid = threadIdx.x;
    const int w = tid >> 5, lane = tid & 31;
    const int h = blockIdx.y;
    const int qrow0 = blockIdx.x * 128;

    const __half* qhp = qh + (size_t)qrow0 * DMODEL + h * HDIM;
    const __half* khp = kh + h * HDIM;
    const __half* vhp = vth + (size_t)h * HDIM * NHID;

    // ---- stage Q ----
    #pragma unroll
    for (int it = 0; it < 8; it++) {
        int i = tid + it * 256;               // 0..2047
        int r = i >> 4, c = i & 15, s = c >> 2, c16 = c & 3;
        uint32_t sa = sb + SQ + (uint32_t)(s * 10240 + r * 80 + c16 * 16);
        cp16(sa, qhp + (size_t)r * DMODEL + s * 32 + c16 * 8);
    }
    CP_COMMIT();

    auto loadK = [&](int c) {
        const uint32_t kb = sb + ((c & 1) ? SK1 : SK0);
        const int j0 = c * CHUNK;
        #pragma unroll
        for (int it = 0; it < 8; it++) {
            int i = tid + it * 256;           // 0..2047
            int r = i >> 4, cc = i & 15, s = cc >> 2, c16 = cc & 3;
            uint32_t sa = kb + (uint32_t)(s * 10240 + r * 80 + c16 * 16);
            cp16(sa, khp + (size_t)(j0 + r) * DMODEL + s * 32 + c16 * 8);
        }
    };
    auto loadV = [&](int c) {
        const uint32_t vb = sb + ((c & 1) ? SV1 : SV0);
        const int j0 = c * CHUNK;
        #pragma unroll
        for (int it = 0; it < 8; it++) {
            int i = tid + it * 256;           // 0..2047
            int r = i >> 4, cc = i & 15, s = cc >> 2, c16 = cc & 3;
            uint32_t sa = vb + (uint32_t)(s * 10240 + r * 80 + c16 * 16);
            cp16(sa, vhp + (size_t)r * NHID + j0 + s * 32 + c16 * 8);
        }
    };

    loadK(0); loadV(0); CP_COMMIT();
    loadK(1); loadV(1); CP_COMMIT();

    const uint32_t qa = (uint32_t)((w * 16 + (lane & 15)) * 80 + (lane >> 4) * 16);
    const uint32_t ba = (uint32_t)(((((lane >> 4) << 3) + (lane & 7)) * 80)
                                   + ((lane >> 3) & 1) * 16);

    float Y[16][4];
    #pragma unroll
    for (int i = 0; i < 16; i++)
        #pragma unroll
        for (int j = 0; j < 4; j++) Y[i][j] = 0.0f;
    float l0 = 0.0f, l1 = 0.0f;

    for (int c = 0; c < NCHUNK; c++) {
        CP_WAIT(1);
        __syncthreads();

        // ---- QK: S[128 x 128], 1-term fp16 ----
        const uint32_t kb = sb + ((c & 1) ? SK1 : SK0);
        float S[16][4];
        #pragma unroll
        for (int i = 0; i < 16; i++)
            #pragma unroll
            for (int j = 0; j < 4; j++) S[i][j] = 0.0f;

        #pragma unroll
        for (int kk = 0; kk < 8; kk++) {      // over d (K dim of QK)
            uint32_t qaddr = sb + SQ + (uint32_t)((kk >> 1) * 10240 + (kk & 1) * 32) + qa;
            uint32_t ah[4];
            ldsm4(ah[0], ah[1], ah[2], ah[3], qaddr);
            uint32_t bh[16][2];
            #pragma unroll
            for (int p = 0; p < 8; p++) {     // over slots (16 per p)
                uint32_t ka = kb + (uint32_t)((kk >> 1) * 10240 + p * 1280 + (kk & 1) * 32) + ba;
                ldsm4(bh[2*p][0], bh[2*p][1], bh[2*p+1][0], bh[2*p+1][1], ka);
            }
            #pragma unroll
            for (int nt = 0; nt < 16; nt++)
                mma_f16(S[nt], ah, bh[nt]);
        }

        // ---- exp (no max subtraction; logits bounded) + pack P fp16 ----
        uint32_t pa[8][4];
        #pragma unroll
        for (int kk2 = 0; kk2 < 8; kk2++) {
            #pragma unroll
            for (int half = 0; half < 2; half++) {
                int nt = 2 * kk2 + half;
                float e0 = __expf(S[nt][0]);
                float e1 = __expf(S[nt][1]);
                float e2 = __expf(S[nt][2]);
                float e3 = __expf(S[nt][3]);
                l0 += e0 + e1;
                l1 += e2 + e3;
                pa[kk2][2*half]     = pkh(e0, e1);
                pa[kk2][2*half + 1] = pkh(e2, e3);
            }
        }

        // ---- AV: 1-term ----
        const uint32_t vb = sb + ((c & 1) ? SV1 : SV0);
        #pragma unroll
        for (int kk2 = 0; kk2 < 8; kk2++) {   // over slots (K dim of AV)
            #pragma unroll
            for (int p = 0; p < 8; p++) {     // over dims (16 per p)
                uint32_t va = vb + (uint32_t)((kk2 >> 1) * 10240 + p * 1280
                                              + (kk2 & 1) * 32) + ba;
                uint32_t vh[4];
                ldsm4(vh[0], vh[1], vh[2], vh[3], va);
                uint32_t b0[2] = {vh[0], vh[1]}, b1[2] = {vh[2], vh[3]};
                mma_f16(Y[2*p],     pa[kk2], b0);
                mma_f16(Y[2*p + 1], pa[kk2], b1);
            }
        }
        __syncthreads();

        if (c + 2 < NCHUNK) { loadK(c + 2); loadV(c + 2); }
        CP_COMMIT();
    }

    // ---- epilogue: reduce l across quad, y = Y / l, split hi/lo fp16 ----
    #pragma unroll
    for (int o = 1; o <= 2; o <<= 1) {
        l0 += __shfl_xor_sync(0xFFFFFFFFu, l0, o);
        l1 += __shfl_xor_sync(0xFFFFFFFFu, l1, o);
    }
    const float r0 = 1.0f / l0, r1 = 1.0f / l1;
    const int g = lane >> 2, colb = (lane & 3) * 2;
    #pragma unroll
    for (int nt = 0; nt < 16; nt++) {
        float v0 = Y[nt][0] * r0, v1 = Y[nt][1] * r0;
        float v2 = Y[nt][2] * r1, v3 = Y[nt][3] * r1;
        uint32_t h01 = pkh(v0, v1), h23 = pkh(v2, v3);
        uint32_t lo01 = pkh(v0 - lo_f(h01), v1 - hi_f(h01));
        uint32_t lo23 = pkh(v2 - lo_f(h23), v3 - hi_f(h23));
        size_t o0 = (size_t)(qrow0 + w * 16 + g) * DMODEL + h * HDIM + nt * 8 + colb;
        size_t o1 = o0 + (size_t)8 * DMODEL;
        *reinterpret_cast<uint32_t*>(yh + o0) = h01;
        *reinterpret_cast<uint32_t*>(yl + o0) = lo01;
        *reinterpret_cast<uint32_t*>(yh + o1) = h23;
        *reinterpret_cast<uint32_t*>(yl + o1) = lo23;
    }
}

// ---------------------------------------------------------------------------
// Split-fp16 HMMA GEMM.
// TERMS=1: ah·bh.  TERMS=2: ah·bh + al·bh (A hi/lo, B hi only).
// ---------------------------------------------------------------------------
#define STAGE_B 40960
#define TILE_B  10240

template <int TERMS>
__global__ __launch_bounds__(256, 1)
void gemm_mma(const __half* __restrict__ Ah, const __half* __restrict__ Al,
              const __half* __restrict__ Bh,
              float* __restrict__ C, int K,
              int lda, int ldb, int ldc)
{
    extern __shared__ char smem[];
    const uint32_t sbase = smem_u32(smem);
    const int tid = threadIdx.x;
    const int wid = tid >> 5, lane = tid & 31;
    const int wm = wid & 3, wn = wid >> 2;
    const int m0 = blockIdx.x * 128, n0 = blockIdx.y * 128;

    const int nc = K / 32;
    const int lr0 = tid >> 2, lc0 = tid & 3;
    const int lr1 = lr0 + 64;

    auto load_stage = [&](int c) {
        const int k0 = c * 32;
        const uint32_t sb = sbase + (uint32_t)(c % 3) * STAGE_B;
        {
            uint32_t sa = sb + (uint32_t)(lr0 * 80 + lc0 * 16);
            long long ga = (long long)(m0 + lr0) * lda + k0 + lc0 * 8;
            cp16(sa, Ah + ga);
            if (TERMS == 2) cp16(sa + TILE_B, Al + ga);
            long long gb = (long long)(n0 + lr0) * ldb + k0 + lc0 * 8;
            cp16(sa + 2 * TILE_B, Bh + gb);
        }
        {
            uint32_t sa = sb + (uint32_t)(lr1 * 80 + lc0 * 16);
            long long ga = (long long)(m0 + lr1) * lda + k0 + lc0 * 8;
            cp16(sa, Ah + ga);
            if (TERMS == 2) cp16(sa + TILE_B, Al + ga);
            long long gb = (long long)(n0 + lr1) * ldb + k0 + lc0 * 8;
            cp16(sa + 2 * TILE_B, Bh + gb);
        }
    };

    const uint32_t arow = (uint32_t)((wm * 32 + (lane & 15)) * 80 + (lane >> 4) * 16);
    const uint32_t brow = (uint32_t)((wn * 64 + ((lane >> 4) << 3) + (lane & 7)) * 80
                                     + ((lane >> 3) & 1) * 16);

    float acc[2][8][4];
    #pragma unroll
    for (int i = 0; i < 2; i++)
        #pragma unroll
        for (int j = 0; j < 8; j++)
            #pragma unroll
            for (int q = 0; q < 4; q++) acc[i][j][q] = 0.0f;

    load_stage(0); CP_COMMIT();
    if (nc > 1) load_stage(1);
    CP_COMMIT();

    for (int c = 0; c < nc; c++) {
        CP_WAIT(1);
        __syncthreads();
        if (c + 2 < nc) load_stage(c + 2);
        CP_COMMIT();

        const uint32_t sb = sbase + (uint32_t)(c % 3) * STAGE_B;
        #pragma unroll
        for (int kk = 0; kk < 2; kk++) {
            const uint32_t kbyte = (uint32_t)(kk * 32);
            uint32_t ah[2][4], al[2][4];
            #pragma unroll
            for (int mt = 0; mt < 2; mt++) {
                uint32_t ad = sb + arow + (uint32_t)(mt * 16 * 80) + kbyte;
                ldsm4(ah[mt][0], ah[mt][1], ah[mt][2], ah[mt][3], ad);
                if (TERMS == 2) ldsm4(al[mt][0], al[mt][1], al[mt][2], al[mt][3], ad + TILE_B);
            }
            uint32_t bh[8][2];
            #pragma unroll
            for (int p = 0; p < 4; p++) {
                uint32_t bd = sb + 2 * TILE_B + brow + (uint32_t)(p * 16 * 80) + kbyte;
                ldsm4(bh[2*p][0], bh[2*p][1], bh[2*p+1][0], bh[2*p+1][1], bd);
            }
            #pragma unroll
            for (int mt = 0; mt < 2; mt++)
                #pragma unroll
                for (int nt = 0; nt < 8; nt++) {
                    mma_f16(acc[mt][nt], ah[mt], bh[nt]);
                    if (TERMS == 2) mma_f16(acc[mt][nt], al[mt], bh[nt]);
                }
        }
        __syncthreads();
    }

    const int mb = m0 + wm * 32 + (lane >> 2);
    const int nb = n0 + wn * 64 + (lane & 3) * 2;
    #pragma unroll
    for (int mt = 0; mt < 2; mt++)
        #pragma unroll
        for (int nt = 0; nt < 8; nt++) {
            int m = mb + mt * 16;
            int n = nb + nt * 8;
            float2 v0 = {acc[mt][nt][0], acc[mt][nt][1]};
            float2 v1 = {acc[mt][nt][2], acc[mt][nt][3]};
            *reinterpret_cast<float2*>(C + (long long)m * ldc + n) = v0;
            *reinterpret_cast<float2*>(C + (long long)(m + 8) * ldc + n) = v1;
        }
}

// ---------------------------------------------------------------------------
// Elementwise fp32 -> fp16
// ---------------------------------------------------------------------------
__global__ void split_kernel(const float* __restrict__ in,
                             __half* __restrict__ hi, size_t n4) {
    size_t i = (size_t)blockIdx.x * blockDim.x + threadIdx.x;
    if (i >= n4) return;
    float4 v = reinterpret_cast<const float4*>(in)[i];
    reinterpret_cast<uint32_t*>(hi)[i * 2]     = pkh(v.x, v.y);
    reinterpret_cast<uint32_t*>(hi)[i * 2 + 1] = pkh(v.z, v.w);
}

// ---------------------------------------------------------------------------
// Transpose: out[c][r] = fp16(in[r][c])
// ---------------------------------------------------------------------------
__global__ void transpose_h(const float* __restrict__ in, int ldi, long long inZ,
                            __half* __restrict__ oh, int ldo, long long outZ) {
    __shared__ float t[32][33];
    in += blockIdx.z * inZ;
    const long long ob = blockIdx.z * outZ;
    const int r0 = blockIdx.y * 32, c0 = blockIdx.x * 32;
    #pragma unroll
    for (int i = threadIdx.y; i < 32; i += 8)
        t[i][threadIdx.x] = in[(long long)(r0 + i) * ldi + c0 + threadIdx.x];
    __syncthreads();
    #pragma unroll
    for (int i = threadIdx.y; i < 32; i += 8) {
        long long o = ob + (long long)(c0 + i) * ldo + r0 + threadIdx.x;
        oh[o] = __float2half_rn(t[threadIdx.x][i]);
    }
}

// ---------------------------------------------------------------------------
// Row (128) L2-normalize, optional per-head scale, emit fp16
// ---------------------------------------------------------------------------
__global__ void normalize_h(const float* __restrict__ src,
                            __half* __restrict__ hi,
                            const float* __restrict__ attn_scale,
                            int nrows, int useScale) {
    int row  = blockIdx.x * (blockDim.x >> 5) + (threadIdx.x >> 5);
    int lane = threadIdx.x & 31;
    if (row >= nrows) return;
    float4 v = reinterpret_cast<const float4*>(src + (size_t)row * HDIM)[lane];
    float ss = v.x * v.x + v.y * v.y + v.z * v.z + v.w * v.w;
    #pragma unroll
    for (int o = 16; o; o >>= 1) ss += __shfl_xor_sync(0xFFFFFFFFu, ss, o);
    float sc = rsqrtf(ss + EPSN);
    if (useScale) sc *= attn_scale[row & (NHEADS - 1)];
    size_t off = (size_t)row * HDIM + lane * 4;
    *reinterpret_cast<uint32_t*>(hi + off)     = pkh(v.x * sc, v.y * sc);
    *reinterpret_cast<uint32_t*>(hi + off + 2) = pkh(v.z * sc, v.w * sc);
}

// ---------------------------------------------------------------------------
// Launch
// ---------------------------------------------------------------------------
extern "C" void kernel_launch(void* const* d_in, const int* in_sizes, int n_in,
                              void* d_out, int out_size) {
    const float* x     = (const float*)d_in[0];
    const float* Wq    = (const float*)d_in[1];
    const float* keys  = (const float*)d_in[2];
    const float* vals  = (const float*)d_in[3];
    const float* ascal = (const float*)d_in[4];
    const float* Wo    = (const float*)d_in[5];
    float* out = (float*)d_out;

    __half *xh, *wqh, *woh, *qh, *kh, *vth, *yh, *yl;
    float *qf;
    cudaGetSymbolAddress((void**)&xh, g_xh);
    cudaGetSymbolAddress((void**)&wqh, g_wqt_h);
    cudaGetSymbolAddress((void**)&woh, g_wot_h);
    cudaGetSymbolAddress((void**)&qf, g_qf);
    cudaGetSymbolAddress((void**)&qh, g_qh);
    cudaGetSymbolAddress((void**)&kh, g_kh);
    cudaGetSymbolAddress((void**)&vth, g_vth);
    cudaGetSymbolAddress((void**)&yh, g_yh);   cudaGetSymbolAddress((void**)&yl, g_yl);

    const int SMEM = 3 * STAGE_B;   // 122880 B
    cudaFuncSetAttribute(gemm_mma<1>, cudaFuncAttributeMaxDynamicSharedMemorySize, SMEM);
    cudaFuncSetAttribute(gemm_mma<2>, cudaFuncAttributeMaxDynamicSharedMemorySize, SMEM);
    cudaFuncSetAttribute(attn_fused, cudaFuncAttributeMaxDynamicSharedMemorySize, SMEM_ATTN);

    // ---- prep ----
    split_kernel<<<(S_LEN * DMODEL / 4 + 255) / 256, 256>>>(x, xh,
                                                            (size_t)S_LEN * DMODEL / 4);
    transpose_h<<<dim3(32, 32, 1), dim3(32, 8)>>>(Wq, DMODEL, 0, wqh, DMODEL, 0);
    transpose_h<<<dim3(32, 32, 1), dim3(32, 8)>>>(Wo, DMODEL, 0, woh, DMODEL, 0);
    transpose_h<<<dim3(HDIM / 32, NHID / 32, NHEADS), dim3(32, 8)>>>(
        vals, DMODEL, (long long)HDIM, vth, NHID, (long long)HDIM * NHID);
    normalize_h<<<(NHID * NHEADS) / 8, 256>>>(keys, kh, ascal, NHID * NHEADS, 1);

    // ---- Q-proj (1-term fp16) ----
    gemm_mma<1><<<dim3(S_LEN / 128, DMODEL / 128, 1), 256, SMEM>>>(
        xh, xh, wqh, qf, DMODEL, DMODEL, DMODEL, DMODEL);

    // ---- normalize q -> fp16 ----
    normalize_h<<<(S_LEN * NHEADS) / 8, 256>>>(qf, qh, ascal, S_LEN * NHEADS, 0);

    // ---- fused attention ----
    attn_fused<<<dim3(S_LEN / 128, NHEADS), 256, SMEM_ATTN>>>(qh, kh, vth, yh, yl);

    // ---- O-proj (2-term fp16: y-hi + y-lo, Wo hi) ----
    gemm_mma<2><<<dim3(S_LEN / 128, DMODEL / 128, 1), 256, SMEM>>>(
        yh, yl, woh, out, DMODEL, DMODEL, DMODEL, DMODEL);
}

// round 8
// speedup vs baseline: 7.2304x; 1.2177x over previous
#include <cuda_runtime.h>
#include <cuda_fp16.h>
#include <stdint.h>

#define S_LEN   4096
#define DMODEL  1024
#define NHEADS  8
#define HDIM    128
#define NHID    2048
#define EPSN    1e-6f
#define CHUNK   128
#define NCHUNK  (NHID / CHUNK)

// ---------------------------------------------------------------------------
// Scratch (device globals — no allocations allowed)
// ---------------------------------------------------------------------------
__device__ __align__(16) __half g_xh[(size_t)S_LEN * DMODEL];
__device__ __align__(16) __half g_wqt_h[(size_t)DMODEL * DMODEL];
__device__ __align__(16) __half g_wot_h[(size_t)DMODEL * DMODEL];
__device__ __align__(16) __half g_qh[(size_t)S_LEN * DMODEL];
__device__ __align__(16) __half g_kh[(size_t)NHID * NHEADS * HDIM];
__device__ __align__(16) __half g_vth[(size_t)NHEADS * HDIM * NHID];
__device__ __align__(16) __half g_yh[(size_t)S_LEN * DMODEL];

// ---------------------------------------------------------------------------
// PTX helpers (baseline sm_80+ only)
// ---------------------------------------------------------------------------
__device__ __forceinline__ uint32_t smem_u32(const void* p) {
    uint32_t a;
    asm("{ .reg .u64 t; cvta.to.shared.u64 t, %1; cvt.u32.u64 %0, t; }"
        : "=r"(a) : "l"(p));
    return a;
}
__device__ __forceinline__ void cp16(uint32_t s, const void* g) {
    asm volatile("cp.async.cg.shared.global [%0], [%1], 16;" :: "r"(s), "l"(g));
}
#define CP_COMMIT() asm volatile("cp.async.commit_group;" ::: "memory")
#define CP_WAIT(n)  asm volatile("cp.async.wait_group %0;" :: "n"(n) : "memory")

__device__ __forceinline__ void ldsm4(uint32_t& r0, uint32_t& r1,
                                      uint32_t& r2, uint32_t& r3, uint32_t a) {
    asm volatile("ldmatrix.sync.aligned.m8n8.x4.shared.b16 {%0,%1,%2,%3}, [%4];"
                 : "=r"(r0), "=r"(r1), "=r"(r2), "=r"(r3) : "r"(a));
}
__device__ __forceinline__ void mma_f16(float* d, const uint32_t* a, const uint32_t* b) {
    asm volatile(
        "mma.sync.aligned.m16n8k16.row.col.f32.f16.f16.f32 "
        "{%0,%1,%2,%3}, {%4,%5,%6,%7}, {%8,%9}, {%0,%1,%2,%3};"
        : "+f"(d[0]), "+f"(d[1]), "+f"(d[2]), "+f"(d[3])
        : "r"(a[0]), "r"(a[1]), "r"(a[2]), "r"(a[3]), "r"(b[0]), "r"(b[1]));
}
__device__ __forceinline__ uint32_t pkh(float x, float y) {
    __half2 h = __floats2half2_rn(x, y);
    return *reinterpret_cast<uint32_t*>(&h);
}

// ---------------------------------------------------------------------------
// Fused attention (fp16, all 1-term): Y = softmax(Q·K^T) V per (128 rows, head)
// Unnormalized exp (|logits| <= attn_scale); divide by l at epilogue.
// smem (half, rows padded to 80B per 32 elems):
//   Q:  0..40960          : 4 slabs (s*10240), slab = 128 rows x 80B
//   K0: 40960,  K1: 81920 : 4 slabs (s*10240, 128 rows x 80B) [rows = slots]
//   V0: 122880, V1: 163840: 4 slabs (s*10240, 128 rows x 80B) [rows = dims]
// ---------------------------------------------------------------------------
#define SQ   0u
#define SK0  40960u
#define SK1  81920u
#define SV0  122880u
#define SV1  163840u
#define SMEM_ATTN 204800

__global__ __launch_bounds__(256, 1)
void attn_fused(const __half* __restrict__ qh,
                const __half* __restrict__ kh,
                const __half* __restrict__ vth,
                __half* __restrict__ yh)
{
    extern __shared__ char smem[];
    const uint32_t sb = smem_u32(smem);
    const int tid = threadIdx.x;
    const int w = tid >> 5, lane = tid & 31;
    const int h = blockIdx.y;
    const int qrow0 = blockIdx.x * 128;

    const __half* qhp = qh + (size_t)qrow0 * DMODEL + h * HDIM;
    const __half* khp = kh + h * HDIM;
    const __half* vhp = vth + (size_t)h * HDIM * NHID;

    // ---- stage Q ----
    #pragma unroll
    for (int it = 0; it < 8; it++) {
        int i = tid + it * 256;
        int r = i >> 4, c = i & 15, s = c >> 2, c16 = c & 3;
        uint32_t sa = sb + SQ + (uint32_t)(s * 10240 + r * 80 + c16 * 16);
        cp16(sa, qhp + (size_t)r * DMODEL + s * 32 + c16 * 8);
    }
    CP_COMMIT();

    auto loadK = [&](int c) {
        const uint32_t kb = sb + ((c & 1) ? SK1 : SK0);
        const int j0 = c * CHUNK;
        #pragma unroll
        for (int it = 0; it < 8; it++) {
            int i = tid + it * 256;
            int r = i >> 4, cc = i & 15, s = cc >> 2, c16 = cc & 3;
            uint32_t sa = kb + (uint32_t)(s * 10240 + r * 80 + c16 * 16);
            cp16(sa, khp + (size_t)(j0 + r) * DMODEL + s * 32 + c16 * 8);
        }
    };
    auto loadV = [&](int c) {
        const uint32_t vb = sb + ((c & 1) ? SV1 : SV0);
        const int j0 = c * CHUNK;
        #pragma unroll
        for (int it = 0; it < 8; it++) {
            int i = tid + it * 256;
            int r = i >> 4, cc = i & 15, s = cc >> 2, c16 = cc & 3;
            uint32_t sa = vb + (uint32_t)(s * 10240 + r * 80 + c16 * 16);
            cp16(sa, vhp + (size_t)r * NHID + j0 + s * 32 + c16 * 8);
        }
    };

    loadK(0); loadV(0); CP_COMMIT();
    loadK(1); loadV(1); CP_COMMIT();

    const uint32_t qa = (uint32_t)((w * 16 + (lane & 15)) * 80 + (lane >> 4) * 16);
    const uint32_t ba = (uint32_t)(((((lane >> 4) << 3) + (lane & 7)) * 80)
                                   + ((lane >> 3) & 1) * 16);

    float Y[16][4];
    #pragma unroll
    for (int i = 0; i < 16; i++)
        #pragma unroll
        for (int j = 0; j < 4; j++) Y[i][j] = 0.0f;
    float l0 = 0.0f, l1 = 0.0f;

    for (int c = 0; c < NCHUNK; c++) {
        CP_WAIT(1);
        __syncthreads();

        const uint32_t kb = sb + ((c & 1) ? SK1 : SK0);
        float S[16][4];
        #pragma unroll
        for (int i = 0; i < 16; i++)
            #pragma unroll
            for (int j = 0; j < 4; j++) S[i][j] = 0.0f;

        #pragma unroll
        for (int kk = 0; kk < 8; kk++) {
            uint32_t qaddr = sb + SQ + (uint32_t)((kk >> 1) * 10240 + (kk & 1) * 32) + qa;
            uint32_t ah[4];
            ldsm4(ah[0], ah[1], ah[2], ah[3], qaddr);
            uint32_t bh[16][2];
            #pragma unroll
            for (int p = 0; p < 8; p++) {
                uint32_t ka = kb + (uint32_t)((kk >> 1) * 10240 + p * 1280 + (kk & 1) * 32) + ba;
                ldsm4(bh[2*p][0], bh[2*p][1], bh[2*p+1][0], bh[2*p+1][1], ka);
            }
            #pragma unroll
            for (int nt = 0; nt < 16; nt++)
                mma_f16(S[nt], ah, bh[nt]);
        }

        // ---- exp + pack P fp16 ----
        uint32_t pa[8][4];
        #pragma unroll
        for (int kk2 = 0; kk2 < 8; kk2++) {
            #pragma unroll
            for (int half = 0; half < 2; half++) {
                int nt = 2 * kk2 + half;
                float e0 = __expf(S[nt][0]);
                float e1 = __expf(S[nt][1]);
                float e2 = __expf(S[nt][2]);
                float e3 = __expf(S[nt][3]);
                l0 += e0 + e1;
                l1 += e2 + e3;
                pa[kk2][2*half]     = pkh(e0, e1);
                pa[kk2][2*half + 1] = pkh(e2, e3);
            }
        }

        // ---- AV ----
        const uint32_t vb = sb + ((c & 1) ? SV1 : SV0);
        #pragma unroll
        for (int kk2 = 0; kk2 < 8; kk2++) {
            #pragma unroll
            for (int p = 0; p < 8; p++) {
                uint32_t va = vb + (uint32_t)((kk2 >> 1) * 10240 + p * 1280
                                              + (kk2 & 1) * 32) + ba;
                uint32_t vh[4];
                ldsm4(vh[0], vh[1], vh[2], vh[3], va);
                uint32_t b0[2] = {vh[0], vh[1]}, b1[2] = {vh[2], vh[3]};
                mma_f16(Y[2*p],     pa[kk2], b0);
                mma_f16(Y[2*p + 1], pa[kk2], b1);
            }
        }
        __syncthreads();

        if (c + 2 < NCHUNK) { loadK(c + 2); loadV(c + 2); }
        CP_COMMIT();
    }

    // ---- epilogue ----
    #pragma unroll
    for (int o = 1; o <= 2; o <<= 1) {
        l0 += __shfl_xor_sync(0xFFFFFFFFu, l0, o);
        l1 += __shfl_xor_sync(0xFFFFFFFFu, l1, o);
    }
    const float r0 = 1.0f / l0, r1 = 1.0f / l1;
    const int g = lane >> 2, colb = (lane & 3) * 2;
    #pragma unroll
    for (int nt = 0; nt < 16; nt++) {
        uint32_t h01 = pkh(Y[nt][0] * r0, Y[nt][1] * r0);
        uint32_t h23 = pkh(Y[nt][2] * r1, Y[nt][3] * r1);
        size_t o0 = (size_t)(qrow0 + w * 16 + g) * DMODEL + h * HDIM + nt * 8 + colb;
        *reinterpret_cast<uint32_t*>(yh + o0) = h01;
        *reinterpret_cast<uint32_t*>(yh + o0 + (size_t)8 * DMODEL) = h23;
    }
}

// ---------------------------------------------------------------------------
// 1-term fp16 HMMA GEMM, 3-stage. EPI=0: fp32 store. EPI=1: per-row (within
// 128-col tile = one head) L2-normalize, store fp16.
// ---------------------------------------------------------------------------
#define STAGE_B 20480
#define TILE_B  10240
#define SMEM_GEMM (3 * STAGE_B)

template <int EPI>
__global__ __launch_bounds__(256)
void gemm_mma(const __half* __restrict__ Ah, const __half* __restrict__ Bh,
              void* __restrict__ Cv, int K, int lda, int ldb, int ldc)
{
    extern __shared__ char smem[];
    const uint32_t sbase = smem_u32(smem);
    const int tid = threadIdx.x;
    const int wid = tid >> 5, lane = tid & 31;
    const int wm = wid & 3, wn = wid >> 2;
    const int m0 = blockIdx.x * 128, n0 = blockIdx.y * 128;

    const int nc = K / 32;
    const int lr0 = tid >> 2, lc0 = tid & 3;
    const int lr1 = lr0 + 64;

    auto load_stage = [&](int c) {
        const int k0 = c * 32;
        const uint32_t sb = sbase + (uint32_t)(c % 3) * STAGE_B;
        {
            uint32_t sa = sb + (uint32_t)(lr0 * 80 + lc0 * 16);
            cp16(sa, Ah + (long long)(m0 + lr0) * lda + k0 + lc0 * 8);
            cp16(sa + TILE_B, Bh + (long long)(n0 + lr0) * ldb + k0 + lc0 * 8);
        }
        {
            uint32_t sa = sb + (uint32_t)(lr1 * 80 + lc0 * 16);
            cp16(sa, Ah + (long long)(m0 + lr1) * lda + k0 + lc0 * 8);
            cp16(sa + TILE_B, Bh + (long long)(n0 + lr1) * ldb + k0 + lc0 * 8);
        }
    };

    const uint32_t arow = (uint32_t)((wm * 32 + (lane & 15)) * 80 + (lane >> 4) * 16);
    const uint32_t brow = (uint32_t)((wn * 64 + ((lane >> 4) << 3) + (lane & 7)) * 80
                                     + ((lane >> 3) & 1) * 16);

    float acc[2][8][4];
    #pragma unroll
    for (int i = 0; i < 2; i++)
        #pragma unroll
        for (int j = 0; j < 8; j++)
            #pragma unroll
            for (int q = 0; q < 4; q++) acc[i][j][q] = 0.0f;

    load_stage(0); CP_COMMIT();
    if (nc > 1) load_stage(1);
    CP_COMMIT();

    for (int c = 0; c < nc; c++) {
        CP_WAIT(1);
        __syncthreads();
        if (c + 2 < nc) load_stage(c + 2);
        CP_COMMIT();

        const uint32_t sb = sbase + (uint32_t)(c % 3) * STAGE_B;
        #pragma unroll
        for (int kk = 0; kk < 2; kk++) {
            const uint32_t kbyte = (uint32_t)(kk * 32);
            uint32_t ah[2][4];
            #pragma unroll
            for (int mt = 0; mt < 2; mt++) {
                uint32_t ad = sb + arow + (uint32_t)(mt * 16 * 80) + kbyte;
                ldsm4(ah[mt][0], ah[mt][1], ah[mt][2], ah[mt][3], ad);
            }
            uint32_t bh[8][2];
            #pragma unroll
            for (int p = 0; p < 4; p++) {
                uint32_t bd = sb + TILE_B + brow + (uint32_t)(p * 16 * 80) + kbyte;
                ldsm4(bh[2*p][0], bh[2*p][1], bh[2*p+1][0], bh[2*p+1][1], bd);
            }
            #pragma unroll
            for (int mt = 0; mt < 2; mt++)
                #pragma unroll
                for (int nt = 0; nt < 8; nt++)
                    mma_f16(acc[mt][nt], ah[mt], bh[nt]);
        }
        __syncthreads();
    }

    if (EPI == 0) {
        float* C = (float*)Cv;
        const int mb = m0 + wm * 32 + (lane >> 2);
        const int nb = n0 + wn * 64 + (lane & 3) * 2;
        #pragma unroll
        for (int mt = 0; mt < 2; mt++)
            #pragma unroll
            for (int nt = 0; nt < 8; nt++) {
                int m = mb + mt * 16, n = nb + nt * 8;
                float2 v0 = {acc[mt][nt][0], acc[mt][nt][1]};
                float2 v1 = {acc[mt][nt][2], acc[mt][nt][3]};
                *reinterpret_cast<float2*>(C + (long long)m * ldc + n) = v0;
                *reinterpret_cast<float2*>(C + (long long)(m + 8) * ldc + n) = v1;
            }
    } else {
        // ---- fused L2-normalize over the 128-col tile (one head) ----
        __half* C = (__half*)Cv;
        float p[4];
        #pragma unroll
        for (int i = 0; i < 4; i++) p[i] = 0.0f;
        #pragma unroll
        for (int mt = 0; mt < 2; mt++)
            #pragma unroll
            for (int nt = 0; nt < 8; nt++) {
                p[mt*2]   += acc[mt][nt][0]*acc[mt][nt][0] + acc[mt][nt][1]*acc[mt][nt][1];
                p[mt*2+1] += acc[mt][nt][2]*acc[mt][nt][2] + acc[mt][nt][3]*acc[mt][nt][3];
            }
        #pragma unroll
        for (int o = 1; o <= 2; o <<= 1)
            #pragma unroll
            for (int i = 0; i < 4; i++)
                p[i] += __shfl_xor_sync(0xFFFFFFFFu, p[i], o);
        float* rs = reinterpret_cast<float*>(smem);   // 128 rows x 2 warps
        const int rl = wm * 32 + (lane >> 2);
        if ((lane & 3) == 0) {
            rs[(rl +  0) * 2 + wn] = p[0];
            rs[(rl +  8) * 2 + wn] = p[1];
            rs[(rl + 16) * 2 + wn] = p[2];
            rs[(rl + 24) * 2 + wn] = p[3];
        }
        __syncthreads();
        float sc[4];
        #pragma unroll
        for (int i = 0; i < 4; i++) {
            int r = rl + (i & 1) * 8 + (i >> 1) * 16;
            sc[i] = rsqrtf(rs[r * 2] + rs[r * 2 + 1] + EPSN);
        }
        const int mb = m0 + wm * 32 + (lane >> 2);
        const int nb = n0 + wn * 64 + (lane & 3) * 2;
        #pragma unroll
        for (int mt = 0; mt < 2; mt++)
            #pragma unroll
            for (int nt = 0; nt < 8; nt++) {
                int m = mb + mt * 16, n = nb + nt * 8;
                uint32_t u0 = pkh(acc[mt][nt][0] * sc[mt*2],
                                  acc[mt][nt][1] * sc[mt*2]);
                uint32_t u1 = pkh(acc[mt][nt][2] * sc[mt*2+1],
                                  acc[mt][nt][3] * sc[mt*2+1]);
                *reinterpret_cast<uint32_t*>(C + (long long)m * ldc + n) = u0;
                *reinterpret_cast<uint32_t*>(C + (long long)(m + 8) * ldc + n) = u1;
            }
    }
}

// ---------------------------------------------------------------------------
// Elementwise fp32 -> fp16
// ---------------------------------------------------------------------------
__global__ void split_kernel(const float* __restrict__ in,
                             __half* __restrict__ hi, size_t n4) {
    size_t i = (size_t)blockIdx.x * blockDim.x + threadIdx.x;
    if (i >= n4) return;
    float4 v = reinterpret_cast<const float4*>(in)[i];
    reinterpret_cast<uint32_t*>(hi)[i * 2]     = pkh(v.x, v.y);
    reinterpret_cast<uint32_t*>(hi)[i * 2 + 1] = pkh(v.z, v.w);
}

// ---------------------------------------------------------------------------
// Transpose: out[c][r] = fp16(in[r][c])
// ---------------------------------------------------------------------------
__global__ void transpose_h(const float* __restrict__ in, int ldi, long long inZ,
                            __half* __restrict__ oh, int ldo, long long outZ) {
    __shared__ float t[32][33];
    in += blockIdx.z * inZ;
    const long long ob = blockIdx.z * outZ;
    const int r0 = blockIdx.y * 32, c0 = blockIdx.x * 32;
    #pragma unroll
    for (int i = threadIdx.y; i < 32; i += 8)
        t[i][threadIdx.x] = in[(long long)(r0 + i) * ldi + c0 + threadIdx.x];
    __syncthreads();
    #pragma unroll
    for (int i = threadIdx.y; i < 32; i += 8) {
        long long o = ob + (long long)(c0 + i) * ldo + r0 + threadIdx.x;
        oh[o] = __float2half_rn(t[threadIdx.x][i]);
    }
}

// ---------------------------------------------------------------------------
// Row (128) L2-normalize + per-head scale, emit fp16 (keys)
// ---------------------------------------------------------------------------
__global__ void normalize_h(const float* __restrict__ src,
                            __half* __restrict__ hi,
                            const float* __restrict__ attn_scale, int nrows) {
    int row  = blockIdx.x * (blockDim.x >> 5) + (threadIdx.x >> 5);
    int lane = threadIdx.x & 31;
    if (row >= nrows) return;
    float4 v = reinterpret_cast<const float4*>(src + (size_t)row * HDIM)[lane];
    float ss = v.x * v.x + v.y * v.y + v.z * v.z + v.w * v.w;
    #pragma unroll
    for (int o = 16; o; o >>= 1) ss += __shfl_xor_sync(0xFFFFFFFFu, ss, o);
    float sc = rsqrtf(ss + EPSN) * attn_scale[row & (NHEADS - 1)];
    size_t off = (size_t)row * HDIM + lane * 4;
    *reinterpret_cast<uint32_t*>(hi + off)     = pkh(v.x * sc, v.y * sc);
    *reinterpret_cast<uint32_t*>(hi + off + 2) = pkh(v.z * sc, v.w * sc);
}

// ---------------------------------------------------------------------------
// Launch (prep forked onto a second stream; fork/join via events)
// ---------------------------------------------------------------------------
extern "C" void kernel_launch(void* const* d_in, const int* in_sizes, int n_in,
                              void* d_out, int out_size) {
    const float* x     = (const float*)d_in[0];
    const float* Wq    = (const float*)d_in[1];
    const float* keys  = (const float*)d_in[2];
    const float* vals  = (const float*)d_in[3];
    const float* ascal = (const float*)d_in[4];
    const float* Wo    = (const float*)d_in[5];
    float* out = (float*)d_out;

    __half *xh, *wqh, *woh, *qh, *kh, *vth, *yh;
    cudaGetSymbolAddress((void**)&xh, g_xh);
    cudaGetSymbolAddress((void**)&wqh, g_wqt_h);
    cudaGetSymbolAddress((void**)&woh, g_wot_h);
    cudaGetSymbolAddress((void**)&qh, g_qh);
    cudaGetSymbolAddress((void**)&kh, g_kh);
    cudaGetSymbolAddress((void**)&vth, g_vth);
    cudaGetSymbolAddress((void**)&yh, g_yh);

    cudaFuncSetAttribute(gemm_mma<0>, cudaFuncAttributeMaxDynamicSharedMemorySize, SMEM_GEMM);
    cudaFuncSetAttribute(gemm_mma<1>, cudaFuncAttributeMaxDynamicSharedMemorySize, SMEM_GEMM);
    cudaFuncSetAttribute(attn_fused, cudaFuncAttributeMaxDynamicSharedMemorySize, SMEM_ATTN);

    static cudaStream_t s1 = nullptr;
    static cudaEvent_t evF = nullptr, evJ = nullptr;
    if (!s1) {
        cudaStreamCreateWithFlags(&s1, cudaStreamNonBlocking);
        cudaEventCreateWithFlags(&evF, cudaEventDisableTiming);
        cudaEventCreateWithFlags(&evJ, cudaEventDisableTiming);
    }

    // fork side stream for attn/O-proj prep
    cudaEventRecord(evF, 0);
    cudaStreamWaitEvent(s1, evF, 0);
    normalize_h<<<(NHID * NHEADS) / 8, 256, 0, s1>>>(keys, kh, ascal, NHID * NHEADS);
    transpose_h<<<dim3(HDIM / 32, NHID / 32, NHEADS), dim3(32, 8), 0, s1>>>(
        vals, DMODEL, (long long)HDIM, vth, NHID, (long long)HDIM * NHID);
    transpose_h<<<dim3(32, 32, 1), dim3(32, 8), 0, s1>>>(Wo, DMODEL, 0, woh, DMODEL, 0);
    cudaEventRecord(evJ, s1);

    // main stream: Q pipeline
    split_kernel<<<(S_LEN * DMODEL / 4 + 255) / 256, 256>>>(x, xh,
                                                            (size_t)S_LEN * DMODEL / 4);
    transpose_h<<<dim3(32, 32, 1), dim3(32, 8)>>>(Wq, DMODEL, 0, wqh, DMODEL, 0);

    // Q-proj with fused normalize -> qh fp16
    gemm_mma<1><<<dim3(S_LEN / 128, DMODEL / 128), 256, SMEM_GEMM>>>(
        xh, wqh, qh, DMODEL, DMODEL, DMODEL, DMODEL);

    // join side stream, then attention
    cudaStreamWaitEvent(0, evJ, 0);
    attn_fused<<<dim3(S_LEN / 128, NHEADS), 256, SMEM_ATTN>>>(qh, kh, vth, yh);

    // O-proj (1-term) -> fp32 out
    gemm_mma<0><<<dim3(S_LEN / 128, DMODEL / 128), 256, SMEM_GEMM>>>(
        yh, woh, out, DMODEL, DMODEL, DMODEL, DMODEL);
}

// round 9
// speedup vs baseline: 7.9020x; 1.0929x over previous
#include <cuda_runtime.h>
#include <cuda_fp16.h>
#include <stdint.h>

#define S_LEN   4096
#define DMODEL  1024
#define NHEADS  8
#define HDIM    128
#define NHID    2048
#define EPSN    1e-6f
#define CHUNK   64
#define NCHUNK  (NHID / CHUNK)

// ---------------------------------------------------------------------------
// Scratch (device globals — no allocations allowed)
// ---------------------------------------------------------------------------
__device__ __align__(16) __half g_xh[(size_t)S_LEN * DMODEL];
__device__ __align__(16) __half g_wqt_h[(size_t)DMODEL * DMODEL];
__device__ __align__(16) __half g_wot_h[(size_t)DMODEL * DMODEL];
__device__ __align__(16) __half g_qh[(size_t)S_LEN * DMODEL];
__device__ __align__(16) __half g_kh[(size_t)NHID * NHEADS * HDIM];
__device__ __align__(16) __half g_vth[(size_t)NHEADS * HDIM * NHID];
__device__ __align__(16) __half g_yh[(size_t)S_LEN * DMODEL];

// ---------------------------------------------------------------------------
// PTX helpers (baseline sm_80+ only)
// ---------------------------------------------------------------------------
__device__ __forceinline__ uint32_t smem_u32(const void* p) {
    uint32_t a;
    asm("{ .reg .u64 t; cvta.to.shared.u64 t, %1; cvt.u32.u64 %0, t; }"
        : "=r"(a) : "l"(p));
    return a;
}
__device__ __forceinline__ void cp16(uint32_t s, const void* g) {
    asm volatile("cp.async.cg.shared.global [%0], [%1], 16;" :: "r"(s), "l"(g));
}
#define CP_COMMIT() asm volatile("cp.async.commit_group;" ::: "memory")
#define CP_WAIT(n)  asm volatile("cp.async.wait_group %0;" :: "n"(n) : "memory")

__device__ __forceinline__ void ldsm4(uint32_t& r0, uint32_t& r1,
                                      uint32_t& r2, uint32_t& r3, uint32_t a) {
    asm volatile("ldmatrix.sync.aligned.m8n8.x4.shared.b16 {%0,%1,%2,%3}, [%4];"
                 : "=r"(r0), "=r"(r1), "=r"(r2), "=r"(r3) : "r"(a));
}
__device__ __forceinline__ void mma_f16(float* d, const uint32_t* a, const uint32_t* b) {
    asm volatile(
        "mma.sync.aligned.m16n8k16.row.col.f32.f16.f16.f32 "
        "{%0,%1,%2,%3}, {%4,%5,%6,%7}, {%8,%9}, {%0,%1,%2,%3};"
        : "+f"(d[0]), "+f"(d[1]), "+f"(d[2]), "+f"(d[3])
        : "r"(a[0]), "r"(a[1]), "r"(a[2]), "r"(a[3]), "r"(b[0]), "r"(b[1]));
}
__device__ __forceinline__ uint32_t pkh(float x, float y) {
    __half2 h = __floats2half2_rn(x, y);
    return *reinterpret_cast<uint32_t*>(&h);
}
// SW64 swizzle: rows of 64B; XOR bits[4:5] with row bits[1:2]
__device__ __forceinline__ uint32_t sw64(uint32_t off) {
    return off ^ ((off >> 3) & 0x30u);
}

// ---------------------------------------------------------------------------
// Fused attention (fp16, all 1-term), SW64 layout, 2 CTAs/SM.
// smem (bytes):
//   Q:  0..32768         : 4 slabs of 8192 (128 rows x 64B, SW64)
//   K0: 32768, K1: 49152 : per chunk 4 slabs of 4096 (64 rows x 64B)
//   V0: 65536, V1: 81920 : per chunk 2 slabs of 8192 (128 rows x 64B)
// ---------------------------------------------------------------------------
#define SQ   0u
#define SK0  32768u
#define SK1  49152u
#define SV0  65536u
#define SV1  81920u
#define SMEM_ATTN 98304

__global__ __launch_bounds__(256, 2)
void attn_fused(const __half* __restrict__ qh,
                const __half* __restrict__ kh,
                const __half* __restrict__ vth,
                __half* __restrict__ yh)
{
    extern __shared__ char smem[];
    const uint32_t sb = smem_u32(smem);
    const int tid = threadIdx.x;
    const int w = tid >> 5, lane = tid & 31;
    const int h = blockIdx.y;
    const int qrow0 = blockIdx.x * 128;

    const __half* qhp = qh + (size_t)qrow0 * DMODEL + h * HDIM;
    const __half* khp = kh + h * HDIM;
    const __half* vhp = vth + (size_t)h * HDIM * NHID;

    // ---- stage Q: 4 slabs x 128 rows x 4 chunks ----
    #pragma unroll
    for (int it = 0; it < 8; it++) {
        int i = tid + it * 256;               // 0..2047
        int s = i >> 9, r = (i >> 2) & 127, c16 = i & 3;
        uint32_t sa = sb + SQ + (uint32_t)(s * 8192) + sw64((uint32_t)(r * 64 + c16 * 16));
        cp16(sa, qhp + (size_t)r * DMODEL + s * 32 + c16 * 8);
    }
    CP_COMMIT();

    auto loadK = [&](int c) {
        const uint32_t kb = sb + ((c & 1) ? SK1 : SK0);
        const int j0 = c * CHUNK;
        #pragma unroll
        for (int it = 0; it < 4; it++) {
            int i = tid + it * 256;           // 0..1023
            int s = i >> 8, r = (i >> 2) & 63, c16 = i & 3;
            uint32_t sa = kb + (uint32_t)(s * 4096) + sw64((uint32_t)(r * 64 + c16 * 16));
            cp16(sa, khp + (size_t)(j0 + r) * DMODEL + s * 32 + c16 * 8);
        }
    };
    auto loadV = [&](int c) {
        const uint32_t vb = sb + ((c & 1) ? SV1 : SV0);
        const int j0 = c * CHUNK;
        #pragma unroll
        for (int it = 0; it < 4; it++) {
            int i = tid + it * 256;           // 0..1023
            int s = i >> 9, r = (i >> 2) & 127, c16 = i & 3;
            uint32_t sa = vb + (uint32_t)(s * 8192) + sw64((uint32_t)(r * 64 + c16 * 16));
            cp16(sa, vhp + (size_t)r * NHID + j0 + s * 32 + c16 * 8);
        }
    };

    loadK(0); loadV(0); CP_COMMIT();
    loadK(1); loadV(1); CP_COMMIT();

    // ldmatrix lane address components (SW64)
    const int row_a = w * 16 + (lane & 15);
    const uint32_t qrowpart = (uint32_t)(row_a * 64 + (lane >> 4) * 16);
    const uint32_t qxor = (uint32_t)((row_a & 6) << 3);
    const int row_b = ((lane >> 4) << 3) + (lane & 7);
    const uint32_t browpart = (uint32_t)(row_b * 64 + ((lane >> 3) & 1) * 16);
    const uint32_t bxor = (uint32_t)((row_b & 6) << 3);

    float Y[16][4];
    #pragma unroll
    for (int i = 0; i < 16; i++)
        #pragma unroll
        for (int j = 0; j < 4; j++) Y[i][j] = 0.0f;
    float l0 = 0.0f, l1 = 0.0f;

    for (int c = 0; c < NCHUNK; c++) {
        CP_WAIT(1);
        __syncthreads();

        // ---- QK: S[128 x 64] ----
        const uint32_t kb = sb + ((c & 1) ? SK1 : SK0);
        float S[8][4];
        #pragma unroll
        for (int i = 0; i < 8; i++)
            #pragma unroll
            for (int j = 0; j < 4; j++) S[i][j] = 0.0f;

        #pragma unroll
        for (int kk = 0; kk < 8; kk++) {
            uint32_t kko = (uint32_t)((kk & 1) * 32);
            uint32_t qaddr = sb + SQ + (uint32_t)((kk >> 1) * 8192)
                           + ((qrowpart | kko) ^ qxor);
            uint32_t ah[4];
            ldsm4(ah[0], ah[1], ah[2], ah[3], qaddr);
            uint32_t bh[8][2];
            #pragma unroll
            for (int p = 0; p < 4; p++) {
                uint32_t ka = kb + (uint32_t)((kk >> 1) * 4096 + p * 1024)
                            + ((browpart | kko) ^ bxor);
                ldsm4(bh[2*p][0], bh[2*p][1], bh[2*p+1][0], bh[2*p+1][1], ka);
            }
            #pragma unroll
            for (int nt = 0; nt < 8; nt++)
                mma_f16(S[nt], ah, bh[nt]);
        }

        // ---- exp + pack P fp16 ----
        uint32_t pa[4][4];
        #pragma unroll
        for (int kk2 = 0; kk2 < 4; kk2++) {
            #pragma unroll
            for (int half = 0; half < 2; half++) {
                int nt = 2 * kk2 + half;
                float e0 = __expf(S[nt][0]);
                float e1 = __expf(S[nt][1]);
                float e2 = __expf(S[nt][2]);
                float e3 = __expf(S[nt][3]);
                l0 += e0 + e1;
                l1 += e2 + e3;
                pa[kk2][2*half]     = pkh(e0, e1);
                pa[kk2][2*half + 1] = pkh(e2, e3);
            }
        }

        // ---- AV ----
        const uint32_t vb = sb + ((c & 1) ? SV1 : SV0);
        #pragma unroll
        for (int kk2 = 0; kk2 < 4; kk2++) {
            uint32_t kko = (uint32_t)((kk2 & 1) * 32);
            #pragma unroll
            for (int p = 0; p < 8; p++) {
                uint32_t va = vb + (uint32_t)((kk2 >> 1) * 8192 + p * 1024)
                            + ((browpart | kko) ^ bxor);
                uint32_t vh[4];
                ldsm4(vh[0], vh[1], vh[2], vh[3], va);
                uint32_t b0[2] = {vh[0], vh[1]}, b1[2] = {vh[2], vh[3]};
                mma_f16(Y[2*p],     pa[kk2], b0);
                mma_f16(Y[2*p + 1], pa[kk2], b1);
            }
        }
        __syncthreads();

        if (c + 2 < NCHUNK) { loadK(c + 2); loadV(c + 2); }
        CP_COMMIT();
    }

    // ---- epilogue ----
    #pragma unroll
    for (int o = 1; o <= 2; o <<= 1) {
        l0 += __shfl_xor_sync(0xFFFFFFFFu, l0, o);
        l1 += __shfl_xor_sync(0xFFFFFFFFu, l1, o);
    }
    const float r0 = 1.0f / l0, r1 = 1.0f / l1;
    const int g = lane >> 2, colb = (lane & 3) * 2;
    #pragma unroll
    for (int nt = 0; nt < 16; nt++) {
        uint32_t h01 = pkh(Y[nt][0] * r0, Y[nt][1] * r0);
        uint32_t h23 = pkh(Y[nt][2] * r1, Y[nt][3] * r1);
        size_t o0 = (size_t)(qrow0 + w * 16 + g) * DMODEL + h * HDIM + nt * 8 + colb;
        *reinterpret_cast<uint32_t*>(yh + o0) = h01;
        *reinterpret_cast<uint32_t*>(yh + o0 + (size_t)8 * DMODEL) = h23;
    }
}

// ---------------------------------------------------------------------------
// 1-term fp16 HMMA GEMM, 3-stage (unchanged from round 8).
// EPI=0: fp32 store. EPI=1: per-row L2-normalize within 128-col tile, fp16.
// ---------------------------------------------------------------------------
#define STAGE_B 20480
#define TILE_B  10240
#define SMEM_GEMM (3 * STAGE_B)

template <int EPI>
__global__ __launch_bounds__(256)
void gemm_mma(const __half* __restrict__ Ah, const __half* __restrict__ Bh,
              void* __restrict__ Cv, int K, int lda, int ldb, int ldc)
{
    extern __shared__ char smem[];
    const uint32_t sbase = smem_u32(smem);
    const int tid = threadIdx.x;
    const int wid = tid >> 5, lane = tid & 31;
    const int wm = wid & 3, wn = wid >> 2;
    const int m0 = blockIdx.x * 128, n0 = blockIdx.y * 128;

    const int nc = K / 32;
    const int lr0 = tid >> 2, lc0 = tid & 3;
    const int lr1 = lr0 + 64;

    auto load_stage = [&](int c) {
        const int k0 = c * 32;
        const uint32_t sb = sbase + (uint32_t)(c % 3) * STAGE_B;
        {
            uint32_t sa = sb + (uint32_t)(lr0 * 80 + lc0 * 16);
            cp16(sa, Ah + (long long)(m0 + lr0) * lda + k0 + lc0 * 8);
            cp16(sa + TILE_B, Bh + (long long)(n0 + lr0) * ldb + k0 + lc0 * 8);
        }
        {
            uint32_t sa = sb + (uint32_t)(lr1 * 80 + lc0 * 16);
            cp16(sa, Ah + (long long)(m0 + lr1) * lda + k0 + lc0 * 8);
            cp16(sa + TILE_B, Bh + (long long)(n0 + lr1) * ldb + k0 + lc0 * 8);
        }
    };

    const uint32_t arow = (uint32_t)((wm * 32 + (lane & 15)) * 80 + (lane >> 4) * 16);
    const uint32_t brow = (uint32_t)((wn * 64 + ((lane >> 4) << 3) + (lane & 7)) * 80
                                     + ((lane >> 3) & 1) * 16);

    float acc[2][8][4];
    #pragma unroll
    for (int i = 0; i < 2; i++)
        #pragma unroll
        for (int j = 0; j < 8; j++)
            #pragma unroll
            for (int q = 0; q < 4; q++) acc[i][j][q] = 0.0f;

    load_stage(0); CP_COMMIT();
    if (nc > 1) load_stage(1);
    CP_COMMIT();

    for (int c = 0; c < nc; c++) {
        CP_WAIT(1);
        __syncthreads();
        if (c + 2 < nc) load_stage(c + 2);
        CP_COMMIT();

        const uint32_t sb = sbase + (uint32_t)(c % 3) * STAGE_B;
        #pragma unroll
        for (int kk = 0; kk < 2; kk++) {
            const uint32_t kbyte = (uint32_t)(kk * 32);
            uint32_t ah[2][4];
            #pragma unroll
            for (int mt = 0; mt < 2; mt++) {
                uint32_t ad = sb + arow + (uint32_t)(mt * 16 * 80) + kbyte;
                ldsm4(ah[mt][0], ah[mt][1], ah[mt][2], ah[mt][3], ad);
            }
            uint32_t bh[8][2];
            #pragma unroll
            for (int p = 0; p < 4; p++) {
                uint32_t bd = sb + TILE_B + brow + (uint32_t)(p * 16 * 80) + kbyte;
                ldsm4(bh[2*p][0], bh[2*p][1], bh[2*p+1][0], bh[2*p+1][1], bd);
            }
            #pragma unroll
            for (int mt = 0; mt < 2; mt++)
                #pragma unroll
                for (int nt = 0; nt < 8; nt++)
                    mma_f16(acc[mt][nt], ah[mt], bh[nt]);
        }
        __syncthreads();
    }

    if (EPI == 0) {
        float* C = (float*)Cv;
        const int mb = m0 + wm * 32 + (lane >> 2);
        const int nb = n0 + wn * 64 + (lane & 3) * 2;
        #pragma unroll
        for (int mt = 0; mt < 2; mt++)
            #pragma unroll
            for (int nt = 0; nt < 8; nt++) {
                int m = mb + mt * 16, n = nb + nt * 8;
                float2 v0 = {acc[mt][nt][0], acc[mt][nt][1]};
                float2 v1 = {acc[mt][nt][2], acc[mt][nt][3]};
                *reinterpret_cast<float2*>(C + (long long)m * ldc + n) = v0;
                *reinterpret_cast<float2*>(C + (long long)(m + 8) * ldc + n) = v1;
            }
    } else {
        __half* C = (__half*)Cv;
        float p[4];
        #pragma unroll
        for (int i = 0; i < 4; i++) p[i] = 0.0f;
        #pragma unroll
        for (int mt = 0; mt < 2; mt++)
            #pragma unroll
            for (int nt = 0; nt < 8; nt++) {
                p[mt*2]   += acc[mt][nt][0]*acc[mt][nt][0] + acc[mt][nt][1]*acc[mt][nt][1];
                p[mt*2+1] += acc[mt][nt][2]*acc[mt][nt][2] + acc[mt][nt][3]*acc[mt][nt][3];
            }
        #pragma unroll
        for (int o = 1; o <= 2; o <<= 1)
            #pragma unroll
            for (int i = 0; i < 4; i++)
                p[i] += __shfl_xor_sync(0xFFFFFFFFu, p[i], o);
        float* rs = reinterpret_cast<float*>(smem);
        const int rl = wm * 32 + (lane >> 2);
        if ((lane & 3) == 0) {
            rs[(rl +  0) * 2 + wn] = p[0];
            rs[(rl +  8) * 2 + wn] = p[1];
            rs[(rl + 16) * 2 + wn] = p[2];
            rs[(rl + 24) * 2 + wn] = p[3];
        }
        __syncthreads();
        float sc[4];
        #pragma unroll
        for (int i = 0; i < 4; i++) {
            int r = rl + (i & 1) * 8 + (i >> 1) * 16;
            sc[i] = rsqrtf(rs[r * 2] + rs[r * 2 + 1] + EPSN);
        }
        const int mb = m0 + wm * 32 + (lane >> 2);
        const int nb = n0 + wn * 64 + (lane & 3) * 2;
        #pragma unroll
        for (int mt = 0; mt < 2; mt++)
            #pragma unroll
            for (int nt = 0; nt < 8; nt++) {
                int m = mb + mt * 16, n = nb + nt * 8;
                uint32_t u0 = pkh(acc[mt][nt][0] * sc[mt*2],
                                  acc[mt][nt][1] * sc[mt*2]);
                uint32_t u1 = pkh(acc[mt][nt][2] * sc[mt*2+1],
                                  acc[mt][nt][3] * sc[mt*2+1]);
                *reinterpret_cast<uint32_t*>(C + (long long)m * ldc + n) = u0;
                *reinterpret_cast<uint32_t*>(C + (long long)(m + 8) * ldc + n) = u1;
            }
    }
}

// ---------------------------------------------------------------------------
// Elementwise fp32 -> fp16
// ---------------------------------------------------------------------------
__global__ void split_kernel(const float* __restrict__ in,
                             __half* __restrict__ hi, size_t n4) {
    size_t i = (size_t)blockIdx.x * blockDim.x + threadIdx.x;
    if (i >= n4) return;
    float4 v = reinterpret_cast<const float4*>(in)[i];
    reinterpret_cast<uint32_t*>(hi)[i * 2]     = pkh(v.x, v.y);
    reinterpret_cast<uint32_t*>(hi)[i * 2 + 1] = pkh(v.z, v.w);
}

// ---------------------------------------------------------------------------
// Transpose: out[c][r] = fp16(in[r][c])
// ---------------------------------------------------------------------------
__global__ void transpose_h(const float* __restrict__ in, int ldi, long long inZ,
                            __half* __restrict__ oh, int ldo, long long outZ) {
    __shared__ float t[32][33];
    in += blockIdx.z * inZ;
    const long long ob = blockIdx.z * outZ;
    const int r0 = blockIdx.y * 32, c0 = blockIdx.x * 32;
    #pragma unroll
    for (int i = threadIdx.y; i < 32; i += 8)
        t[i][threadIdx.x] = in[(long long)(r0 + i) * ldi + c0 + threadIdx.x];
    __syncthreads();
    #pragma unroll
    for (int i = threadIdx.y; i < 32; i += 8) {
        long long o = ob + (long long)(c0 + i) * ldo + r0 + threadIdx.x;
        oh[o] = __float2half_rn(t[threadIdx.x][i]);
    }
}

// ---------------------------------------------------------------------------
// Row (128) L2-normalize + per-head scale, emit fp16 (keys)
// ---------------------------------------------------------------------------
__global__ void normalize_h(const float* __restrict__ src,
                            __half* __restrict__ hi,
                            const float* __restrict__ attn_scale, int nrows) {
    int row  = blockIdx.x * (blockDim.x >> 5) + (threadIdx.x >> 5);
    int lane = threadIdx.x & 31;
    if (row >= nrows) return;
    float4 v = reinterpret_cast<const float4*>(src + (size_t)row * HDIM)[lane];
    float ss = v.x * v.x + v.y * v.y + v.z * v.z + v.w * v.w;
    #pragma unroll
    for (int o = 16; o; o >>= 1) ss += __shfl_xor_sync(0xFFFFFFFFu, ss, o);
    float sc = rsqrtf(ss + EPSN) * attn_scale[row & (NHEADS - 1)];
    size_t off = (size_t)row * HDIM + lane * 4;
    *reinterpret_cast<uint32_t*>(hi + off)     = pkh(v.x * sc, v.y * sc);
    *reinterpret_cast<uint32_t*>(hi + off + 2) = pkh(v.z * sc, v.w * sc);
}

// ---------------------------------------------------------------------------
// Launch (prep on side stream; fork/join via events)
// ---------------------------------------------------------------------------
extern "C" void kernel_launch(void* const* d_in, const int* in_sizes, int n_in,
                              void* d_out, int out_size) {
    const float* x     = (const float*)d_in[0];
    const float* Wq    = (const float*)d_in[1];
    const float* keys  = (const float*)d_in[2];
    const float* vals  = (const float*)d_in[3];
    const float* ascal = (const float*)d_in[4];
    const float* Wo    = (const float*)d_in[5];
    float* out = (float*)d_out;

    __half *xh, *wqh, *woh, *qh, *kh, *vth, *yh;
    cudaGetSymbolAddress((void**)&xh, g_xh);
    cudaGetSymbolAddress((void**)&wqh, g_wqt_h);
    cudaGetSymbolAddress((void**)&woh, g_wot_h);
    cudaGetSymbolAddress((void**)&qh, g_qh);
    cudaGetSymbolAddress((void**)&kh, g_kh);
    cudaGetSymbolAddress((void**)&vth, g_vth);
    cudaGetSymbolAddress((void**)&yh, g_yh);

    cudaFuncSetAttribute(gemm_mma<0>, cudaFuncAttributeMaxDynamicSharedMemorySize, SMEM_GEMM);
    cudaFuncSetAttribute(gemm_mma<1>, cudaFuncAttributeMaxDynamicSharedMemorySize, SMEM_GEMM);
    cudaFuncSetAttribute(attn_fused, cudaFuncAttributeMaxDynamicSharedMemorySize, SMEM_ATTN);

    static cudaStream_t s1 = nullptr;
    static cudaEvent_t evF = nullptr, evW = nullptr, evJ = nullptr;
    if (!s1) {
        cudaStreamCreateWithFlags(&s1, cudaStreamNonBlocking);
        cudaEventCreateWithFlags(&evF, cudaEventDisableTiming);
        cudaEventCreateWithFlags(&evW, cudaEventDisableTiming);
        cudaEventCreateWithFlags(&evJ, cudaEventDisableTiming);
    }

    // fork: side stream does Wq transpose (needed early) + attn/O-proj prep
    cudaEventRecord(evF, 0);
    cudaStreamWaitEvent(s1, evF, 0);
    transpose_h<<<dim3(32, 32, 1), dim3(32, 8), 0, s1>>>(Wq, DMODEL, 0, wqh, DMODEL, 0);
    cudaEventRecord(evW, s1);
    normalize_h<<<(NHID * NHEADS) / 8, 256, 0, s1>>>(keys, kh, ascal, NHID * NHEADS);
    transpose_h<<<dim3(HDIM / 32, NHID / 32, NHEADS), dim3(32, 8), 0, s1>>>(
        vals, DMODEL, (long long)HDIM, vth, NHID, (long long)HDIM * NHID);
    transpose_h<<<dim3(32, 32, 1), dim3(32, 8), 0, s1>>>(Wo, DMODEL, 0, woh, DMODEL, 0);
    cudaEventRecord(evJ, s1);

    // main: split x (concurrent with Wq transpose)
    split_kernel<<<(S_LEN * DMODEL / 4 + 255) / 256, 256>>>(x, xh,
                                                            (size_t)S_LEN * DMODEL / 4);
    cudaStreamWaitEvent(0, evW, 0);

    // Q-proj with fused normalize -> qh fp16
    gemm_mma<1><<<dim3(S_LEN / 128, DMODEL / 128), 256, SMEM_GEMM>>>(
        xh, wqh, qh, DMODEL, DMODEL, DMODEL, DMODEL);

    // join side stream, then attention
    cudaStreamWaitEvent(0, evJ, 0);
    attn_fused<<<dim3(S_LEN / 128, NHEADS), 256, SMEM_ATTN>>>(qh, kh, vth, yh);

    // O-proj (1-term) -> fp32 out
    gemm_mma<0><<<dim3(S_LEN / 128, DMODEL / 128), 256, SMEM_GEMM>>>(
        yh, woh, out, DMODEL, DMODEL, DMODEL, DMODEL);
}

// round 10
// speedup vs baseline: 8.1345x; 1.0294x over previous
#include <cuda_runtime.h>
#include <cuda_fp16.h>
#include <stdint.h>

#define S_LEN   4096
#define DMODEL  1024
#define NHEADS  8
#define HDIM    128
#define NHID    2048
#define EPSN    1e-6f
#define CHUNK   64
#define NCHUNK  (NHID / CHUNK)

// ---------------------------------------------------------------------------
// Scratch (device globals — no allocations allowed)
// ---------------------------------------------------------------------------
__device__ __align__(16) __half g_wqt_h[(size_t)DMODEL * DMODEL];
__device__ __align__(16) __half g_wot_h[(size_t)DMODEL * DMODEL];
__device__ __align__(16) __half g_qh[(size_t)S_LEN * DMODEL];
__device__ __align__(16) __half g_kh[(size_t)NHID * NHEADS * HDIM];
__device__ __align__(16) __half g_vth[(size_t)NHEADS * HDIM * NHID];
__device__ __align__(16) __half g_yh[(size_t)S_LEN * DMODEL];

// ---------------------------------------------------------------------------
// PTX helpers (baseline sm_80+ only)
// ---------------------------------------------------------------------------
__device__ __forceinline__ uint32_t smem_u32(const void* p) {
    uint32_t a;
    asm("{ .reg .u64 t; cvta.to.shared.u64 t, %1; cvt.u32.u64 %0, t; }"
        : "=r"(a) : "l"(p));
    return a;
}
__device__ __forceinline__ void cp16(uint32_t s, const void* g) {
    asm volatile("cp.async.cg.shared.global [%0], [%1], 16;" :: "r"(s), "l"(g));
}
#define CP_COMMIT() asm volatile("cp.async.commit_group;" ::: "memory")
#define CP_WAIT(n)  asm volatile("cp.async.wait_group %0;" :: "n"(n) : "memory")

__device__ __forceinline__ void ldsm4(uint32_t& r0, uint32_t& r1,
                                      uint32_t& r2, uint32_t& r3, uint32_t a) {
    asm volatile("ldmatrix.sync.aligned.m8n8.x4.shared.b16 {%0,%1,%2,%3}, [%4];"
                 : "=r"(r0), "=r"(r1), "=r"(r2), "=r"(r3) : "r"(a));
}
__device__ __forceinline__ void mma_f16(float* d, const uint32_t* a, const uint32_t* b) {
    asm volatile(
        "mma.sync.aligned.m16n8k16.row.col.f32.f16.f16.f32 "
        "{%0,%1,%2,%3}, {%4,%5,%6,%7}, {%8,%9}, {%0,%1,%2,%3};"
        : "+f"(d[0]), "+f"(d[1]), "+f"(d[2]), "+f"(d[3])
        : "r"(a[0]), "r"(a[1]), "r"(a[2]), "r"(a[3]), "r"(b[0]), "r"(b[1]));
}
__device__ __forceinline__ uint32_t pkh(float x, float y) {
    __half2 h = __floats2half2_rn(x, y);
    return *reinterpret_cast<uint32_t*>(&h);
}
// SW64 swizzle: rows of 64B; XOR bits[4:5] with row bits[1:2]
__device__ __forceinline__ uint32_t sw64(uint32_t off) {
    return off ^ ((off >> 3) & 0x30u);
}

// ---------------------------------------------------------------------------
// Fused attention (fp16, all 1-term), SW64 layout, 2 CTAs/SM (round-9 proven).
// ---------------------------------------------------------------------------
#define SQ   0u
#define SK0  32768u
#define SK1  49152u
#define SV0  65536u
#define SV1  81920u
#define SMEM_ATTN 98304

__global__ __launch_bounds__(256, 2)
void attn_fused(const __half* __restrict__ qh,
                const __half* __restrict__ kh,
                const __half* __restrict__ vth,
                __half* __restrict__ yh)
{
    extern __shared__ char smem[];
    const uint32_t sb = smem_u32(smem);
    const int tid = threadIdx.x;
    const int w = tid >> 5, lane = tid & 31;
    const int h = blockIdx.y;
    const int qrow0 = blockIdx.x * 128;

    const __half* qhp = qh + (size_t)qrow0 * DMODEL + h * HDIM;
    const __half* khp = kh + h * HDIM;
    const __half* vhp = vth + (size_t)h * HDIM * NHID;

    #pragma unroll
    for (int it = 0; it < 8; it++) {
        int i = tid + it * 256;
        int s = i >> 9, r = (i >> 2) & 127, c16 = i & 3;
        uint32_t sa = sb + SQ + (uint32_t)(s * 8192) + sw64((uint32_t)(r * 64 + c16 * 16));
        cp16(sa, qhp + (size_t)r * DMODEL + s * 32 + c16 * 8);
    }
    CP_COMMIT();

    auto loadK = [&](int c) {
        const uint32_t kb = sb + ((c & 1) ? SK1 : SK0);
        const int j0 = c * CHUNK;
        #pragma unroll
        for (int it = 0; it < 4; it++) {
            int i = tid + it * 256;
            int s = i >> 8, r = (i >> 2) & 63, c16 = i & 3;
            uint32_t sa = kb + (uint32_t)(s * 4096) + sw64((uint32_t)(r * 64 + c16 * 16));
            cp16(sa, khp + (size_t)(j0 + r) * DMODEL + s * 32 + c16 * 8);
        }
    };
    auto loadV = [&](int c) {
        const uint32_t vb = sb + ((c & 1) ? SV1 : SV0);
        const int j0 = c * CHUNK;
        #pragma unroll
        for (int it = 0; it < 4; it++) {
            int i = tid + it * 256;
            int s = i >> 9, r = (i >> 2) & 127, c16 = i & 3;
            uint32_t sa = vb + (uint32_t)(s * 8192) + sw64((uint32_t)(r * 64 + c16 * 16));
            cp16(sa, vhp + (size_t)r * NHID + j0 + s * 32 + c16 * 8);
        }
    };

    loadK(0); loadV(0); CP_COMMIT();
    loadK(1); loadV(1); CP_COMMIT();

    const int row_a = w * 16 + (lane & 15);
    const uint32_t qrowpart = (uint32_t)(row_a * 64 + (lane >> 4) * 16);
    const uint32_t qxor = (uint32_t)((row_a & 6) << 3);
    const int row_b = ((lane >> 4) << 3) + (lane & 7);
    const uint32_t browpart = (uint32_t)(row_b * 64 + ((lane >> 3) & 1) * 16);
    const uint32_t bxor = (uint32_t)((row_b & 6) << 3);

    float Y[16][4];
    #pragma unroll
    for (int i = 0; i < 16; i++)
        #pragma unroll
        for (int j = 0; j < 4; j++) Y[i][j] = 0.0f;
    float l0 = 0.0f, l1 = 0.0f;

    for (int c = 0; c < NCHUNK; c++) {
        CP_WAIT(1);
        __syncthreads();

        const uint32_t kb = sb + ((c & 1) ? SK1 : SK0);
        float S[8][4];
        #pragma unroll
        for (int i = 0; i < 8; i++)
            #pragma unroll
            for (int j = 0; j < 4; j++) S[i][j] = 0.0f;

        #pragma unroll
        for (int kk = 0; kk < 8; kk++) {
            uint32_t kko = (uint32_t)((kk & 1) * 32);
            uint32_t qaddr = sb + SQ + (uint32_t)((kk >> 1) * 8192)
                           + ((qrowpart | kko) ^ qxor);
            uint32_t ah[4];
            ldsm4(ah[0], ah[1], ah[2], ah[3], qaddr);
            uint32_t bh[8][2];
            #pragma unroll
            for (int p = 0; p < 4; p++) {
                uint32_t ka = kb + (uint32_t)((kk >> 1) * 4096 + p * 1024)
                            + ((browpart | kko) ^ bxor);
                ldsm4(bh[2*p][0], bh[2*p][1], bh[2*p+1][0], bh[2*p+1][1], ka);
            }
            #pragma unroll
            for (int nt = 0; nt < 8; nt++)
                mma_f16(S[nt], ah, bh[nt]);
        }

        uint32_t pa[4][4];
        #pragma unroll
        for (int kk2 = 0; kk2 < 4; kk2++) {
            #pragma unroll
            for (int half = 0; half < 2; half++) {
                int nt = 2 * kk2 + half;
                float e0 = __expf(S[nt][0]);
                float e1 = __expf(S[nt][1]);
                float e2 = __expf(S[nt][2]);
                float e3 = __expf(S[nt][3]);
                l0 += e0 + e1;
                l1 += e2 + e3;
                pa[kk2][2*half]     = pkh(e0, e1);
                pa[kk2][2*half + 1] = pkh(e2, e3);
            }
        }

        const uint32_t vb = sb + ((c & 1) ? SV1 : SV0);
        #pragma unroll
        for (int kk2 = 0; kk2 < 4; kk2++) {
            uint32_t kko = (uint32_t)((kk2 & 1) * 32);
            #pragma unroll
            for (int p = 0; p < 8; p++) {
                uint32_t va = vb + (uint32_t)((kk2 >> 1) * 8192 + p * 1024)
                            + ((browpart | kko) ^ bxor);
                uint32_t vh[4];
                ldsm4(vh[0], vh[1], vh[2], vh[3], va);
                uint32_t b0[2] = {vh[0], vh[1]}, b1[2] = {vh[2], vh[3]};
                mma_f16(Y[2*p],     pa[kk2], b0);
                mma_f16(Y[2*p + 1], pa[kk2], b1);
            }
        }
        __syncthreads();

        if (c + 2 < NCHUNK) { loadK(c + 2); loadV(c + 2); }
        CP_COMMIT();
    }

    #pragma unroll
    for (int o = 1; o <= 2; o <<= 1) {
        l0 += __shfl_xor_sync(0xFFFFFFFFu, l0, o);
        l1 += __shfl_xor_sync(0xFFFFFFFFu, l1, o);
    }
    const float r0 = 1.0f / l0, r1 = 1.0f / l1;
    const int g = lane >> 2, colb = (lane & 3) * 2;
    #pragma unroll
    for (int nt = 0; nt < 16; nt++) {
        uint32_t h01 = pkh(Y[nt][0] * r0, Y[nt][1] * r0);
        uint32_t h23 = pkh(Y[nt][2] * r1, Y[nt][3] * r1);
        size_t o0 = (size_t)(qrow0 + w * 16 + g) * DMODEL + h * HDIM + nt * 8 + colb;
        *reinterpret_cast<uint32_t*>(yh + o0) = h01;
        *reinterpret_cast<uint32_t*>(yh + o0 + (size_t)8 * DMODEL) = h23;
    }
}

// ---------------------------------------------------------------------------
// 1-term fp16 HMMA GEMM, 3-stage, single barrier per iteration.
// AF32=1: A is fp32 in gmem -> LDG + cvt + STS (fused conversion).
// AF32=0: A is fp16 -> cp.async.
// EPI=0: fp32 store. EPI=1: per-row L2-normalize within 128-col tile, fp16.
// ---------------------------------------------------------------------------
#define STAGE_B 20480
#define TILE_B  10240
#define SMEM_GEMM (3 * STAGE_B)

template <int EPI, int AF32>
__global__ __launch_bounds__(256)
void gemm_mma(const void* __restrict__ Av, const __half* __restrict__ Bh,
              void* __restrict__ Cv, int K, int lda, int ldb, int ldc)
{
    extern __shared__ char smem[];
    const uint32_t sbase = smem_u32(smem);
    const int tid = threadIdx.x;
    const int wid = tid >> 5, lane = tid & 31;
    const int wm = wid & 3, wn = wid >> 2;
    const int m0 = blockIdx.x * 128, n0 = blockIdx.y * 128;

    const __half* Ah = (const __half*)Av;
    const float*  Af = (const float*)Av;

    const int nc = K / 32;
    const int lr0 = tid >> 2, lc0 = tid & 3;
    const int lr1 = lr0 + 64;

    // B loader (cp.async, both paths)
    auto loadB = [&](int c) {
        const int k0 = c * 32;
        const uint32_t sb = sbase + (uint32_t)(c % 3) * STAGE_B;
        cp16(sb + TILE_B + (uint32_t)(lr0 * 80 + lc0 * 16),
             Bh + (long long)(n0 + lr0) * ldb + k0 + lc0 * 8);
        cp16(sb + TILE_B + (uint32_t)(lr1 * 80 + lc0 * 16),
             Bh + (long long)(n0 + lr1) * ldb + k0 + lc0 * 8);
    };
    // A loader, fp16 cp.async path
    auto loadA16 = [&](int c) {
        const int k0 = c * 32;
        const uint32_t sb = sbase + (uint32_t)(c % 3) * STAGE_B;
        cp16(sb + (uint32_t)(lr0 * 80 + lc0 * 16),
             Ah + (long long)(m0 + lr0) * lda + k0 + lc0 * 8);
        cp16(sb + (uint32_t)(lr1 * 80 + lc0 * 16),
             Ah + (long long)(m0 + lr1) * lda + k0 + lc0 * 8);
    };
    // A loader, fp32 LDG path: thread covers row (tid>>1), 16 k starting at
    // k = (tid&1)*16 -> two 16B fp16 chunks (c16 = (tid&1)*2 + {0,1})
    const int ar = tid >> 1;
    const int ac0 = (tid & 1) * 2;
    auto ldgA = [&](int c, float4* v) {
        const int k0 = c * 32;
        #pragma unroll
        for (int j = 0; j < 2; j++) {
            const float4* g = reinterpret_cast<const float4*>(
                Af + (long long)(m0 + ar) * lda + k0 + (ac0 + j) * 8);
            v[j * 2]     = g[0];
            v[j * 2 + 1] = g[1];
        }
    };
    auto stsA = [&](int c, const float4* v) {
        const uint32_t so = (uint32_t)(c % 3) * STAGE_B;
        #pragma unroll
        for (int j = 0; j < 2; j++) {
            uint4 u;
            u.x = pkh(v[j*2].x,   v[j*2].y);
            u.y = pkh(v[j*2].z,   v[j*2].w);
            u.z = pkh(v[j*2+1].x, v[j*2+1].y);
            u.w = pkh(v[j*2+1].z, v[j*2+1].w);
            *reinterpret_cast<uint4*>(smem + so + ar * 80 + (ac0 + j) * 16) = u;
        }
    };

    const uint32_t arow = (uint32_t)((wm * 32 + (lane & 15)) * 80 + (lane >> 4) * 16);
    const uint32_t brow = (uint32_t)((wn * 64 + ((lane >> 4) << 3) + (lane & 7)) * 80
                                     + ((lane >> 3) & 1) * 16);

    float acc[2][8][4];
    #pragma unroll
    for (int i = 0; i < 2; i++)
        #pragma unroll
        for (int j = 0; j < 8; j++)
            #pragma unroll
            for (int q = 0; q < 4; q++) acc[i][j][q] = 0.0f;

    float4 va[4];
    // prologue: stages 0 and 1
    if (AF32) { ldgA(0, va); stsA(0, va); } else { loadA16(0); }
    loadB(0); CP_COMMIT();
    if (AF32) { ldgA(1, va); stsA(1, va); } else { loadA16(1); }
    loadB(1); CP_COMMIT();

    for (int c = 0; c < nc; c++) {
        if (AF32 && c + 2 < nc) ldgA(c + 2, va);   // LDG early, hide behind MMAs
        CP_WAIT(1);
        __syncthreads();

        const uint32_t sb = sbase + (uint32_t)(c % 3) * STAGE_B;
        #pragma unroll
        for (int kk = 0; kk < 2; kk++) {
            const uint32_t kbyte = (uint32_t)(kk * 32);
            uint32_t ah[2][4];
            #pragma unroll
            for (int mt = 0; mt < 2; mt++) {
                uint32_t ad = sb + arow + (uint32_t)(mt * 16 * 80) + kbyte;
                ldsm4(ah[mt][0], ah[mt][1], ah[mt][2], ah[mt][3], ad);
            }
            uint32_t bh[8][2];
            #pragma unroll
            for (int p = 0; p < 4; p++) {
                uint32_t bd = sb + TILE_B + brow + (uint32_t)(p * 16 * 80) + kbyte;
                ldsm4(bh[2*p][0], bh[2*p][1], bh[2*p+1][0], bh[2*p+1][1], bd);
            }
            #pragma unroll
            for (int mt = 0; mt < 2; mt++)
                #pragma unroll
                for (int nt = 0; nt < 8; nt++)
                    mma_f16(acc[mt][nt], ah[mt], bh[nt]);
        }

        if (c + 2 < nc) {
            if (AF32) stsA(c + 2, va); else loadA16(c + 2);
            loadB(c + 2);
        }
        CP_COMMIT();
    }

    if (EPI == 0) {
        float* C = (float*)Cv;
        const int mb = m0 + wm * 32 + (lane >> 2);
        const int nb = n0 + wn * 64 + (lane & 3) * 2;
        #pragma unroll
        for (int mt = 0; mt < 2; mt++)
            #pragma unroll
            for (int nt = 0; nt < 8; nt++) {
                int m = mb + mt * 16, n = nb + nt * 8;
                float2 v0 = {acc[mt][nt][0], acc[mt][nt][1]};
                float2 v1 = {acc[mt][nt][2], acc[mt][nt][3]};
                *reinterpret_cast<float2*>(C + (long long)m * ldc + n) = v0;
                *reinterpret_cast<float2*>(C + (long long)(m + 8) * ldc + n) = v1;
            }
    } else {
        __half* C = (__half*)Cv;
        float p[4];
        #pragma unroll
        for (int i = 0; i < 4; i++) p[i] = 0.0f;
        #pragma unroll
        for (int mt = 0; mt < 2; mt++)
            #pragma unroll
            for (int nt = 0; nt < 8; nt++) {
                p[mt*2]   += acc[mt][nt][0]*acc[mt][nt][0] + acc[mt][nt][1]*acc[mt][nt][1];
                p[mt*2+1] += acc[mt][nt][2]*acc[mt][nt][2] + acc[mt][nt][3]*acc[mt][nt][3];
            }
        #pragma unroll
        for (int o = 1; o <= 2; o <<= 1)
            #pragma unroll
            for (int i = 0; i < 4; i++)
                p[i] += __shfl_xor_sync(0xFFFFFFFFu, p[i], o);
        __syncthreads();   // all reads of smem stages done before reuse
        float* rs = reinterpret_cast<float*>(smem);
        const int rl = wm * 32 + (lane >> 2);
        if ((lane & 3) == 0) {
            rs[(rl +  0) * 2 + wn] = p[0];
            rs[(rl +  8) * 2 + wn] = p[1];
            rs[(rl + 16) * 2 + wn] = p[2];
            rs[(rl + 24) * 2 + wn] = p[3];
        }
        __syncthreads();
        float sc[4];
        #pragma unroll
        for (int i = 0; i < 4; i++) {
            int r = rl + (i & 1) * 8 + (i >> 1) * 16;
            sc[i] = rsqrtf(rs[r * 2] + rs[r * 2 + 1] + EPSN);
        }
        const int mb = m0 + wm * 32 + (lane >> 2);
        const int nb = n0 + wn * 64 + (lane & 3) * 2;
        #pragma unroll
        for (int mt = 0; mt < 2; mt++)
            #pragma unroll
            for (int nt = 0; nt < 8; nt++) {
                int m = mb + mt * 16, n = nb + nt * 8;
                uint32_t u0 = pkh(acc[mt][nt][0] * sc[mt*2],
                                  acc[mt][nt][1] * sc[mt*2]);
                uint32_t u1 = pkh(acc[mt][nt][2] * sc[mt*2+1],
                                  acc[mt][nt][3] * sc[mt*2+1]);
                *reinterpret_cast<uint32_t*>(C + (long long)m * ldc + n) = u0;
                *reinterpret_cast<uint32_t*>(C + (long long)(m + 8) * ldc + n) = u1;
            }
    }
}

// ---------------------------------------------------------------------------
// Transpose: out[c][r] = fp16(in[r][c])
// ---------------------------------------------------------------------------
__global__ void transpose_h(const float* __restrict__ in, int ldi, long long inZ,
                            __half* __restrict__ oh, int ldo, long long outZ) {
    __shared__ float t[32][33];
    in += blockIdx.z * inZ;
    const long long ob = blockIdx.z * outZ;
    const int r0 = blockIdx.y * 32, c0 = blockIdx.x * 32;
    #pragma unroll
    for (int i = threadIdx.y; i < 32; i += 8)
        t[i][threadIdx.x] = in[(long long)(r0 + i) * ldi + c0 + threadIdx.x];
    __syncthreads();
    #pragma unroll
    for (int i = threadIdx.y; i < 32; i += 8) {
        long long o = ob + (long long)(c0 + i) * ldo + r0 + threadIdx.x;
        oh[o] = __float2half_rn(t[threadIdx.x][i]);
    }
}

// ---------------------------------------------------------------------------
// Row (128) L2-normalize + per-head scale, emit fp16 (keys)
// ---------------------------------------------------------------------------
__global__ void normalize_h(const float* __restrict__ src,
                            __half* __restrict__ hi,
                            const float* __restrict__ attn_scale, int nrows) {
    int row  = blockIdx.x * (blockDim.x >> 5) + (threadIdx.x >> 5);
    int lane = threadIdx.x & 31;
    if (row >= nrows) return;
    float4 v = reinterpret_cast<const float4*>(src + (size_t)row * HDIM)[lane];
    float ss = v.x * v.x + v.y * v.y + v.z * v.z + v.w * v.w;
    #pragma unroll
    for (int o = 16; o; o >>= 1) ss += __shfl_xor_sync(0xFFFFFFFFu, ss, o);
    float sc = rsqrtf(ss + EPSN) * attn_scale[row & (NHEADS - 1)];
    size_t off = (size_t)row * HDIM + lane * 4;
    *reinterpret_cast<uint32_t*>(hi + off)     = pkh(v.x * sc, v.y * sc);
    *reinterpret_cast<uint32_t*>(hi + off + 2) = pkh(v.z * sc, v.w * sc);
}

// ---------------------------------------------------------------------------
// Launch (side stream prep; fork/join via events)
// ---------------------------------------------------------------------------
extern "C" void kernel_launch(void* const* d_in, const int* in_sizes, int n_in,
                              void* d_out, int out_size) {
    const float* x     = (const float*)d_in[0];
    const float* Wq    = (const float*)d_in[1];
    const float* keys  = (const float*)d_in[2];
    const float* vals  = (const float*)d_in[3];
    const float* ascal = (const float*)d_in[4];
    const float* Wo    = (const float*)d_in[5];
    float* out = (float*)d_out;

    __half *wqh, *woh, *qh, *kh, *vth, *yh;
    cudaGetSymbolAddress((void**)&wqh, g_wqt_h);
    cudaGetSymbolAddress((void**)&woh, g_wot_h);
    cudaGetSymbolAddress((void**)&qh, g_qh);
    cudaGetSymbolAddress((void**)&kh, g_kh);
    cudaGetSymbolAddress((void**)&vth, g_vth);
    cudaGetSymbolAddress((void**)&yh, g_yh);

    cudaFuncSetAttribute((const void*)gemm_mma<0,0>,
                         cudaFuncAttributeMaxDynamicSharedMemorySize, SMEM_GEMM);
    cudaFuncSetAttribute((const void*)gemm_mma<1,1>,
                         cudaFuncAttributeMaxDynamicSharedMemorySize, SMEM_GEMM);
    cudaFuncSetAttribute((const void*)attn_fused,
                         cudaFuncAttributeMaxDynamicSharedMemorySize, SMEM_ATTN);

    static cudaStream_t s1 = nullptr;
    static cudaEvent_t evF = nullptr, evW = nullptr, evJ = nullptr;
    if (!s1) {
        cudaStreamCreateWithFlags(&s1, cudaStreamNonBlocking);
        cudaEventCreateWithFlags(&evF, cudaEventDisableTiming);
        cudaEventCreateWithFlags(&evW, cudaEventDisableTiming);
        cudaEventCreateWithFlags(&evJ, cudaEventDisableTiming);
    }

    // fork: side stream — WqT first (gates Q-proj), then hidden prep
    cudaEventRecord(evF, 0);
    cudaStreamWaitEvent(s1, evF, 0);
    transpose_h<<<dim3(32, 32, 1), dim3(32, 8), 0, s1>>>(Wq, DMODEL, 0, wqh, DMODEL, 0);
    cudaEventRecord(evW, s1);
    normalize_h<<<(NHID * NHEADS) / 8, 256, 0, s1>>>(keys, kh, ascal, NHID * NHEADS);
    transpose_h<<<dim3(HDIM / 32, NHID / 32, NHEADS), dim3(32, 8), 0, s1>>>(
        vals, DMODEL, (long long)HDIM, vth, NHID, (long long)HDIM * NHID);
    transpose_h<<<dim3(32, 32, 1), dim3(32, 8), 0, s1>>>(Wo, DMODEL, 0, woh, DMODEL, 0);
    cudaEventRecord(evJ, s1);

    // main: Q-proj with fused fp32->fp16 conversion of x and fused q-normalize
    cudaStreamWaitEvent(0, evW, 0);
    gemm_mma<1,1><<<dim3(S_LEN / 128, DMODEL / 128), 256, SMEM_GEMM>>>(
        x, wqh, qh, DMODEL, DMODEL, DMODEL, DMODEL);

    // join side stream, then attention
    cudaStreamWaitEvent(0, evJ, 0);
    attn_fused<<<dim3(S_LEN / 128, NHEADS), 256, SMEM_ATTN>>>(qh, kh, vth, yh);

    // O-proj (1-term) -> fp32 out
    gemm_mma<0,0><<<dim3(S_LEN / 128, DMODEL / 128), 256, SMEM_GEMM>>>(
        yh, woh, out, DMODEL, DMODEL, DMODEL, DMODEL);
}